// round 1
// baseline (speedup 1.0000x reference)
#include <cuda_runtime.h>
#include <cstdint>

#define NN 100000
#define EE 1600000
#define MINN 1e-15f
#define MAXN ((float)(1.0 - 1e-5))

// ---------------- scratch (device globals; no allocs allowed) ----------------
__device__ __align__(16) float g_t[(size_t)NN * 64];
__device__ __align__(16) float g_agg[(size_t)NN * 64];
__device__ float g_deg[NN];
__device__ int g_idx64;

// ---------------- helpers ----------------
__device__ __forceinline__ void wsum2(float& a, float& b) {
#pragma unroll
    for (int o = 16; o > 0; o >>= 1) {
        a += __shfl_xor_sync(0xffffffffu, a, o);
        b += __shfl_xor_sync(0xffffffffu, b, o);
    }
}

__device__ __forceinline__ float atanh_clip(float x) {
    return atanhf(fminf(x, MAXN));
}

// proj on a vector whose norm n is already known; updates n
__device__ __forceinline__ void proj2(float& a0, float& a1, float& n) {
    n = fmaxf(n, MINN);
    if (n > MAXN) {
        float s = MAXN / n;
        a0 *= s; a1 *= s;
        n = MAXN;
    }
}

// act: h = proj(expmap0(relu(logmap0(h))))   for two nodes at once
__device__ __forceinline__ void act2(float& A0, float& A1, float& nA,
                                     float& B0, float& B1, float& nB) {
    float lnA = fmaxf(nA, MINN), lnB = fmaxf(nB, MINN);
    float sA = atanh_clip(lnA) / lnA, sB = atanh_clip(lnB) / lnB;
    float tA0 = fmaxf(A0 * sA, 0.f), tA1 = fmaxf(A1 * sA, 0.f);
    float tB0 = fmaxf(B0 * sB, 0.f), tB1 = fmaxf(B1 * sB, 0.f);
    float t2A = tA0 * tA0 + tA1 * tA1, t2B = tB0 * tB0 + tB1 * tB1;
    wsum2(t2A, t2B);
    float tnA = sqrtf(t2A), tnB = sqrtf(t2B);
    float tcA = fmaxf(tnA, MINN), tcB = fmaxf(tnB, MINN);
    float seA = tanhf(tcA) / tcA, seB = tanhf(tcB) / tcB;
    A0 = tA0 * seA; A1 = tA1 * seA; nA = seA * tnA;
    B0 = tB0 * seB; B1 = tB1 * seB; nB = seB * tnB;
    proj2(A0, A1, nA);
    proj2(B0, B1, nB);
}

// One square (64->64) hyperbolic layer for 2 nodes held across the warp.
// Wt: 64*32 float2, Wt[k*32+j] = (W[j][k], W[j+32][k]).
// xb: per-warp 64 float2 staging buffer, xb[k] = (xA[k], xB[k]).
__device__ __forceinline__ void do_layer64(
    float& A0, float& A1, float& nA,
    float& B0, float& B1, float& nB,
    const float2* __restrict__ Wt, const float* __restrict__ eb, float ebn2,
    float2* xb, int j, bool act) {
    __syncwarp();
    xb[j] = make_float2(A0, B0);
    xb[32 + j] = make_float2(A1, B1);
    __syncwarp();
    float mA0 = 0.f, mA1 = 0.f, mB0 = 0.f, mB1 = 0.f;
#pragma unroll
    for (int k = 0; k < 64; k++) {
        float2 xk = xb[k];
        float2 wk = Wt[k * 32 + j];
        mA0 = fmaf(xk.x, wk.x, mA0);
        mA1 = fmaf(xk.x, wk.y, mA1);
        mB0 = fmaf(xk.y, wk.x, mB0);
        mB1 = fmaf(xk.y, wk.y, mB1);
    }
    // mobius_matvec scale
    float xnA = fmaxf(nA, MINN), xnB = fmaxf(nB, MINN);
    float s2A = mA0 * mA0 + mA1 * mA1, s2B = mB0 * mB0 + mB1 * mB1;
    wsum2(s2A, s2B);
    float mlenA = sqrtf(s2A), mlenB = sqrtf(s2B);
    float mxnA = fmaxf(mlenA, MINN), mxnB = fmaxf(mlenB, MINN);
    float rA = tanhf(mxnA / xnA * atanh_clip(xnA));
    float rB = tanhf(mxnB / xnB * atanh_clip(xnB));
    float scA = rA / mxnA, scB = rB / mxnB;
    A0 = mA0 * scA; A1 = mA1 * scA; nA = rA * (mlenA / mxnA);
    B0 = mB0 * scB; B1 = mB1 * scB; nB = rB * (mlenB / mxnB);
    proj2(A0, A1, nA);
    proj2(B0, B1, nB);
    // mobius_add(h, expmap0(b))
    float e0 = eb[j], e1 = eb[32 + j];
    float xyA = A0 * e0 + A1 * e1, xyB = B0 * e0 + B1 * e1;
    wsum2(xyA, xyB);
    {
        float x2 = nA * nA;
        float c1 = 1.f + 2.f * xyA + ebn2, c2 = 1.f - x2;
        float den = fmaxf(1.f + 2.f * xyA + x2 * ebn2, MINN);
        A0 = (c1 * A0 + c2 * e0) / den;
        A1 = (c1 * A1 + c2 * e1) / den;
    }
    {
        float x2 = nB * nB;
        float c1 = 1.f + 2.f * xyB + ebn2, c2 = 1.f - x2;
        float den = fmaxf(1.f + 2.f * xyB + x2 * ebn2, MINN);
        B0 = (c1 * B0 + c2 * e0) / den;
        B1 = (c1 * B1 + c2 * e1) / den;
    }
    float q2A = A0 * A0 + A1 * A1, q2B = B0 * B0 + B1 * B1;
    wsum2(q2A, q2B);
    nA = sqrtf(q2A); nB = sqrtf(q2B);
    proj2(A0, A1, nA);
    proj2(B0, B1, nB);
    if (act) act2(A0, A1, nA, B0, B1, nB);
}

// Final 64->32 layer (no act), Wt: 64*32 floats, Wt[k*32+j] = W6[j*64+k]
__device__ __forceinline__ void do_layer_out(
    float& A0, float& nA, float& B0, float& nB,
    float A1, float B1,
    const float* __restrict__ Wt, const float* __restrict__ eb, float ebn2,
    float2* xb, int j) {
    __syncwarp();
    xb[j] = make_float2(A0, B0);
    xb[32 + j] = make_float2(A1, B1);
    __syncwarp();
    float mA = 0.f, mB = 0.f;
#pragma unroll
    for (int k = 0; k < 64; k++) {
        float2 xk = xb[k];
        float w = Wt[k * 32 + j];
        mA = fmaf(xk.x, w, mA);
        mB = fmaf(xk.y, w, mB);
    }
    float xnA = fmaxf(nA, MINN), xnB = fmaxf(nB, MINN);
    float s2A = mA * mA, s2B = mB * mB;
    wsum2(s2A, s2B);
    float mlenA = sqrtf(s2A), mlenB = sqrtf(s2B);
    float mxnA = fmaxf(mlenA, MINN), mxnB = fmaxf(mlenB, MINN);
    float rA = tanhf(mxnA / xnA * atanh_clip(xnA));
    float rB = tanhf(mxnB / xnB * atanh_clip(xnB));
    A0 = mA * (rA / mxnA); nA = rA * (mlenA / mxnA);
    B0 = mB * (rB / mxnB); nB = rB * (mlenB / mxnB);
    float d1 = 0.f;
    proj2(A0, d1, nA);
    d1 = 0.f;
    proj2(B0, d1, nB);
    // mobius_add with 32-dim bias
    float e0 = eb[j];
    float xyA = A0 * e0, xyB = B0 * e0;
    wsum2(xyA, xyB);
    {
        float x2 = nA * nA;
        float c1 = 1.f + 2.f * xyA + ebn2, c2 = 1.f - x2;
        float den = fmaxf(1.f + 2.f * xyA + x2 * ebn2, MINN);
        A0 = (c1 * A0 + c2 * e0) / den;
    }
    {
        float x2 = nB * nB;
        float c1 = 1.f + 2.f * xyB + ebn2, c2 = 1.f - x2;
        float den = fmaxf(1.f + 2.f * xyB + x2 * ebn2, MINN);
        B0 = (c1 * B0 + c2 * e0) / den;
    }
    float q2A = A0 * A0, q2B = B0 * B0;
    wsum2(q2A, q2B);
    nA = sqrtf(q2A); nB = sqrtf(q2B);
    d1 = 0.f; proj2(A0, d1, nA);
    d1 = 0.f; proj2(B0, d1, nB);
}

// bias -> eb = expmap0(b) (dim floats), and |eb|^2; computed by one warp
__device__ __forceinline__ void compute_eb64(const float* __restrict__ b,
                                             float* eb, float* ebn2, int j) {
    float v0 = b[j], v1 = b[32 + j];
    float s2 = v0 * v0 + v1 * v1, dummy = 0.f;
    wsum2(s2, dummy);
    float bn = sqrtf(s2), bc = fmaxf(bn, MINN);
    float se = tanhf(bc) / bc;
    eb[j] = v0 * se;
    eb[32 + j] = v1 * se;
    if (j == 0) *ebn2 = (se * bn) * (se * bn);
}

// ---------------- kernel A: poincare + layers 1..4 (matvec/bias) + logmap ----
__global__ void __launch_bounds__(256) nodeA_kernel(
    const float* __restrict__ x,
    const float* __restrict__ W1, const float* __restrict__ b1,
    const float* __restrict__ W2, const float* __restrict__ b2,
    const float* __restrict__ W3, const float* __restrict__ b3,
    const float* __restrict__ W4, const float* __restrict__ b4) {
    extern __shared__ unsigned char smem_raw[];
    float2* Ws = (float2*)smem_raw;           // 4 * 64 * 32 float2
    float2* xbuf = Ws + 4 * 2048;             // 8 warps * 64 float2
    float* eb = (float*)(xbuf + 8 * 64);      // 4 * 64 floats
    float* ebn2 = eb + 4 * 64;                // 4 floats
    int tid = threadIdx.x;

    const float* Wp[4] = {W1, W2, W3, W4};
#pragma unroll
    for (int L = 0; L < 4; L++) {
        const float* W = Wp[L];
        int K = (L == 0) ? 63 : 64;
        for (int i = tid; i < 2048; i += 256) {
            int k = i >> 5, j = i & 31;
            float2 v = make_float2(0.f, 0.f);
            if (k < K) { v.x = W[j * K + k]; v.y = W[(j + 32) * K + k]; }
            Ws[L * 2048 + k * 32 + j] = v;
        }
    }
    int w = tid >> 5, j = tid & 31;
    if (w < 4) {
        const float* bp[4] = {b1, b2, b3, b4};
        compute_eb64(bp[w], eb + w * 64, ebn2 + w, j);
    }
    __syncthreads();

    int iA = blockIdx.x * 16 + w * 2;
    int iB = iA + 1;
    float2* xb = xbuf + w * 64;
    const float* xA = x + (size_t)iA * 64;
    const float* xB = x + (size_t)iB * 64;
    float invA = 1.f / (xA[0] + 1.f);
    float invB = 1.f / (xB[0] + 1.f);
    float A0 = xA[1 + j] * invA;
    float A1 = (j < 31) ? xA[33 + j] * invA : 0.f;
    float B0 = xB[1 + j] * invB;
    float B1 = (j < 31) ? xB[33 + j] * invB : 0.f;
    float n2A = A0 * A0 + A1 * A1, n2B = B0 * B0 + B1 * B1;
    wsum2(n2A, n2B);
    float nA = sqrtf(n2A), nB = sqrtf(n2B);
    proj2(A0, A1, nA);
    proj2(B0, B1, nB);

    do_layer64(A0, A1, nA, B0, B1, nB, Ws,        eb,       ebn2[0], xb, j, true);
    do_layer64(A0, A1, nA, B0, B1, nB, Ws + 2048, eb + 64,  ebn2[1], xb, j, true);
    do_layer64(A0, A1, nA, B0, B1, nB, Ws + 4096, eb + 128, ebn2[2], xb, j, true);
    do_layer64(A0, A1, nA, B0, B1, nB, Ws + 6144, eb + 192, ebn2[3], xb, j, false);

    // t = logmap0(h)
    float lA = fmaxf(nA, MINN), lB = fmaxf(nB, MINN);
    float sA = atanh_clip(lA) / lA, sB = atanh_clip(lB) / lB;
    g_t[(size_t)iA * 64 + j] = A0 * sA;
    g_t[(size_t)iA * 64 + 32 + j] = A1 * sA;
    g_t[(size_t)iB * 64 + j] = B0 * sB;
    g_t[(size_t)iB * 64 + 32 + j] = B1 * sB;
}

// ---------------- kernel B: agg epilogue of L4 + act + layer 5 + logmap -----
__global__ void __launch_bounds__(256) nodeB_kernel(
    const float* __restrict__ W5, const float* __restrict__ b5) {
    extern __shared__ unsigned char smem_raw[];
    float2* Ws = (float2*)smem_raw;          // 2048 float2
    float2* xbuf = Ws + 2048;                // 8 * 64 float2
    float* eb = (float*)(xbuf + 8 * 64);     // 64
    float* ebn2 = eb + 64;                   // 1 (+pad)
    int tid = threadIdx.x;
    for (int i = tid; i < 2048; i += 256) {
        int k = i >> 5, j = i & 31;
        Ws[k * 32 + j] = make_float2(W5[j * 64 + k], W5[(j + 32) * 64 + k]);
    }
    int w = tid >> 5, j = tid & 31;
    if (w == 0) compute_eb64(b5, eb, ebn2, j);
    __syncthreads();

    int iA = blockIdx.x * 16 + w * 2;
    int iB = iA + 1;
    float2* xb = xbuf + w * 64;
    float dA = fmaxf(g_deg[iA], 1.f), dB = fmaxf(g_deg[iB], 1.f);
    float A0 = g_agg[(size_t)iA * 64 + j] / dA;
    float A1 = g_agg[(size_t)iA * 64 + 32 + j] / dA;
    float B0 = g_agg[(size_t)iB * 64 + j] / dB;
    float B1 = g_agg[(size_t)iB * 64 + 32 + j] / dB;
    // h = proj(expmap0(agg))
    float n2A = A0 * A0 + A1 * A1, n2B = B0 * B0 + B1 * B1;
    wsum2(n2A, n2B);
    float unA = sqrtf(n2A), unB = sqrtf(n2B);
    float ucA = fmaxf(unA, MINN), ucB = fmaxf(unB, MINN);
    float seA = tanhf(ucA) / ucA, seB = tanhf(ucB) / ucB;
    A0 *= seA; A1 *= seA; float nA = seA * unA;
    B0 *= seB; B1 *= seB; float nB = seB * unB;
    proj2(A0, A1, nA);
    proj2(B0, B1, nB);
    // layer-4 activation
    act2(A0, A1, nA, B0, B1, nB);
    // layer 5 matvec + bias (no act before agg)
    do_layer64(A0, A1, nA, B0, B1, nB, Ws, eb, ebn2[0], xb, j, false);
    // logmap0 -> g_t
    float lA = fmaxf(nA, MINN), lB = fmaxf(nB, MINN);
    float sA = atanh_clip(lA) / lA, sB = atanh_clip(lB) / lB;
    g_t[(size_t)iA * 64 + j] = A0 * sA;
    g_t[(size_t)iA * 64 + 32 + j] = A1 * sA;
    g_t[(size_t)iB * 64 + j] = B0 * sB;
    g_t[(size_t)iB * 64 + 32 + j] = B1 * sB;
}

// ---------------- kernel C: agg epilogue of L5 + act + layer 6 -> out -------
__global__ void __launch_bounds__(256) nodeC_kernel(
    const float* __restrict__ W6, const float* __restrict__ b6,
    float* __restrict__ out) {
    extern __shared__ unsigned char smem_raw[];
    float* Ws = (float*)smem_raw;            // 64*32 floats
    float2* xbuf = (float2*)(Ws + 2048);     // 8 * 64 float2
    float* eb = (float*)(xbuf + 8 * 64);     // 32
    float* ebn2 = eb + 32;                   // 1
    int tid = threadIdx.x;
    for (int i = tid; i < 2048; i += 256) {
        int k = i >> 5, j = i & 31;
        Ws[k * 32 + j] = W6[j * 64 + k];
    }
    int w = tid >> 5, j = tid & 31;
    if (w == 0) {
        float v0 = b6[j];
        float s2 = v0 * v0, dummy = 0.f;
        wsum2(s2, dummy);
        float bn = sqrtf(s2), bc = fmaxf(bn, MINN);
        float se = tanhf(bc) / bc;
        eb[j] = v0 * se;
        if (j == 0) *ebn2 = (se * bn) * (se * bn);
    }
    __syncthreads();

    int iA = blockIdx.x * 16 + w * 2;
    int iB = iA + 1;
    float2* xb = xbuf + w * 64;
    float dA = fmaxf(g_deg[iA], 1.f), dB = fmaxf(g_deg[iB], 1.f);
    float A0 = g_agg[(size_t)iA * 64 + j] / dA;
    float A1 = g_agg[(size_t)iA * 64 + 32 + j] / dA;
    float B0 = g_agg[(size_t)iB * 64 + j] / dB;
    float B1 = g_agg[(size_t)iB * 64 + 32 + j] / dB;
    float n2A = A0 * A0 + A1 * A1, n2B = B0 * B0 + B1 * B1;
    wsum2(n2A, n2B);
    float unA = sqrtf(n2A), unB = sqrtf(n2B);
    float ucA = fmaxf(unA, MINN), ucB = fmaxf(unB, MINN);
    float seA = tanhf(ucA) / ucA, seB = tanhf(ucB) / ucB;
    A0 *= seA; A1 *= seA; float nA = seA * unA;
    B0 *= seB; B1 *= seB; float nB = seB * unB;
    proj2(A0, A1, nA);
    proj2(B0, B1, nB);
    // layer-5 activation
    act2(A0, A1, nA, B0, B1, nB);
    // layer 6: 64 -> 32, bias, proj, no act
    do_layer_out(A0, nA, B0, nB, A1, B1, Ws, eb, ebn2[0], xb, j);
    out[(size_t)iA * 32 + j] = A0;
    out[(size_t)iB * 32 + j] = B0;
}

// ---------------- edge scatter: agg[dst] += t[src]; optional degree ---------
__global__ void __launch_bounds__(256) scatter_kernel(const void* __restrict__ edges,
                                                      int withDeg) {
    long long i = (long long)blockIdx.x * 256 + threadIdx.x;  // 0 .. EE*16
    int e = (int)(i >> 4);
    int c = (int)(i & 15);
    if (e >= EE) return;
    long long src, dst;
    if (g_idx64) {
        const long long* p = (const long long*)edges;
        src = p[e];
        dst = p[EE + e];
    } else {
        const int* p = (const int*)edges;
        src = p[e];
        dst = p[EE + e];
    }
    const float4 v = *(const float4*)(g_t + (size_t)src * 64 + c * 4);
    float* ap = g_agg + (size_t)dst * 64 + c * 4;
    asm volatile("red.global.add.v4.f32 [%0], {%1,%2,%3,%4};"
                 :: "l"(ap), "f"(v.x), "f"(v.y), "f"(v.z), "f"(v.w)
                 : "memory");
    if (withDeg && c == 0) atomicAdd(g_deg + dst, 1.0f);
}

// ---------------- zero scratch ----------------
__global__ void __launch_bounds__(256) zero_kernel(int withDeg) {
    size_t i = (size_t)blockIdx.x * 256 + threadIdx.x;  // over NN*16 float4
    if (i < (size_t)NN * 16) ((float4*)g_agg)[i] = make_float4(0.f, 0.f, 0.f, 0.f);
    if (withDeg && i < NN) g_deg[i] = 0.f;
}

// ---------------- edge index dtype detection (int64 vs int32) ---------------
__global__ void detect_kernel(const int* __restrict__ e32) {
    __shared__ int nz;
    if (threadIdx.x == 0) nz = 0;
    __syncthreads();
    for (int i = threadIdx.x; i < 1024; i += 256)
        if (e32[2 * i + 1] != 0) atomicAdd(&nz, 1);
    __syncthreads();
    if (threadIdx.x == 0) g_idx64 = (nz == 0) ? 1 : 0;
}

// ---------------- launch ----------------
extern "C" void kernel_launch(void* const* d_in, const int* in_sizes, int n_in,
                              void* d_out, int out_size) {
    const float* x = (const float*)d_in[0];
    const float* W1 = (const float*)d_in[1];
    const float* b1 = (const float*)d_in[2];
    const float* W2 = (const float*)d_in[3];
    const float* b2 = (const float*)d_in[4];
    const float* W3 = (const float*)d_in[5];
    const float* b3 = (const float*)d_in[6];
    const float* W4 = (const float*)d_in[7];
    const float* b4 = (const float*)d_in[8];
    const float* W5 = (const float*)d_in[9];
    const float* b5 = (const float*)d_in[10];
    const float* W6 = (const float*)d_in[11];
    const float* b6 = (const float*)d_in[12];
    const void* edges = d_in[13];
    float* out = (float*)d_out;

    const int SMEM_A = 4 * 2048 * 8 + 8 * 64 * 8 + 4 * 64 * 4 + 16;     // 70672
    const int SMEM_B = 2048 * 8 + 8 * 64 * 8 + 64 * 4 + 16;             // 20752
    const int SMEM_C = 2048 * 4 + 8 * 64 * 8 + 32 * 4 + 16;             // 12432

    cudaFuncSetAttribute(nodeA_kernel, cudaFuncAttributeMaxDynamicSharedMemorySize, SMEM_A);

    const int NODE_BLOCKS = NN / 16;                 // 6250
    const int SCAT_BLOCKS = (EE * 16) / 256;         // 100000
    const int ZERO_BLOCKS = (NN * 16 + 255) / 256;   // 6250

    detect_kernel<<<1, 256>>>((const int*)edges);
    zero_kernel<<<ZERO_BLOCKS, 256>>>(1);
    nodeA_kernel<<<NODE_BLOCKS, 256, SMEM_A>>>(x, W1, b1, W2, b2, W3, b3, W4, b4);
    scatter_kernel<<<SCAT_BLOCKS, 256>>>(edges, 1);
    nodeB_kernel<<<NODE_BLOCKS, 256, SMEM_B>>>(W5, b5);
    zero_kernel<<<ZERO_BLOCKS, 256>>>(0);
    scatter_kernel<<<SCAT_BLOCKS, 256>>>(edges, 0);
    nodeC_kernel<<<NODE_BLOCKS, 256, SMEM_C>>>(W6, b6, out);
}

// round 2
// speedup vs baseline: 1.3733x; 1.3733x over previous
#include <cuda_runtime.h>
#include <cstdint>

#define NN 100000
#define EE 1600000
#define MINN 1e-15f
#define MAXN ((float)(1.0 - 1e-5))

// ---------------- scratch (device globals; no allocs allowed) ----------------
__device__ __align__(16) float g_t[(size_t)NN * 64];
__device__ __align__(16) float g_agg[(size_t)NN * 64];
__device__ float g_deg[NN];
__device__ int g_idx64;

// ---------------- fast math (all args nonnegative here) ----------------
__device__ __forceinline__ float fast_tanh(float x) {   // x >= 0
    float e = __expf(-2.f * x);
    return __fdividef(1.f - e, 1.f + e);
}
__device__ __forceinline__ float fast_atanh(float x) {  // 0 <= x < 1
    x = fminf(x, MAXN);
    return 0.5f * __logf(__fdividef(1.f + x, 1.f - x));
}

__device__ __forceinline__ void wsum4(float* v) {
#pragma unroll
    for (int o = 16; o > 0; o >>= 1) {
#pragma unroll
        for (int q = 0; q < 4; q++) v[q] += __shfl_xor_sync(0xffffffffu, v[q], o);
    }
}

__device__ __forceinline__ void proj1(float& a, float& b, float& n) {
    n = fmaxf(n, MINN);
    if (n > MAXN) {
        float s = __fdividef(MAXN, n);
        a *= s; b *= s; n = MAXN;
    }
}

// act: h = proj(expmap0(relu(logmap0(h)))) for 4 nodes
__device__ __forceinline__ void act4(float h0[4], float h1[4], float n[4]) {
    float t2[4];
#pragma unroll
    for (int q = 0; q < 4; q++) {
        float ln = fmaxf(n[q], MINN);
        float s = __fdividef(fast_atanh(ln), ln);
        h0[q] = fmaxf(h0[q] * s, 0.f);
        h1[q] = fmaxf(h1[q] * s, 0.f);
        t2[q] = h0[q] * h0[q] + h1[q] * h1[q];
    }
    wsum4(t2);
#pragma unroll
    for (int q = 0; q < 4; q++) {
        float tn = sqrtf(t2[q]);
        float tc = fmaxf(tn, MINN);
        float se = __fdividef(fast_tanh(tc), tc);
        h0[q] *= se; h1[q] *= se; n[q] = se * tn;
        proj1(h0[q], h1[q], n[q]);
    }
}

// One 64->64 hyperbolic layer for 4 nodes held across the warp.
// Wt: 64*32 float2, Wt[k*32+j] = (W[j][k], W[j+32][k]).
// xb: per-warp 64 float4 staging, xb[k] = x[k] of nodes 0..3.
__device__ __forceinline__ void layer64_4(
    float h0[4], float h1[4], float n[4],
    const float2* __restrict__ Wt, const float* __restrict__ eb, float ebn2,
    float4* xb, int j, bool act) {
    __syncwarp();
    xb[j]      = make_float4(h0[0], h0[1], h0[2], h0[3]);
    xb[32 + j] = make_float4(h1[0], h1[1], h1[2], h1[3]);
    __syncwarp();
    float m0[4] = {0.f, 0.f, 0.f, 0.f}, m1[4] = {0.f, 0.f, 0.f, 0.f};
#pragma unroll
    for (int k = 0; k < 64; k++) {
        float4 xk = xb[k];
        float2 wk = Wt[k * 32 + j];
        m0[0] = fmaf(xk.x, wk.x, m0[0]); m1[0] = fmaf(xk.x, wk.y, m1[0]);
        m0[1] = fmaf(xk.y, wk.x, m0[1]); m1[1] = fmaf(xk.y, wk.y, m1[1]);
        m0[2] = fmaf(xk.z, wk.x, m0[2]); m1[2] = fmaf(xk.z, wk.y, m1[2]);
        m0[3] = fmaf(xk.w, wk.x, m0[3]); m1[3] = fmaf(xk.w, wk.y, m1[3]);
    }
    float s2[4];
#pragma unroll
    for (int q = 0; q < 4; q++) s2[q] = m0[q] * m0[q] + m1[q] * m1[q];
    wsum4(s2);
#pragma unroll
    for (int q = 0; q < 4; q++) {
        float xn = fmaxf(n[q], MINN);
        float ml = sqrtf(s2[q]);
        float mx = fmaxf(ml, MINN);
        float r = fast_tanh(__fdividef(mx, xn) * fast_atanh(xn));
        float sc = __fdividef(r, mx);
        h0[q] = m0[q] * sc; h1[q] = m1[q] * sc;
        n[q] = r * __fdividef(ml, mx);
        proj1(h0[q], h1[q], n[q]);
    }
    // mobius_add(h, expmap0(b))
    float e0 = eb[j], e1 = eb[32 + j];
    float xy[4];
#pragma unroll
    for (int q = 0; q < 4; q++) xy[q] = h0[q] * e0 + h1[q] * e1;
    wsum4(xy);
#pragma unroll
    for (int q = 0; q < 4; q++) {
        float x2 = n[q] * n[q];
        float c1 = 1.f + 2.f * xy[q] + ebn2, c2 = 1.f - x2;
        float den = fmaxf(1.f + 2.f * xy[q] + x2 * ebn2, MINN);
        float inv = __fdividef(1.f, den);
        h0[q] = (c1 * h0[q] + c2 * e0) * inv;
        h1[q] = (c1 * h1[q] + c2 * e1) * inv;
    }
    float q2[4];
#pragma unroll
    for (int q = 0; q < 4; q++) q2[q] = h0[q] * h0[q] + h1[q] * h1[q];
    wsum4(q2);
#pragma unroll
    for (int q = 0; q < 4; q++) { n[q] = sqrtf(q2[q]); proj1(h0[q], h1[q], n[q]); }
    if (act) act4(h0, h1, n);
}

// Final 64->32 layer (no act), Wt[k*32+j] = W6[j*64+k]. Output in o[4].
__device__ __forceinline__ void layer_out_4(
    float h0[4], float h1[4], float n[4], float o[4],
    const float* __restrict__ Wt, const float* __restrict__ eb, float ebn2,
    float4* xb, int j) {
    __syncwarp();
    xb[j]      = make_float4(h0[0], h0[1], h0[2], h0[3]);
    xb[32 + j] = make_float4(h1[0], h1[1], h1[2], h1[3]);
    __syncwarp();
    float m[4] = {0.f, 0.f, 0.f, 0.f};
#pragma unroll
    for (int k = 0; k < 64; k++) {
        float4 xk = xb[k];
        float w = Wt[k * 32 + j];
        m[0] = fmaf(xk.x, w, m[0]); m[1] = fmaf(xk.y, w, m[1]);
        m[2] = fmaf(xk.z, w, m[2]); m[3] = fmaf(xk.w, w, m[3]);
    }
    float s2[4];
#pragma unroll
    for (int q = 0; q < 4; q++) s2[q] = m[q] * m[q];
    wsum4(s2);
    float nn[4];
#pragma unroll
    for (int q = 0; q < 4; q++) {
        float xn = fmaxf(n[q], MINN);
        float ml = sqrtf(s2[q]);
        float mx = fmaxf(ml, MINN);
        float r = fast_tanh(__fdividef(mx, xn) * fast_atanh(xn));
        o[q] = m[q] * __fdividef(r, mx);
        nn[q] = r * __fdividef(ml, mx);
        float d = 0.f;
        proj1(o[q], d, nn[q]);
    }
    float e0 = eb[j];
    float xy[4];
#pragma unroll
    for (int q = 0; q < 4; q++) xy[q] = o[q] * e0;
    wsum4(xy);
#pragma unroll
    for (int q = 0; q < 4; q++) {
        float x2 = nn[q] * nn[q];
        float c1 = 1.f + 2.f * xy[q] + ebn2, c2 = 1.f - x2;
        float den = fmaxf(1.f + 2.f * xy[q] + x2 * ebn2, MINN);
        o[q] = (c1 * o[q] + c2 * e0) * __fdividef(1.f, den);
    }
    float q2[4];
#pragma unroll
    for (int q = 0; q < 4; q++) q2[q] = o[q] * o[q];
    wsum4(q2);
#pragma unroll
    for (int q = 0; q < 4; q++) {
        float nf = sqrtf(q2[q]), d = 0.f;
        proj1(o[q], d, nf);
    }
}

// bias -> eb = expmap0(b), |eb|^2 (dim 64), one warp
__device__ __forceinline__ void compute_eb64(const float* __restrict__ b,
                                             float* eb, float* ebn2, int j) {
    float v0 = b[j], v1 = b[32 + j];
    float s2[4] = {v0 * v0 + v1 * v1, 0.f, 0.f, 0.f};
    wsum4(s2);
    float bn = sqrtf(s2[0]), bc = fmaxf(bn, MINN);
    float se = __fdividef(fast_tanh(bc), bc);
    eb[j] = v0 * se;
    eb[32 + j] = v1 * se;
    if (j == 0) *ebn2 = (se * bn) * (se * bn);
}

// expmap0 of aggregated mean + proj, for 4 nodes (loads from g_agg/g_deg)
__device__ __forceinline__ void load_agg4(int iBase, int j,
                                          float h0[4], float h1[4], float n[4]) {
    float n2[4];
#pragma unroll
    for (int q = 0; q < 4; q++) {
        float d = fmaxf(g_deg[iBase + q], 1.f);
        float inv = __fdividef(1.f, d);
        h0[q] = g_agg[(size_t)(iBase + q) * 64 + j] * inv;
        h1[q] = g_agg[(size_t)(iBase + q) * 64 + 32 + j] * inv;
        n2[q] = h0[q] * h0[q] + h1[q] * h1[q];
    }
    wsum4(n2);
#pragma unroll
    for (int q = 0; q < 4; q++) {
        float un = sqrtf(n2[q]);
        float uc = fmaxf(un, MINN);
        float se = __fdividef(fast_tanh(uc), uc);
        h0[q] *= se; h1[q] *= se; n[q] = se * un;
        proj1(h0[q], h1[q], n[q]);
    }
}

// ---------------- kernel A: poincare + layers 1..4 + logmap ----------------
__global__ void __launch_bounds__(256) nodeA_kernel(
    const float* __restrict__ x,
    const float* __restrict__ W1, const float* __restrict__ b1,
    const float* __restrict__ W2, const float* __restrict__ b2,
    const float* __restrict__ W3, const float* __restrict__ b3,
    const float* __restrict__ W4, const float* __restrict__ b4) {
    extern __shared__ unsigned char smem_raw[];
    float2* Ws = (float2*)smem_raw;            // 4 * 2048 float2 = 64KB
    float4* xbuf = (float4*)(Ws + 4 * 2048);   // 8 warps * 64 float4 = 8KB
    float* eb = (float*)(xbuf + 8 * 64);       // 4 * 64
    float* ebn2 = eb + 4 * 64;                 // 4
    int tid = threadIdx.x;

    const float* Wp[4] = {W1, W2, W3, W4};
#pragma unroll
    for (int L = 0; L < 4; L++) {
        const float* W = Wp[L];
        int K = (L == 0) ? 63 : 64;
        for (int i = tid; i < 2048; i += 256) {
            int k = i >> 5, j = i & 31;
            float2 v = make_float2(0.f, 0.f);
            if (k < K) { v.x = W[j * K + k]; v.y = W[(j + 32) * K + k]; }
            Ws[L * 2048 + k * 32 + j] = v;
        }
    }
    int w = tid >> 5, j = tid & 31;
    if (w < 4) {
        const float* bp[4] = {b1, b2, b3, b4};
        compute_eb64(bp[w], eb + w * 64, ebn2 + w, j);
    }
    __syncthreads();

    int iBase = blockIdx.x * 32 + w * 4;
    float4* xb = xbuf + w * 64;
    float h0[4], h1[4], n[4], n2[4];
#pragma unroll
    for (int q = 0; q < 4; q++) {
        const float* xp = x + (size_t)(iBase + q) * 64;
        float inv = __fdividef(1.f, xp[0] + 1.f);
        h0[q] = xp[1 + j] * inv;
        h1[q] = (j < 31) ? xp[33 + j] * inv : 0.f;
        n2[q] = h0[q] * h0[q] + h1[q] * h1[q];
    }
    wsum4(n2);
#pragma unroll
    for (int q = 0; q < 4; q++) { n[q] = sqrtf(n2[q]); proj1(h0[q], h1[q], n[q]); }

    layer64_4(h0, h1, n, Ws,        eb,       ebn2[0], xb, j, true);
    layer64_4(h0, h1, n, Ws + 2048, eb + 64,  ebn2[1], xb, j, true);
    layer64_4(h0, h1, n, Ws + 4096, eb + 128, ebn2[2], xb, j, true);
    layer64_4(h0, h1, n, Ws + 6144, eb + 192, ebn2[3], xb, j, false);

#pragma unroll
    for (int q = 0; q < 4; q++) {
        float ln = fmaxf(n[q], MINN);
        float s = __fdividef(fast_atanh(ln), ln);
        g_t[(size_t)(iBase + q) * 64 + j] = h0[q] * s;
        g_t[(size_t)(iBase + q) * 64 + 32 + j] = h1[q] * s;
    }
}

// ---------------- kernel B: agg(L4) + act + layer 5 + logmap ----------------
__global__ void __launch_bounds__(256) nodeB_kernel(
    const float* __restrict__ W5, const float* __restrict__ b5) {
    extern __shared__ unsigned char smem_raw[];
    float2* Ws = (float2*)smem_raw;            // 2048 float2
    float4* xbuf = (float4*)(Ws + 2048);       // 8 * 64 float4
    float* eb = (float*)(xbuf + 8 * 64);       // 64
    float* ebn2 = eb + 64;
    int tid = threadIdx.x;
    for (int i = tid; i < 2048; i += 256) {
        int k = i >> 5, j = i & 31;
        Ws[k * 32 + j] = make_float2(W5[j * 64 + k], W5[(j + 32) * 64 + k]);
    }
    int w = tid >> 5, j = tid & 31;
    if (w == 0) compute_eb64(b5, eb, ebn2, j);
    __syncthreads();

    int iBase = blockIdx.x * 32 + w * 4;
    float4* xb = xbuf + w * 64;
    float h0[4], h1[4], n[4];
    load_agg4(iBase, j, h0, h1, n);
    act4(h0, h1, n);                                     // layer-4 activation
    layer64_4(h0, h1, n, Ws, eb, ebn2[0], xb, j, false); // layer-5 matvec+bias
#pragma unroll
    for (int q = 0; q < 4; q++) {
        float ln = fmaxf(n[q], MINN);
        float s = __fdividef(fast_atanh(ln), ln);
        g_t[(size_t)(iBase + q) * 64 + j] = h0[q] * s;
        g_t[(size_t)(iBase + q) * 64 + 32 + j] = h1[q] * s;
    }
}

// ---------------- kernel C: agg(L5) + act + layer 6 -> out ------------------
__global__ void __launch_bounds__(256) nodeC_kernel(
    const float* __restrict__ W6, const float* __restrict__ b6,
    float* __restrict__ out) {
    extern __shared__ unsigned char smem_raw[];
    float* Ws = (float*)smem_raw;              // 64*32 floats
    float4* xbuf = (float4*)(Ws + 2048);       // 8 * 64 float4
    float* eb = (float*)(xbuf + 8 * 64);       // 32
    float* ebn2 = eb + 32;
    int tid = threadIdx.x;
    for (int i = tid; i < 2048; i += 256) {
        int k = i >> 5, j = i & 31;
        Ws[k * 32 + j] = W6[j * 64 + k];
    }
    int w = tid >> 5, j = tid & 31;
    if (w == 0) {
        float v0 = b6[j];
        float s2[4] = {v0 * v0, 0.f, 0.f, 0.f};
        wsum4(s2);
        float bn = sqrtf(s2[0]), bc = fmaxf(bn, MINN);
        float se = __fdividef(fast_tanh(bc), bc);
        eb[j] = v0 * se;
        if (j == 0) *ebn2 = (se * bn) * (se * bn);
    }
    __syncthreads();

    int iBase = blockIdx.x * 32 + w * 4;
    float4* xb = xbuf + w * 64;
    float h0[4], h1[4], n[4], o[4];
    load_agg4(iBase, j, h0, h1, n);
    act4(h0, h1, n);                                  // layer-5 activation
    layer_out_4(h0, h1, n, o, Ws, eb, ebn2[0], xb, j);
#pragma unroll
    for (int q = 0; q < 4; q++)
        out[(size_t)(iBase + q) * 32 + j] = o[q];
}

// ---------------- edge scatter: agg[dst] += t[src] (8 threads/edge) ---------
__global__ void __launch_bounds__(256) scatter_kernel(const void* __restrict__ edges,
                                                      int withDeg) {
    int i = blockIdx.x * 256 + threadIdx.x;  // 0 .. EE*8
    int e = i >> 3;
    int c = i & 7;
    if (e >= EE) return;
    int src, dst;
    if (g_idx64) {
        const long long* p = (const long long*)edges;
        src = (int)__ldg(p + e);
        dst = (int)__ldg(p + EE + e);
    } else {
        const int* p = (const int*)edges;
        src = __ldg(p + e);
        dst = __ldg(p + EE + e);
    }
    const float4* tp = (const float4*)(g_t + (size_t)src * 64) + c * 2;
    float4 v0 = __ldg(tp);
    float4 v1 = __ldg(tp + 1);
    float4* ap = (float4*)(g_agg + (size_t)dst * 64) + c * 2;
    asm volatile("red.global.add.v4.f32 [%0], {%1,%2,%3,%4};"
                 :: "l"(ap), "f"(v0.x), "f"(v0.y), "f"(v0.z), "f"(v0.w)
                 : "memory");
    asm volatile("red.global.add.v4.f32 [%0], {%1,%2,%3,%4};"
                 :: "l"(ap + 1), "f"(v1.x), "f"(v1.y), "f"(v1.z), "f"(v1.w)
                 : "memory");
    if (withDeg && c == 0) atomicAdd(g_deg + dst, 1.0f);
}

// ---------------- zero scratch ----------------
__global__ void __launch_bounds__(256) zero_kernel(int withDeg) {
    size_t i = (size_t)blockIdx.x * 256 + threadIdx.x;
    if (i < (size_t)NN * 16) ((float4*)g_agg)[i] = make_float4(0.f, 0.f, 0.f, 0.f);
    if (withDeg && i < NN) g_deg[i] = 0.f;
}

// ---------------- edge index dtype detection (int64 vs int32) ---------------
__global__ void detect_kernel(const int* __restrict__ e32) {
    __shared__ int nz;
    if (threadIdx.x == 0) nz = 0;
    __syncthreads();
    for (int i = threadIdx.x; i < 1024; i += 256)
        if (e32[2 * i + 1] != 0) atomicAdd(&nz, 1);
    __syncthreads();
    if (threadIdx.x == 0) g_idx64 = (nz == 0) ? 1 : 0;
}

// ---------------- launch ----------------
extern "C" void kernel_launch(void* const* d_in, const int* in_sizes, int n_in,
                              void* d_out, int out_size) {
    const float* x = (const float*)d_in[0];
    const float* W1 = (const float*)d_in[1];
    const float* b1 = (const float*)d_in[2];
    const float* W2 = (const float*)d_in[3];
    const float* b2 = (const float*)d_in[4];
    const float* W3 = (const float*)d_in[5];
    const float* b3 = (const float*)d_in[6];
    const float* W4 = (const float*)d_in[7];
    const float* b4 = (const float*)d_in[8];
    const float* W5 = (const float*)d_in[9];
    const float* b5 = (const float*)d_in[10];
    const float* W6 = (const float*)d_in[11];
    const float* b6 = (const float*)d_in[12];
    const void* edges = d_in[13];
    float* out = (float*)d_out;

    const int SMEM_A = 4 * 2048 * 8 + 8 * 64 * 16 + 4 * 64 * 4 + 16;  // 74768
    const int SMEM_B = 2048 * 8 + 8 * 64 * 16 + 64 * 4 + 16;          // 24848
    const int SMEM_C = 2048 * 4 + 8 * 64 * 16 + 32 * 4 + 16;          // 16528

    cudaFuncSetAttribute(nodeA_kernel, cudaFuncAttributeMaxDynamicSharedMemorySize, SMEM_A);

    const int NODE_BLOCKS = NN / 32;                 // 3125
    const int SCAT_BLOCKS = (EE * 8) / 256;          // 50000
    const int ZERO_BLOCKS = (NN * 16 + 255) / 256;   // 6250

    detect_kernel<<<1, 256>>>((const int*)edges);
    zero_kernel<<<ZERO_BLOCKS, 256>>>(1);
    nodeA_kernel<<<NODE_BLOCKS, 256, SMEM_A>>>(x, W1, b1, W2, b2, W3, b3, W4, b4);
    scatter_kernel<<<SCAT_BLOCKS, 256>>>(edges, 1);
    nodeB_kernel<<<NODE_BLOCKS, 256, SMEM_B>>>(W5, b5);
    zero_kernel<<<ZERO_BLOCKS, 256>>>(0);
    scatter_kernel<<<SCAT_BLOCKS, 256>>>(edges, 0);
    nodeC_kernel<<<NODE_BLOCKS, 256, SMEM_C>>>(W6, b6, out);
}

// round 3
// speedup vs baseline: 1.6593x; 1.2083x over previous
#include <cuda_runtime.h>
#include <cstdint>

#define NN 100000
#define EE 1600000
#define MINN 1e-15f
#define MAXN ((float)(1.0 - 1e-5))
#define SCAN_BLOCKS 98   // 98*1024 >= NN

// ---------------- scratch (device globals; no allocs allowed) ----------------
__device__ __align__(16) float g_t[(size_t)NN * 64];
__device__ __align__(16) float g_t2[(size_t)NN * 64];
__device__ int g_src[EE];
__device__ int g_dst[EE];
__device__ int g_col[EE];
__device__ int g_cnt[NN];
__device__ int g_off[NN + 1];
__device__ int g_cursor[NN];
__device__ int g_bsum[SCAN_BLOCKS];
__device__ int g_idx64;

// ---------------- fast math (all args nonnegative here) ----------------
__device__ __forceinline__ float fast_tanh(float x) {   // x >= 0
    float e = __expf(-2.f * x);
    return __fdividef(1.f - e, 1.f + e);
}
__device__ __forceinline__ float fast_atanh(float x) {  // 0 <= x < 1
    x = fminf(x, MAXN);
    return 0.5f * __logf(__fdividef(1.f + x, 1.f - x));
}

__device__ __forceinline__ void wsum4(float* v) {
#pragma unroll
    for (int o = 16; o > 0; o >>= 1) {
#pragma unroll
        for (int q = 0; q < 4; q++) v[q] += __shfl_xor_sync(0xffffffffu, v[q], o);
    }
}

__device__ __forceinline__ void proj1(float& a, float& b, float& n) {
    n = fmaxf(n, MINN);
    if (n > MAXN) {
        float s = __fdividef(MAXN, n);
        a *= s; b *= s; n = MAXN;
    }
}

// act: h = proj(expmap0(relu(logmap0(h)))) for 4 nodes
__device__ __forceinline__ void act4(float h0[4], float h1[4], float n[4]) {
    float t2[4];
#pragma unroll
    for (int q = 0; q < 4; q++) {
        float ln = fmaxf(n[q], MINN);
        float s = __fdividef(fast_atanh(ln), ln);
        h0[q] = fmaxf(h0[q] * s, 0.f);
        h1[q] = fmaxf(h1[q] * s, 0.f);
        t2[q] = h0[q] * h0[q] + h1[q] * h1[q];
    }
    wsum4(t2);
#pragma unroll
    for (int q = 0; q < 4; q++) {
        float tn = sqrtf(t2[q]);
        float tc = fmaxf(tn, MINN);
        float se = __fdividef(fast_tanh(tc), tc);
        h0[q] *= se; h1[q] *= se; n[q] = se * tn;
        proj1(h0[q], h1[q], n[q]);
    }
}

// One 64->64 hyperbolic layer for 4 nodes held across the warp.
__device__ __forceinline__ void layer64_4(
    float h0[4], float h1[4], float n[4],
    const float2* __restrict__ Wt, const float* __restrict__ eb, float ebn2,
    float4* xb, int j, bool act) {
    __syncwarp();
    xb[j]      = make_float4(h0[0], h0[1], h0[2], h0[3]);
    xb[32 + j] = make_float4(h1[0], h1[1], h1[2], h1[3]);
    __syncwarp();
    float m0[4] = {0.f, 0.f, 0.f, 0.f}, m1[4] = {0.f, 0.f, 0.f, 0.f};
#pragma unroll
    for (int k = 0; k < 64; k++) {
        float4 xk = xb[k];
        float2 wk = Wt[k * 32 + j];
        m0[0] = fmaf(xk.x, wk.x, m0[0]); m1[0] = fmaf(xk.x, wk.y, m1[0]);
        m0[1] = fmaf(xk.y, wk.x, m0[1]); m1[1] = fmaf(xk.y, wk.y, m1[1]);
        m0[2] = fmaf(xk.z, wk.x, m0[2]); m1[2] = fmaf(xk.z, wk.y, m1[2]);
        m0[3] = fmaf(xk.w, wk.x, m0[3]); m1[3] = fmaf(xk.w, wk.y, m1[3]);
    }
    float s2[4];
#pragma unroll
    for (int q = 0; q < 4; q++) s2[q] = m0[q] * m0[q] + m1[q] * m1[q];
    wsum4(s2);
#pragma unroll
    for (int q = 0; q < 4; q++) {
        float xn = fmaxf(n[q], MINN);
        float ml = sqrtf(s2[q]);
        float mx = fmaxf(ml, MINN);
        float r = fast_tanh(__fdividef(mx, xn) * fast_atanh(xn));
        float sc = __fdividef(r, mx);
        h0[q] = m0[q] * sc; h1[q] = m1[q] * sc;
        n[q] = r * __fdividef(ml, mx);
        proj1(h0[q], h1[q], n[q]);
    }
    float e0 = eb[j], e1 = eb[32 + j];
    float xy[4];
#pragma unroll
    for (int q = 0; q < 4; q++) xy[q] = h0[q] * e0 + h1[q] * e1;
    wsum4(xy);
#pragma unroll
    for (int q = 0; q < 4; q++) {
        float x2 = n[q] * n[q];
        float c1 = 1.f + 2.f * xy[q] + ebn2, c2 = 1.f - x2;
        float den = fmaxf(1.f + 2.f * xy[q] + x2 * ebn2, MINN);
        float inv = __fdividef(1.f, den);
        h0[q] = (c1 * h0[q] + c2 * e0) * inv;
        h1[q] = (c1 * h1[q] + c2 * e1) * inv;
    }
    float q2[4];
#pragma unroll
    for (int q = 0; q < 4; q++) q2[q] = h0[q] * h0[q] + h1[q] * h1[q];
    wsum4(q2);
#pragma unroll
    for (int q = 0; q < 4; q++) { n[q] = sqrtf(q2[q]); proj1(h0[q], h1[q], n[q]); }
    if (act) act4(h0, h1, n);
}

// Final 64->32 layer (no act), Wt[k*32+j] = W6[j*64+k]. Output in o[4].
__device__ __forceinline__ void layer_out_4(
    float h0[4], float h1[4], float n[4], float o[4],
    const float* __restrict__ Wt, const float* __restrict__ eb, float ebn2,
    float4* xb, int j) {
    __syncwarp();
    xb[j]      = make_float4(h0[0], h0[1], h0[2], h0[3]);
    xb[32 + j] = make_float4(h1[0], h1[1], h1[2], h1[3]);
    __syncwarp();
    float m[4] = {0.f, 0.f, 0.f, 0.f};
#pragma unroll
    for (int k = 0; k < 64; k++) {
        float4 xk = xb[k];
        float w = Wt[k * 32 + j];
        m[0] = fmaf(xk.x, w, m[0]); m[1] = fmaf(xk.y, w, m[1]);
        m[2] = fmaf(xk.z, w, m[2]); m[3] = fmaf(xk.w, w, m[3]);
    }
    float s2[4];
#pragma unroll
    for (int q = 0; q < 4; q++) s2[q] = m[q] * m[q];
    wsum4(s2);
    float nn[4];
#pragma unroll
    for (int q = 0; q < 4; q++) {
        float xn = fmaxf(n[q], MINN);
        float ml = sqrtf(s2[q]);
        float mx = fmaxf(ml, MINN);
        float r = fast_tanh(__fdividef(mx, xn) * fast_atanh(xn));
        o[q] = m[q] * __fdividef(r, mx);
        nn[q] = r * __fdividef(ml, mx);
        float d = 0.f;
        proj1(o[q], d, nn[q]);
    }
    float e0 = eb[j];
    float xy[4];
#pragma unroll
    for (int q = 0; q < 4; q++) xy[q] = o[q] * e0;
    wsum4(xy);
#pragma unroll
    for (int q = 0; q < 4; q++) {
        float x2 = nn[q] * nn[q];
        float c1 = 1.f + 2.f * xy[q] + ebn2, c2 = 1.f - x2;
        float den = fmaxf(1.f + 2.f * xy[q] + x2 * ebn2, MINN);
        o[q] = (c1 * o[q] + c2 * e0) * __fdividef(1.f, den);
    }
    float q2[4];
#pragma unroll
    for (int q = 0; q < 4; q++) q2[q] = o[q] * o[q];
    wsum4(q2);
#pragma unroll
    for (int q = 0; q < 4; q++) {
        float nf = sqrtf(q2[q]), d = 0.f;
        proj1(o[q], d, nf);
    }
}

// bias -> eb = expmap0(b), |eb|^2 (dim 64), one warp
__device__ __forceinline__ void compute_eb64(const float* __restrict__ b,
                                             float* eb, float* ebn2, int j) {
    float v0 = b[j], v1 = b[32 + j];
    float s2[4] = {v0 * v0 + v1 * v1, 0.f, 0.f, 0.f};
    wsum4(s2);
    float bn = sqrtf(s2[0]), bc = fmaxf(bn, MINN);
    float se = __fdividef(fast_tanh(bc), bc);
    eb[j] = v0 * se;
    eb[32 + j] = v1 * se;
    if (j == 0) *ebn2 = (se * bn) * (se * bn);
}

// CSR gather-aggregate for one node: sums t[src] over neighbors.
// Lane j accumulates components j and j+32. Unroll x4 -> 8 LDGs in flight.
__device__ __forceinline__ void csr_agg(const float* __restrict__ tsrc, int node,
                                        int j, float& o0, float& o1, int& deg) {
    int s = g_off[node], e = g_off[node + 1];
    deg = e - s;
    float a0 = 0.f, a1 = 0.f, b0 = 0.f, b1 = 0.f;
    for (int base = s; base < e; base += 32) {
        int nh = min(32, e - base);
        int idx = (j < nh) ? g_col[base + j] : 0;
        int t = 0;
        for (; t + 4 <= nh; t += 4) {
            int s0 = __shfl_sync(0xffffffffu, idx, t);
            int s1 = __shfl_sync(0xffffffffu, idx, t + 1);
            int s2 = __shfl_sync(0xffffffffu, idx, t + 2);
            int s3 = __shfl_sync(0xffffffffu, idx, t + 3);
            float v00 = __ldg(tsrc + (size_t)s0 * 64 + j);
            float v01 = __ldg(tsrc + (size_t)s0 * 64 + 32 + j);
            float v10 = __ldg(tsrc + (size_t)s1 * 64 + j);
            float v11 = __ldg(tsrc + (size_t)s1 * 64 + 32 + j);
            float v20 = __ldg(tsrc + (size_t)s2 * 64 + j);
            float v21 = __ldg(tsrc + (size_t)s2 * 64 + 32 + j);
            float v30 = __ldg(tsrc + (size_t)s3 * 64 + j);
            float v31 = __ldg(tsrc + (size_t)s3 * 64 + 32 + j);
            a0 += v00; a1 += v01; b0 += v10; b1 += v11;
            a0 += v20; a1 += v21; b0 += v30; b1 += v31;
        }
        for (; t < nh; t++) {
            int sx = __shfl_sync(0xffffffffu, idx, t);
            a0 += __ldg(tsrc + (size_t)sx * 64 + j);
            a1 += __ldg(tsrc + (size_t)sx * 64 + 32 + j);
        }
    }
    o0 = a0 + b0; o1 = a1 + b1;
}

// mean + expmap0 + proj for 4 nodes via CSR gather
__device__ __forceinline__ void load_agg4_csr(const float* __restrict__ tsrc,
                                              int iBase, int j,
                                              float h0[4], float h1[4], float n[4]) {
    float n2[4];
#pragma unroll
    for (int q = 0; q < 4; q++) {
        int deg;
        float a0, a1;
        csr_agg(tsrc, iBase + q, j, a0, a1, deg);
        float inv = __fdividef(1.f, fmaxf((float)deg, 1.f));
        h0[q] = a0 * inv;
        h1[q] = a1 * inv;
        n2[q] = h0[q] * h0[q] + h1[q] * h1[q];
    }
    wsum4(n2);
#pragma unroll
    for (int q = 0; q < 4; q++) {
        float un = sqrtf(n2[q]);
        float uc = fmaxf(un, MINN);
        float se = __fdividef(fast_tanh(uc), uc);
        h0[q] *= se; h1[q] *= se; n[q] = se * un;
        proj1(h0[q], h1[q], n[q]);
    }
}

// ---------------- kernel A: poincare + layers 1..4 + logmap -> g_t ----------
__global__ void __launch_bounds__(256) nodeA_kernel(
    const float* __restrict__ x,
    const float* __restrict__ W1, const float* __restrict__ b1,
    const float* __restrict__ W2, const float* __restrict__ b2,
    const float* __restrict__ W3, const float* __restrict__ b3,
    const float* __restrict__ W4, const float* __restrict__ b4) {
    extern __shared__ unsigned char smem_raw[];
    float2* Ws = (float2*)smem_raw;            // 4 * 2048 float2 = 64KB
    float4* xbuf = (float4*)(Ws + 4 * 2048);   // 8 warps * 64 float4
    float* eb = (float*)(xbuf + 8 * 64);       // 4 * 64
    float* ebn2 = eb + 4 * 64;                 // 4
    int tid = threadIdx.x;

    const float* Wp[4] = {W1, W2, W3, W4};
#pragma unroll
    for (int L = 0; L < 4; L++) {
        const float* W = Wp[L];
        int K = (L == 0) ? 63 : 64;
        for (int i = tid; i < 2048; i += 256) {
            int k = i >> 5, j = i & 31;
            float2 v = make_float2(0.f, 0.f);
            if (k < K) { v.x = W[j * K + k]; v.y = W[(j + 32) * K + k]; }
            Ws[L * 2048 + k * 32 + j] = v;
        }
    }
    int w = tid >> 5, j = tid & 31;
    if (w < 4) {
        const float* bp[4] = {b1, b2, b3, b4};
        compute_eb64(bp[w], eb + w * 64, ebn2 + w, j);
    }
    __syncthreads();

    int iBase = blockIdx.x * 32 + w * 4;
    float4* xb = xbuf + w * 64;
    float h0[4], h1[4], n[4], n2[4];
#pragma unroll
    for (int q = 0; q < 4; q++) {
        const float* xp = x + (size_t)(iBase + q) * 64;
        float inv = __fdividef(1.f, xp[0] + 1.f);
        h0[q] = xp[1 + j] * inv;
        h1[q] = (j < 31) ? xp[33 + j] * inv : 0.f;
        n2[q] = h0[q] * h0[q] + h1[q] * h1[q];
    }
    wsum4(n2);
#pragma unroll
    for (int q = 0; q < 4; q++) { n[q] = sqrtf(n2[q]); proj1(h0[q], h1[q], n[q]); }

    layer64_4(h0, h1, n, Ws,        eb,       ebn2[0], xb, j, true);
    layer64_4(h0, h1, n, Ws + 2048, eb + 64,  ebn2[1], xb, j, true);
    layer64_4(h0, h1, n, Ws + 4096, eb + 128, ebn2[2], xb, j, true);
    layer64_4(h0, h1, n, Ws + 6144, eb + 192, ebn2[3], xb, j, false);

#pragma unroll
    for (int q = 0; q < 4; q++) {
        float ln = fmaxf(n[q], MINN);
        float s = __fdividef(fast_atanh(ln), ln);
        g_t[(size_t)(iBase + q) * 64 + j] = h0[q] * s;
        g_t[(size_t)(iBase + q) * 64 + 32 + j] = h1[q] * s;
    }
}

// ---------------- kernel B: csr-agg(g_t) + act + layer5 + logmap -> g_t2 ----
__global__ void __launch_bounds__(256) nodeB_kernel(
    const float* __restrict__ W5, const float* __restrict__ b5) {
    extern __shared__ unsigned char smem_raw[];
    float2* Ws = (float2*)smem_raw;            // 2048 float2
    float4* xbuf = (float4*)(Ws + 2048);       // 8 * 64 float4
    float* eb = (float*)(xbuf + 8 * 64);       // 64
    float* ebn2 = eb + 64;
    int tid = threadIdx.x;
    for (int i = tid; i < 2048; i += 256) {
        int k = i >> 5, j = i & 31;
        Ws[k * 32 + j] = make_float2(W5[j * 64 + k], W5[(j + 32) * 64 + k]);
    }
    int w = tid >> 5, j = tid & 31;
    if (w == 0) compute_eb64(b5, eb, ebn2, j);
    __syncthreads();

    int iBase = blockIdx.x * 32 + w * 4;
    float4* xb = xbuf + w * 64;
    float h0[4], h1[4], n[4];
    load_agg4_csr(g_t, iBase, j, h0, h1, n);
    act4(h0, h1, n);                                     // layer-4 activation
    layer64_4(h0, h1, n, Ws, eb, ebn2[0], xb, j, false); // layer-5 matvec+bias
#pragma unroll
    for (int q = 0; q < 4; q++) {
        float ln = fmaxf(n[q], MINN);
        float s = __fdividef(fast_atanh(ln), ln);
        g_t2[(size_t)(iBase + q) * 64 + j] = h0[q] * s;
        g_t2[(size_t)(iBase + q) * 64 + 32 + j] = h1[q] * s;
    }
}

// ---------------- kernel C: csr-agg(g_t2) + act + layer6 -> out -------------
__global__ void __launch_bounds__(256) nodeC_kernel(
    const float* __restrict__ W6, const float* __restrict__ b6,
    float* __restrict__ out) {
    extern __shared__ unsigned char smem_raw[];
    float* Ws = (float*)smem_raw;              // 64*32 floats
    float4* xbuf = (float4*)(Ws + 2048);       // 8 * 64 float4
    float* eb = (float*)(xbuf + 8 * 64);       // 32
    float* ebn2 = eb + 32;
    int tid = threadIdx.x;
    for (int i = tid; i < 2048; i += 256) {
        int k = i >> 5, j = i & 31;
        Ws[k * 32 + j] = W6[j * 64 + k];
    }
    int w = tid >> 5, j = tid & 31;
    if (w == 0) {
        float v0 = b6[j];
        float s2[4] = {v0 * v0, 0.f, 0.f, 0.f};
        wsum4(s2);
        float bn = sqrtf(s2[0]), bc = fmaxf(bn, MINN);
        float se = __fdividef(fast_tanh(bc), bc);
        eb[j] = v0 * se;
        if (j == 0) *ebn2 = (se * bn) * (se * bn);
    }
    __syncthreads();

    int iBase = blockIdx.x * 32 + w * 4;
    float4* xb = xbuf + w * 64;
    float h0[4], h1[4], n[4], o[4];
    load_agg4_csr(g_t2, iBase, j, h0, h1, n);
    act4(h0, h1, n);                                  // layer-5 activation
    layer_out_4(h0, h1, n, o, Ws, eb, ebn2[0], xb, j);
#pragma unroll
    for (int q = 0; q < 4; q++)
        out[(size_t)(iBase + q) * 32 + j] = o[q];
}

// ---------------- CSR build kernels ----------------
__global__ void detect_kernel(const int* __restrict__ e32) {
    __shared__ int nz;
    if (threadIdx.x == 0) nz = 0;
    __syncthreads();
    for (int i = threadIdx.x; i < 1024; i += 256)
        if (e32[2 * i + 1] != 0) atomicAdd(&nz, 1);
    __syncthreads();
    if (threadIdx.x == 0) g_idx64 = (nz == 0) ? 1 : 0;
}

__global__ void __launch_bounds__(256) convert_kernel(const void* __restrict__ edges) {
    int i = blockIdx.x * 256 + threadIdx.x;
    if (i < NN) g_cnt[i] = 0;
    if (i >= EE) return;
    int s, d;
    if (g_idx64) {
        const long long* p = (const long long*)edges;
        s = (int)__ldg(p + i);
        d = (int)__ldg(p + EE + i);
    } else {
        const int* p = (const int*)edges;
        s = __ldg(p + i);
        d = __ldg(p + EE + i);
    }
    g_src[i] = s;
    g_dst[i] = d;
}

__global__ void __launch_bounds__(256) hist_kernel() {
    int i = blockIdx.x * 256 + threadIdx.x;
    if (i < EE) atomicAdd(&g_cnt[g_dst[i]], 1);
}

__global__ void __launch_bounds__(1024) scan_part_kernel() {
    __shared__ int sm[1024];
    int gi = blockIdx.x * 1024 + threadIdx.x;
    int v = (gi < NN) ? g_cnt[gi] : 0;
    sm[threadIdx.x] = v;
    __syncthreads();
#pragma unroll
    for (int o = 1; o < 1024; o <<= 1) {
        int t = (threadIdx.x >= o) ? sm[threadIdx.x - o] : 0;
        __syncthreads();
        sm[threadIdx.x] += t;
        __syncthreads();
    }
    int incl = sm[threadIdx.x];
    if (gi < NN) g_off[gi] = incl - v;  // exclusive within block
    if (threadIdx.x == 1023) g_bsum[blockIdx.x] = incl;
}

__global__ void scan_top_kernel() {
    if (threadIdx.x == 0) {
        int acc = 0;
        for (int b = 0; b < SCAN_BLOCKS; b++) {
            int t = g_bsum[b];
            g_bsum[b] = acc;
            acc += t;
        }
    }
}

__global__ void __launch_bounds__(1024) scan_add_kernel() {
    int gi = blockIdx.x * 1024 + threadIdx.x;
    if (gi < NN) {
        int o = g_off[gi] + g_bsum[blockIdx.x];
        g_off[gi] = o;
        g_cursor[gi] = o;
    }
    if (gi == 0) g_off[NN] = EE;
}

__global__ void __launch_bounds__(256) fill_kernel() {
    int i = blockIdx.x * 256 + threadIdx.x;
    if (i >= EE) return;
    int d = g_dst[i];
    int pos = atomicAdd(&g_cursor[d], 1);
    g_col[pos] = g_src[i];
}

// ---------------- launch ----------------
extern "C" void kernel_launch(void* const* d_in, const int* in_sizes, int n_in,
                              void* d_out, int out_size) {
    const float* x = (const float*)d_in[0];
    const float* W1 = (const float*)d_in[1];
    const float* b1 = (const float*)d_in[2];
    const float* W2 = (const float*)d_in[3];
    const float* b2 = (const float*)d_in[4];
    const float* W3 = (const float*)d_in[5];
    const float* b3 = (const float*)d_in[6];
    const float* W4 = (const float*)d_in[7];
    const float* b4 = (const float*)d_in[8];
    const float* W5 = (const float*)d_in[9];
    const float* b5 = (const float*)d_in[10];
    const float* W6 = (const float*)d_in[11];
    const float* b6 = (const float*)d_in[12];
    const void* edges = d_in[13];
    float* out = (float*)d_out;

    const int SMEM_A = 4 * 2048 * 8 + 8 * 64 * 16 + 4 * 64 * 4 + 16;  // 74768
    const int SMEM_B = 2048 * 8 + 8 * 64 * 16 + 64 * 4 + 16;
    const int SMEM_C = 2048 * 4 + 8 * 64 * 16 + 32 * 4 + 16;

    cudaFuncSetAttribute(nodeA_kernel, cudaFuncAttributeMaxDynamicSharedMemorySize, SMEM_A);

    const int NODE_BLOCKS = NN / 32;          // 3125
    const int EDGE_BLOCKS = (EE + 255) / 256; // 6250

    detect_kernel<<<1, 256>>>((const int*)edges);
    convert_kernel<<<EDGE_BLOCKS, 256>>>(edges);
    hist_kernel<<<EDGE_BLOCKS, 256>>>();
    scan_part_kernel<<<SCAN_BLOCKS, 1024>>>();
    scan_top_kernel<<<1, 32>>>();
    scan_add_kernel<<<SCAN_BLOCKS, 1024>>>();
    fill_kernel<<<EDGE_BLOCKS, 256>>>();
    nodeA_kernel<<<NODE_BLOCKS, 256, SMEM_A>>>(x, W1, b1, W2, b2, W3, b3, W4, b4);
    nodeB_kernel<<<NODE_BLOCKS, 256, SMEM_B>>>(W5, b5);
    nodeC_kernel<<<NODE_BLOCKS, 256, SMEM_C>>>(W6, b6, out);
}

// round 4
// speedup vs baseline: 1.7481x; 1.0535x over previous
#include <cuda_runtime.h>
#include <cstdint>

#define NN 100000
#define EE 1600000
#define MINN 1e-15f
#define MAXN ((float)(1.0 - 1e-5))
#define SCAN_BLOCKS 98   // 98*1024 >= NN

typedef unsigned long long ull;

// ---------------- scratch (device globals; no allocs allowed) ----------------
__device__ __align__(16) float g_t[(size_t)NN * 64];
__device__ __align__(16) float g_t2[(size_t)NN * 64];
__device__ int g_col[EE];
__device__ int g_cnt[NN];
__device__ int g_off[NN + 1];
__device__ int g_cursor[NN];
__device__ int g_bsum[SCAN_BLOCKS];
__device__ int g_idx64;

// ---------------- packed f32x2 helpers ----------------
__device__ __forceinline__ ull pack2(float lo, float hi) {
    ull r;
    asm("mov.b64 %0, {%1, %2};" : "=l"(r) : "f"(lo), "f"(hi));
    return r;
}
__device__ __forceinline__ void fma2(ull& d, ull a, ull b) {
    asm("fma.rn.f32x2 %0, %1, %2, %0;" : "+l"(d) : "l"(a), "l"(b));
}
__device__ __forceinline__ float pairsum(ull v) {
    float lo, hi;
    asm("mov.b64 {%0, %1}, %2;" : "=f"(lo), "=f"(hi) : "l"(v));
    return lo + hi;
}

// ---------------- fast math (args nonnegative here) ----------------
__device__ __forceinline__ float fast_tanh(float x) {   // x >= 0
    float e = __expf(-2.f * x);
    return __fdividef(1.f - e, 1.f + e);
}
__device__ __forceinline__ float fast_atanh(float x) {  // 0 <= x < 1
    x = fminf(x, MAXN);
    return 0.5f * __logf(__fdividef(1.f + x, 1.f - x));
}

__device__ __forceinline__ void wsum4(float* v) {
#pragma unroll
    for (int o = 16; o > 0; o >>= 1) {
#pragma unroll
        for (int q = 0; q < 4; q++) v[q] += __shfl_xor_sync(0xffffffffu, v[q], o);
    }
}

// lane-slot select: value of node s (s = j&3), all entries warp-uniform
__device__ __forceinline__ float sel4(const float a[4], int s) {
    float x = (s & 1) ? a[1] : a[0];
    float y = (s & 1) ? a[3] : a[2];
    return (s & 2) ? y : x;
}
// broadcast node-q values from lanes 0..3
__device__ __forceinline__ void bcast4(float v, float o[4]) {
    o[0] = __shfl_sync(0xffffffffu, v, 0);
    o[1] = __shfl_sync(0xffffffffu, v, 1);
    o[2] = __shfl_sync(0xffffffffu, v, 2);
    o[3] = __shfl_sync(0xffffffffu, v, 3);
}

// act: h = proj(expmap0(relu(logmap0(h)))), slot form
__device__ __forceinline__ void act4s(float h0[4], float h1[4], float n[4], int s) {
    float lv = fmaxf(sel4(n, s), MINN);
    float sa = __fdividef(fast_atanh(lv), lv);
    float SA[4];
    bcast4(sa, SA);
    float t2[4];
#pragma unroll
    for (int q = 0; q < 4; q++) {
        h0[q] = fmaxf(h0[q] * SA[q], 0.f);
        h1[q] = fmaxf(h1[q] * SA[q], 0.f);
        t2[q] = h0[q] * h0[q] + h1[q] * h1[q];
    }
    wsum4(t2);
    float tn = sqrtf(sel4(t2, s));
    float tc = fmaxf(tn, MINN);
    float se = __fdividef(fast_tanh(tc), tc);
    float nn = fmaxf(se * tn, MINN);
    if (nn > MAXN) { se *= __fdividef(MAXN, nn); nn = MAXN; }
    float SE[4];
    bcast4(se, SE);
    bcast4(nn, n);
#pragma unroll
    for (int q = 0; q < 4; q++) { h0[q] *= SE[q]; h1[q] *= SE[q]; }
}

// stage 4 nodes' 64-dim vectors into k-paired layout:
// x2f[(k>>1)*8 + q*2 + (k&1)] = h[q][k]
__device__ __forceinline__ void stage_x(float* x2f, const float h0[4],
                                        const float h1[4], int j) {
    __syncwarp();
#pragma unroll
    for (int q = 0; q < 4; q++) {
        x2f[(j >> 1) * 8 + q * 2 + (j & 1)] = h0[q];
        x2f[(16 + (j >> 1)) * 8 + q * 2 + (j & 1)] = h1[q];
    }
    __syncwarp();
}

// One 64->64 hyperbolic layer for 4 nodes held across the warp.
// Wq[t*32+j] = {(W[j][2t],W[j][2t+1]), (W[j+32][2t],W[j+32][2t+1])}
__device__ __forceinline__ void layer64_4(
    float h0[4], float h1[4], float n[4],
    const ulonglong2* __restrict__ Wq, const float* __restrict__ eb, float ebn2,
    float* x2f, int j, bool act) {
    int s = j & 3;
    stage_x(x2f, h0, h1, j);
    const ulonglong2* xq2 = (const ulonglong2*)x2f;
    ull a0[4] = {0, 0, 0, 0}, a1[4] = {0, 0, 0, 0};
#pragma unroll
    for (int t = 0; t < 32; t++) {
        ulonglong2 wv = Wq[t * 32 + j];
        ulonglong2 xA = xq2[t * 2];
        ulonglong2 xB = xq2[t * 2 + 1];
        fma2(a0[0], xA.x, wv.x); fma2(a1[0], xA.x, wv.y);
        fma2(a0[1], xA.y, wv.x); fma2(a1[1], xA.y, wv.y);
        fma2(a0[2], xB.x, wv.x); fma2(a1[2], xB.x, wv.y);
        fma2(a0[3], xB.y, wv.x); fma2(a1[3], xB.y, wv.y);
    }
    float m0[4], m1[4], s2[4];
#pragma unroll
    for (int q = 0; q < 4; q++) {
        m0[q] = pairsum(a0[q]);
        m1[q] = pairsum(a1[q]);
        s2[q] = m0[q] * m0[q] + m1[q] * m1[q];
    }
    wsum4(s2);
    // mobius_matvec scale + proj, slot form
    float nv = fmaxf(sel4(n, s), MINN);
    float ml = sqrtf(sel4(s2, s));
    float mx = fmaxf(ml, MINN);
    float r = fast_tanh(__fdividef(mx, nv) * fast_atanh(nv));
    float sc = __fdividef(r, mx);
    float nn = fmaxf(r * __fdividef(ml, mx), MINN);
    if (nn > MAXN) { sc *= __fdividef(MAXN, nn); nn = MAXN; }
    float SC[4];
    bcast4(sc, SC);
#pragma unroll
    for (int q = 0; q < 4; q++) { h0[q] = m0[q] * SC[q]; h1[q] = m1[q] * SC[q]; }
    // mobius_add(h, expmap0(b))
    float e0 = eb[j], e1 = eb[32 + j];
    float xy[4];
#pragma unroll
    for (int q = 0; q < 4; q++) xy[q] = h0[q] * e0 + h1[q] * e1;
    wsum4(xy);
    float xyv = sel4(xy, s);
    float x2v = nn * nn;
    float c1 = 1.f + 2.f * xyv + ebn2;
    float c2 = 1.f - x2v;
    float inv = __fdividef(1.f, fmaxf(1.f + 2.f * xyv + x2v * ebn2, MINN));
    float C1[4], C2[4];
    bcast4(c1 * inv, C1);
    bcast4(c2 * inv, C2);
    float q2[4];
#pragma unroll
    for (int q = 0; q < 4; q++) {
        h0[q] = C1[q] * h0[q] + C2[q] * e0;
        h1[q] = C1[q] * h1[q] + C2[q] * e1;
        q2[q] = h0[q] * h0[q] + h1[q] * h1[q];
    }
    wsum4(q2);
    float nf = fmaxf(sqrtf(sel4(q2, s)), MINN);
    float ps = 1.f;
    if (nf > MAXN) { ps = __fdividef(MAXN, nf); nf = MAXN; }
    if (act) {
        float sa = ps * __fdividef(fast_atanh(nf), nf);   // proj + logmap0
        float SA[4];
        bcast4(sa, SA);
        float t2[4];
#pragma unroll
        for (int q = 0; q < 4; q++) {
            h0[q] = fmaxf(h0[q] * SA[q], 0.f);
            h1[q] = fmaxf(h1[q] * SA[q], 0.f);
            t2[q] = h0[q] * h0[q] + h1[q] * h1[q];
        }
        wsum4(t2);
        float tn = sqrtf(sel4(t2, s));
        float tc = fmaxf(tn, MINN);
        float se = __fdividef(fast_tanh(tc), tc);
        float nfin = fmaxf(se * tn, MINN);
        if (nfin > MAXN) { se *= __fdividef(MAXN, nfin); nfin = MAXN; }
        float SE[4];
        bcast4(se, SE);
        bcast4(nfin, n);
#pragma unroll
        for (int q = 0; q < 4; q++) { h0[q] *= SE[q]; h1[q] *= SE[q]; }
    } else {
        float PS[4];
        bcast4(ps, PS);
        bcast4(nf, n);
#pragma unroll
        for (int q = 0; q < 4; q++) { h0[q] *= PS[q]; h1[q] *= PS[q]; }
    }
}

// Final 64->32 layer (no act). W6q[t*32+j] = (W6[j][2t], W6[j][2t+1]).
__device__ __forceinline__ void layer_out_4(
    float h0[4], float h1[4], float n[4], float o[4],
    const ull* __restrict__ W6q, const float* __restrict__ eb, float ebn2,
    float* x2f, int j) {
    int s = j & 3;
    stage_x(x2f, h0, h1, j);
    const ulonglong2* xq2 = (const ulonglong2*)x2f;
    ull a[4] = {0, 0, 0, 0};
#pragma unroll
    for (int t = 0; t < 32; t++) {
        ull wv = W6q[t * 32 + j];
        ulonglong2 xA = xq2[t * 2];
        ulonglong2 xB = xq2[t * 2 + 1];
        fma2(a[0], xA.x, wv); fma2(a[1], xA.y, wv);
        fma2(a[2], xB.x, wv); fma2(a[3], xB.y, wv);
    }
    float m[4], s2[4];
#pragma unroll
    for (int q = 0; q < 4; q++) { m[q] = pairsum(a[q]); s2[q] = m[q] * m[q]; }
    wsum4(s2);
    float nv = fmaxf(sel4(n, s), MINN);
    float ml = sqrtf(sel4(s2, s));
    float mx = fmaxf(ml, MINN);
    float r = fast_tanh(__fdividef(mx, nv) * fast_atanh(nv));
    float sc = __fdividef(r, mx);
    float nn = fmaxf(r * __fdividef(ml, mx), MINN);
    if (nn > MAXN) { sc *= __fdividef(MAXN, nn); nn = MAXN; }
    float SC[4];
    bcast4(sc, SC);
#pragma unroll
    for (int q = 0; q < 4; q++) o[q] = m[q] * SC[q];
    float e0 = eb[j];
    float xy[4];
#pragma unroll
    for (int q = 0; q < 4; q++) xy[q] = o[q] * e0;
    wsum4(xy);
    float xyv = sel4(xy, s);
    float x2v = nn * nn;
    float c1 = 1.f + 2.f * xyv + ebn2;
    float c2 = 1.f - x2v;
    float inv = __fdividef(1.f, fmaxf(1.f + 2.f * xyv + x2v * ebn2, MINN));
    float C1[4], C2[4];
    bcast4(c1 * inv, C1);
    bcast4(c2 * inv, C2);
    float q2[4];
#pragma unroll
    for (int q = 0; q < 4; q++) {
        o[q] = C1[q] * o[q] + C2[q] * e0;
        q2[q] = o[q] * o[q];
    }
    wsum4(q2);
    float nf = fmaxf(sqrtf(sel4(q2, s)), MINN);
    float ps = 1.f;
    if (nf > MAXN) ps = __fdividef(MAXN, nf);
    float PS[4];
    bcast4(ps, PS);
#pragma unroll
    for (int q = 0; q < 4; q++) o[q] *= PS[q];
}

// bias -> eb = expmap0(b), |eb|^2 (dim 64), one warp
__device__ __forceinline__ void compute_eb64(const float* __restrict__ b,
                                             float* eb, float* ebn2, int j) {
    float v0 = b[j], v1 = b[32 + j];
    float s2[4] = {v0 * v0 + v1 * v1, 0.f, 0.f, 0.f};
    wsum4(s2);
    float bn = sqrtf(s2[0]), bc = fmaxf(bn, MINN);
    float se = __fdividef(fast_tanh(bc), bc);
    eb[j] = v0 * se;
    eb[32 + j] = v1 * se;
    if (j == 0) *ebn2 = (se * bn) * (se * bn);
}

// CSR gather-aggregate for one node.
__device__ __forceinline__ void csr_agg(const float* __restrict__ tsrc, int node,
                                        int j, float& o0, float& o1, int& deg) {
    int s = g_off[node], e = g_off[node + 1];
    deg = e - s;
    float a0 = 0.f, a1 = 0.f, b0 = 0.f, b1 = 0.f;
    for (int base = s; base < e; base += 32) {
        int nh = min(32, e - base);
        int idx = (j < nh) ? g_col[base + j] : 0;
        int t = 0;
        for (; t + 4 <= nh; t += 4) {
            int s0 = __shfl_sync(0xffffffffu, idx, t);
            int s1 = __shfl_sync(0xffffffffu, idx, t + 1);
            int s2 = __shfl_sync(0xffffffffu, idx, t + 2);
            int s3 = __shfl_sync(0xffffffffu, idx, t + 3);
            float v00 = __ldg(tsrc + (size_t)s0 * 64 + j);
            float v01 = __ldg(tsrc + (size_t)s0 * 64 + 32 + j);
            float v10 = __ldg(tsrc + (size_t)s1 * 64 + j);
            float v11 = __ldg(tsrc + (size_t)s1 * 64 + 32 + j);
            float v20 = __ldg(tsrc + (size_t)s2 * 64 + j);
            float v21 = __ldg(tsrc + (size_t)s2 * 64 + 32 + j);
            float v30 = __ldg(tsrc + (size_t)s3 * 64 + j);
            float v31 = __ldg(tsrc + (size_t)s3 * 64 + 32 + j);
            a0 += v00; a1 += v01; b0 += v10; b1 += v11;
            a0 += v20; a1 += v21; b0 += v30; b1 += v31;
        }
        for (; t < nh; t++) {
            int sx = __shfl_sync(0xffffffffu, idx, t);
            a0 += __ldg(tsrc + (size_t)sx * 64 + j);
            a1 += __ldg(tsrc + (size_t)sx * 64 + 32 + j);
        }
    }
    o0 = a0 + b0; o1 = a1 + b1;
}

// mean + expmap0 + proj for 4 nodes via CSR gather, slot form
__device__ __forceinline__ void load_agg4_csr(const float* __restrict__ tsrc,
                                              int iBase, int j,
                                              float h0[4], float h1[4], float n[4]) {
    int s = j & 3;
    float n2[4];
#pragma unroll
    for (int q = 0; q < 4; q++) {
        int deg;
        float a0, a1;
        csr_agg(tsrc, iBase + q, j, a0, a1, deg);
        float inv = __fdividef(1.f, fmaxf((float)deg, 1.f));
        h0[q] = a0 * inv;
        h1[q] = a1 * inv;
        n2[q] = h0[q] * h0[q] + h1[q] * h1[q];
    }
    wsum4(n2);
    float un = sqrtf(sel4(n2, s));
    float uc = fmaxf(un, MINN);
    float se = __fdividef(fast_tanh(uc), uc);
    float nn = fmaxf(se * un, MINN);
    if (nn > MAXN) { se *= __fdividef(MAXN, nn); nn = MAXN; }
    float SE[4];
    bcast4(se, SE);
    bcast4(nn, n);
#pragma unroll
    for (int q = 0; q < 4; q++) { h0[q] *= SE[q]; h1[q] *= SE[q]; }
}

// load weights of one 64x64 (or 64x63) layer into k-paired smem layout
__device__ __forceinline__ void load_Wq(ulonglong2* Wq, const float* __restrict__ W,
                                        int K, int tid) {
    for (int i = tid; i < 1024; i += 256) {
        int t = i >> 5, jj = i & 31;
        int k0 = 2 * t, k1 = 2 * t + 1;
        float w00 = W[jj * K + k0];
        float w01 = (k1 < K) ? W[jj * K + k1] : 0.f;
        float w10 = W[(jj + 32) * K + k0];
        float w11 = (k1 < K) ? W[(jj + 32) * K + k1] : 0.f;
        ulonglong2 v;
        v.x = pack2(w00, w01);
        v.y = pack2(w10, w11);
        Wq[t * 32 + jj] = v;
    }
}

// ---------------- kernel A: poincare + layers 1..4 + logmap -> g_t ----------
__global__ void __launch_bounds__(256) nodeA_kernel(
    const float* __restrict__ x,
    const float* __restrict__ W1, const float* __restrict__ b1,
    const float* __restrict__ W2, const float* __restrict__ b2,
    const float* __restrict__ W3, const float* __restrict__ b3,
    const float* __restrict__ W4, const float* __restrict__ b4) {
    extern __shared__ unsigned char smem_raw[];
    ulonglong2* Wq = (ulonglong2*)smem_raw;      // 4*1024 entries = 64KB
    float* xall = (float*)(Wq + 4 * 1024);       // 8 warps * 256 floats
    float* eb = xall + 8 * 256;                  // 4*64
    float* ebn2 = eb + 256;                      // 4
    int tid = threadIdx.x;

    load_Wq(Wq,        W1, 63, tid);
    load_Wq(Wq + 1024, W2, 64, tid);
    load_Wq(Wq + 2048, W3, 64, tid);
    load_Wq(Wq + 3072, W4, 64, tid);
    int w = tid >> 5, j = tid & 31;
    if (w < 4) {
        const float* bp[4] = {b1, b2, b3, b4};
        compute_eb64(bp[w], eb + w * 64, ebn2 + w, j);
    }
    __syncthreads();

    int iBase = blockIdx.x * 32 + w * 4;
    float* x2f = xall + w * 256;
    int s = j & 3;
    float h0[4], h1[4], n[4], n2[4];
#pragma unroll
    for (int q = 0; q < 4; q++) {
        const float* xp = x + (size_t)(iBase + q) * 64;
        float inv = __fdividef(1.f, xp[0] + 1.f);
        h0[q] = xp[1 + j] * inv;
        h1[q] = (j < 31) ? xp[33 + j] * inv : 0.f;
        n2[q] = h0[q] * h0[q] + h1[q] * h1[q];
    }
    wsum4(n2);
    {
        float nf = fmaxf(sqrtf(sel4(n2, s)), MINN);
        float ps = 1.f;
        if (nf > MAXN) { ps = __fdividef(MAXN, nf); nf = MAXN; }
        float PS[4];
        bcast4(ps, PS);
        bcast4(nf, n);
#pragma unroll
        for (int q = 0; q < 4; q++) { h0[q] *= PS[q]; h1[q] *= PS[q]; }
    }

    layer64_4(h0, h1, n, Wq,        eb,       ebn2[0], x2f, j, true);
    layer64_4(h0, h1, n, Wq + 1024, eb + 64,  ebn2[1], x2f, j, true);
    layer64_4(h0, h1, n, Wq + 2048, eb + 128, ebn2[2], x2f, j, true);
    layer64_4(h0, h1, n, Wq + 3072, eb + 192, ebn2[3], x2f, j, false);

    // t = logmap0(h)
    float lv = fmaxf(sel4(n, s), MINN);
    float sl = __fdividef(fast_atanh(lv), lv);
    float SL[4];
    bcast4(sl, SL);
#pragma unroll
    for (int q = 0; q < 4; q++) {
        g_t[(size_t)(iBase + q) * 64 + j] = h0[q] * SL[q];
        g_t[(size_t)(iBase + q) * 64 + 32 + j] = h1[q] * SL[q];
    }
}

// ---------------- kernel B: csr-agg(g_t) + act + layer5 + logmap -> g_t2 ----
__global__ void __launch_bounds__(256) nodeB_kernel(
    const float* __restrict__ W5, const float* __restrict__ b5) {
    extern __shared__ unsigned char smem_raw[];
    ulonglong2* Wq = (ulonglong2*)smem_raw;      // 1024 entries = 16KB
    float* xall = (float*)(Wq + 1024);           // 8 * 256 floats
    float* eb = xall + 8 * 256;                  // 64
    float* ebn2 = eb + 64;
    int tid = threadIdx.x;
    load_Wq(Wq, W5, 64, tid);
    int w = tid >> 5, j = tid & 31;
    if (w == 0) compute_eb64(b5, eb, ebn2, j);
    __syncthreads();

    int iBase = blockIdx.x * 32 + w * 4;
    float* x2f = xall + w * 256;
    int s = j & 3;
    float h0[4], h1[4], n[4];
    load_agg4_csr(g_t, iBase, j, h0, h1, n);
    act4s(h0, h1, n, s);                                  // layer-4 activation
    layer64_4(h0, h1, n, Wq, eb, ebn2[0], x2f, j, false); // layer-5 matvec+bias
    float lv = fmaxf(sel4(n, s), MINN);
    float sl = __fdividef(fast_atanh(lv), lv);
    float SL[4];
    bcast4(sl, SL);
#pragma unroll
    for (int q = 0; q < 4; q++) {
        g_t2[(size_t)(iBase + q) * 64 + j] = h0[q] * SL[q];
        g_t2[(size_t)(iBase + q) * 64 + 32 + j] = h1[q] * SL[q];
    }
}

// ---------------- kernel C: csr-agg(g_t2) + act + layer6 -> out -------------
__global__ void __launch_bounds__(256) nodeC_kernel(
    const float* __restrict__ W6, const float* __restrict__ b6,
    float* __restrict__ out) {
    extern __shared__ unsigned char smem_raw[];
    ull* W6q = (ull*)smem_raw;                   // 1024 entries = 8KB
    float* xall = (float*)(W6q + 1024);          // 8 * 256 floats
    float* eb = xall + 8 * 256;                  // 32
    float* ebn2 = eb + 32;
    int tid = threadIdx.x;
    for (int i = tid; i < 1024; i += 256) {
        int t = i >> 5, jj = i & 31;
        W6q[t * 32 + jj] = pack2(W6[jj * 64 + 2 * t], W6[jj * 64 + 2 * t + 1]);
    }
    int w = tid >> 5, j = tid & 31;
    if (w == 0) {
        float v0 = b6[j];
        float s2[4] = {v0 * v0, 0.f, 0.f, 0.f};
        wsum4(s2);
        float bn = sqrtf(s2[0]), bc = fmaxf(bn, MINN);
        float se = __fdividef(fast_tanh(bc), bc);
        eb[j] = v0 * se;
        if (j == 0) *ebn2 = (se * bn) * (se * bn);
    }
    __syncthreads();

    int iBase = blockIdx.x * 32 + w * 4;
    float* x2f = xall + w * 256;
    int s = j & 3;
    float h0[4], h1[4], n[4], o[4];
    load_agg4_csr(g_t2, iBase, j, h0, h1, n);
    act4s(h0, h1, n, s);                               // layer-5 activation
    layer_out_4(h0, h1, n, o, W6q, eb, ebn2[0], x2f, j);
#pragma unroll
    for (int q = 0; q < 4; q++)
        out[(size_t)(iBase + q) * 32 + j] = o[q];
}

// ---------------- CSR build kernels ----------------
__global__ void detect_kernel(const int* __restrict__ e32) {
    __shared__ int nz;
    if (threadIdx.x == 0) nz = 0;
    __syncthreads();
    for (int i = threadIdx.x; i < 1024; i += 256)
        if (e32[2 * i + 1] != 0) atomicAdd(&nz, 1);
    __syncthreads();
    if (threadIdx.x == 0) g_idx64 = (nz == 0) ? 1 : 0;
}

__global__ void __launch_bounds__(1024) zero_cnt_kernel() {
    int i = blockIdx.x * 1024 + threadIdx.x;
    if (i < NN) g_cnt[i] = 0;
}

__global__ void __launch_bounds__(256) hist_kernel(const void* __restrict__ edges) {
    int i = blockIdx.x * 256 + threadIdx.x;
    if (i >= EE) return;
    int d = g_idx64 ? (int)__ldg((const long long*)edges + EE + i)
                    : __ldg((const int*)edges + EE + i);
    atomicAdd(&g_cnt[d], 1);
}

__global__ void __launch_bounds__(1024) scan_part_kernel() {
    __shared__ int sm[1024];
    int gi = blockIdx.x * 1024 + threadIdx.x;
    int v = (gi < NN) ? g_cnt[gi] : 0;
    sm[threadIdx.x] = v;
    __syncthreads();
#pragma unroll
    for (int o = 1; o < 1024; o <<= 1) {
        int t = (threadIdx.x >= o) ? sm[threadIdx.x - o] : 0;
        __syncthreads();
        sm[threadIdx.x] += t;
        __syncthreads();
    }
    int incl = sm[threadIdx.x];
    if (gi < NN) g_off[gi] = incl - v;  // exclusive within block
    if (threadIdx.x == 1023) g_bsum[blockIdx.x] = incl;
}

__global__ void scan_top_kernel() {
    if (threadIdx.x == 0) {
        int acc = 0;
        for (int b = 0; b < SCAN_BLOCKS; b++) {
            int t = g_bsum[b];
            g_bsum[b] = acc;
            acc += t;
        }
    }
}

__global__ void __launch_bounds__(1024) scan_add_kernel() {
    int gi = blockIdx.x * 1024 + threadIdx.x;
    if (gi < NN) {
        int o = g_off[gi] + g_bsum[blockIdx.x];
        g_off[gi] = o;
        g_cursor[gi] = o;
    }
    if (gi == 0) g_off[NN] = EE;
}

__global__ void __launch_bounds__(256) fill_kernel(const void* __restrict__ edges) {
    int i = blockIdx.x * 256 + threadIdx.x;
    if (i >= EE) return;
    int sV, dV;
    if (g_idx64) {
        sV = (int)__ldg((const long long*)edges + i);
        dV = (int)__ldg((const long long*)edges + EE + i);
    } else {
        sV = __ldg((const int*)edges + i);
        dV = __ldg((const int*)edges + EE + i);
    }
    int pos = atomicAdd(&g_cursor[dV], 1);
    g_col[pos] = sV;
}

// ---------------- launch ----------------
extern "C" void kernel_launch(void* const* d_in, const int* in_sizes, int n_in,
                              void* d_out, int out_size) {
    const float* x = (const float*)d_in[0];
    const float* W1 = (const float*)d_in[1];
    const float* b1 = (const float*)d_in[2];
    const float* W2 = (const float*)d_in[3];
    const float* b2 = (const float*)d_in[4];
    const float* W3 = (const float*)d_in[5];
    const float* b3 = (const float*)d_in[6];
    const float* W4 = (const float*)d_in[7];
    const float* b4 = (const float*)d_in[8];
    const float* W5 = (const float*)d_in[9];
    const float* b5 = (const float*)d_in[10];
    const float* W6 = (const float*)d_in[11];
    const float* b6 = (const float*)d_in[12];
    const void* edges = d_in[13];
    float* out = (float*)d_out;

    const int SMEM_A = 4 * 1024 * 16 + 8 * 256 * 4 + 256 * 4 + 16;  // 74768
    const int SMEM_B = 1024 * 16 + 8 * 256 * 4 + 64 * 4 + 16;       // 24848
    const int SMEM_C = 1024 * 8 + 8 * 256 * 4 + 32 * 4 + 16;        // 16528

    cudaFuncSetAttribute(nodeA_kernel, cudaFuncAttributeMaxDynamicSharedMemorySize, SMEM_A);

    const int NODE_BLOCKS = NN / 32;          // 3125
    const int EDGE_BLOCKS = (EE + 255) / 256; // 6250

    detect_kernel<<<1, 256>>>((const int*)edges);
    zero_cnt_kernel<<<SCAN_BLOCKS, 1024>>>();
    hist_kernel<<<EDGE_BLOCKS, 256>>>(edges);
    scan_part_kernel<<<SCAN_BLOCKS, 1024>>>();
    scan_top_kernel<<<1, 32>>>();
    scan_add_kernel<<<SCAN_BLOCKS, 1024>>>();
    fill_kernel<<<EDGE_BLOCKS, 256>>>(edges);
    nodeA_kernel<<<NODE_BLOCKS, 256, SMEM_A>>>(x, W1, b1, W2, b2, W3, b3, W4, b4);
    nodeB_kernel<<<NODE_BLOCKS, 256, SMEM_B>>>(W5, b5);
    nodeC_kernel<<<NODE_BLOCKS, 256, SMEM_C>>>(W6, b6, out);
}

// round 5
// speedup vs baseline: 1.8461x; 1.0561x over previous
#include <cuda_runtime.h>
#include <cstdint>

#define NN 100000
#define EE 1600000
#define MINN 1e-15f
#define MAXN ((float)(1.0 - 1e-5))
#define SCAN_BLOCKS 98   // 98*1024 >= NN

typedef unsigned long long ull;

// ---------------- scratch (device globals; no allocs allowed) ----------------
__device__ __align__(16) float g_t[(size_t)NN * 64];
__device__ __align__(16) float g_t2[(size_t)NN * 64];
__device__ int g_col[EE];
__device__ int g_cnt[NN];
__device__ int g_off[NN + 1];
__device__ int g_cursor[NN];
__device__ int g_bsum[SCAN_BLOCKS];
__device__ int g_idx64;

// ---------------- packed f32x2 helpers ----------------
__device__ __forceinline__ ull pack2(float lo, float hi) {
    ull r;
    asm("mov.b64 %0, {%1, %2};" : "=l"(r) : "f"(lo), "f"(hi));
    return r;
}
__device__ __forceinline__ void fma2(ull& d, ull a, ull b) {
    asm("fma.rn.f32x2 %0, %1, %2, %0;" : "+l"(d) : "l"(a), "l"(b));
}
__device__ __forceinline__ float pairsum(ull v) {
    float lo, hi;
    asm("mov.b64 {%0, %1}, %2;" : "=f"(lo), "=f"(hi) : "l"(v));
    return lo + hi;
}

// ---------------- fast math (args nonnegative here) ----------------
__device__ __forceinline__ float fast_tanh(float x) {   // x >= 0
    float e = __expf(-2.f * x);
    return __fdividef(1.f - e, 1.f + e);
}
__device__ __forceinline__ float fast_atanh(float x) {  // 0 <= x < 1
    x = fminf(x, MAXN);
    return 0.5f * __logf(__fdividef(1.f + x, 1.f - x));
}

__device__ __forceinline__ void wsum4(float* v) {
#pragma unroll
    for (int o = 16; o > 0; o >>= 1) {
#pragma unroll
        for (int q = 0; q < 4; q++) v[q] += __shfl_xor_sync(0xffffffffu, v[q], o);
    }
}

// lane-slot select: value of node s (s = j&3), all entries warp-uniform
__device__ __forceinline__ float sel4(const float a[4], int s) {
    float x = (s & 1) ? a[1] : a[0];
    float y = (s & 1) ? a[3] : a[2];
    return (s & 2) ? y : x;
}
// broadcast node-q values from lanes 0..3
__device__ __forceinline__ void bcast4(float v, float o[4]) {
    o[0] = __shfl_sync(0xffffffffu, v, 0);
    o[1] = __shfl_sync(0xffffffffu, v, 1);
    o[2] = __shfl_sync(0xffffffffu, v, 2);
    o[3] = __shfl_sync(0xffffffffu, v, 3);
}

// act: h = proj(expmap0(relu(logmap0(h)))), slot form
__device__ __forceinline__ void act4s(float h0[4], float h1[4], float n[4], int s) {
    float lv = fmaxf(sel4(n, s), MINN);
    float sa = __fdividef(fast_atanh(lv), lv);
    float SA[4];
    bcast4(sa, SA);
    float t2[4];
#pragma unroll
    for (int q = 0; q < 4; q++) {
        h0[q] = fmaxf(h0[q] * SA[q], 0.f);
        h1[q] = fmaxf(h1[q] * SA[q], 0.f);
        t2[q] = h0[q] * h0[q] + h1[q] * h1[q];
    }
    wsum4(t2);
    float tn = sqrtf(sel4(t2, s));
    float tc = fmaxf(tn, MINN);
    float se = __fdividef(fast_tanh(tc), tc);
    float nn = fmaxf(se * tn, MINN);
    if (nn > MAXN) { se *= __fdividef(MAXN, nn); nn = MAXN; }
    float SE[4];
    bcast4(se, SE);
    bcast4(nn, n);
#pragma unroll
    for (int q = 0; q < 4; q++) { h0[q] *= SE[q]; h1[q] *= SE[q]; }
}

// stage 4 nodes' vectors: lane j owns comps (2j, 2j+1); xq[j*4+q] = pair j of node q
__device__ __forceinline__ void stage_x(float* x2f, const float h0[4],
                                        const float h1[4], int j) {
    __syncwarp();
    ulonglong2* xq2 = (ulonglong2*)x2f;
    ulonglong2 v0, v1;
    v0.x = pack2(h0[0], h1[0]);
    v0.y = pack2(h0[1], h1[1]);
    v1.x = pack2(h0[2], h1[2]);
    v1.y = pack2(h0[3], h1[3]);
    xq2[j * 2] = v0;
    xq2[j * 2 + 1] = v1;
    __syncwarp();
}

// One 64->64 hyperbolic layer for 4 nodes held across the warp.
// Lane j owns output comps (2j, 2j+1).
// Wq[t*32+j] = {pack2(W[2j][2t],W[2j][2t+1]), pack2(W[2j+1][2t],W[2j+1][2t+1])}
__device__ __forceinline__ void layer64_4(
    float h0[4], float h1[4], float n[4],
    const ulonglong2* __restrict__ Wq, const float* __restrict__ eb, float ebn2,
    float* x2f, int j, bool act) {
    int s = j & 3;
    stage_x(x2f, h0, h1, j);
    const ulonglong2* xq2 = (const ulonglong2*)x2f;
    ull a0[4] = {0, 0, 0, 0}, a1[4] = {0, 0, 0, 0};
#pragma unroll
    for (int t = 0; t < 32; t++) {
        ulonglong2 wv = Wq[t * 32 + j];
        ulonglong2 xA = xq2[t * 2];
        ulonglong2 xB = xq2[t * 2 + 1];
        fma2(a0[0], xA.x, wv.x); fma2(a1[0], xA.x, wv.y);
        fma2(a0[1], xA.y, wv.x); fma2(a1[1], xA.y, wv.y);
        fma2(a0[2], xB.x, wv.x); fma2(a1[2], xB.x, wv.y);
        fma2(a0[3], xB.y, wv.x); fma2(a1[3], xB.y, wv.y);
    }
    float m0[4], m1[4], s2[4];
#pragma unroll
    for (int q = 0; q < 4; q++) {
        m0[q] = pairsum(a0[q]);
        m1[q] = pairsum(a1[q]);
        s2[q] = m0[q] * m0[q] + m1[q] * m1[q];
    }
    wsum4(s2);
    // mobius_matvec scale + proj, slot form
    float nv = fmaxf(sel4(n, s), MINN);
    float ml = sqrtf(sel4(s2, s));
    float mx = fmaxf(ml, MINN);
    float r = fast_tanh(__fdividef(mx, nv) * fast_atanh(nv));
    float sc = __fdividef(r, mx);
    float nn = fmaxf(r * __fdividef(ml, mx), MINN);
    if (nn > MAXN) { sc *= __fdividef(MAXN, nn); nn = MAXN; }
    float SC[4];
    bcast4(sc, SC);
#pragma unroll
    for (int q = 0; q < 4; q++) { h0[q] = m0[q] * SC[q]; h1[q] = m1[q] * SC[q]; }
    // mobius_add(h, expmap0(b))
    float2 ev = *(const float2*)(eb + 2 * j);
    float e0 = ev.x, e1 = ev.y;
    float xy[4];
#pragma unroll
    for (int q = 0; q < 4; q++) xy[q] = h0[q] * e0 + h1[q] * e1;
    wsum4(xy);
    float xyv = sel4(xy, s);
    float x2v = nn * nn;
    float c1 = 1.f + 2.f * xyv + ebn2;
    float c2 = 1.f - x2v;
    float inv = __fdividef(1.f, fmaxf(1.f + 2.f * xyv + x2v * ebn2, MINN));
    float C1[4], C2[4];
    bcast4(c1 * inv, C1);
    bcast4(c2 * inv, C2);
    float q2[4];
#pragma unroll
    for (int q = 0; q < 4; q++) {
        h0[q] = C1[q] * h0[q] + C2[q] * e0;
        h1[q] = C1[q] * h1[q] + C2[q] * e1;
        q2[q] = h0[q] * h0[q] + h1[q] * h1[q];
    }
    wsum4(q2);
    float nf = fmaxf(sqrtf(sel4(q2, s)), MINN);
    float ps = 1.f;
    if (nf > MAXN) { ps = __fdividef(MAXN, nf); nf = MAXN; }
    if (act) {
        float sa = ps * __fdividef(fast_atanh(nf), nf);   // proj + logmap0
        float SA[4];
        bcast4(sa, SA);
        float t2[4];
#pragma unroll
        for (int q = 0; q < 4; q++) {
            h0[q] = fmaxf(h0[q] * SA[q], 0.f);
            h1[q] = fmaxf(h1[q] * SA[q], 0.f);
            t2[q] = h0[q] * h0[q] + h1[q] * h1[q];
        }
        wsum4(t2);
        float tn = sqrtf(sel4(t2, s));
        float tc = fmaxf(tn, MINN);
        float se = __fdividef(fast_tanh(tc), tc);
        float nfin = fmaxf(se * tn, MINN);
        if (nfin > MAXN) { se *= __fdividef(MAXN, nfin); nfin = MAXN; }
        float SE[4];
        bcast4(se, SE);
        bcast4(nfin, n);
#pragma unroll
        for (int q = 0; q < 4; q++) { h0[q] *= SE[q]; h1[q] *= SE[q]; }
    } else {
        float PS[4];
        bcast4(ps, PS);
        bcast4(nf, n);
#pragma unroll
        for (int q = 0; q < 4; q++) { h0[q] *= PS[q]; h1[q] *= PS[q]; }
    }
}

// Final 64->32 layer (no act). Lane j owns out comp j.
// W6q[t*32+j] = pack2(W6[j][2t], W6[j][2t+1]).
__device__ __forceinline__ void layer_out_4(
    float h0[4], float h1[4], float n[4], float o[4],
    const ull* __restrict__ W6q, const float* __restrict__ eb, float ebn2,
    float* x2f, int j) {
    int s = j & 3;
    stage_x(x2f, h0, h1, j);
    const ulonglong2* xq2 = (const ulonglong2*)x2f;
    ull a[4] = {0, 0, 0, 0};
#pragma unroll
    for (int t = 0; t < 32; t++) {
        ull wv = W6q[t * 32 + j];
        ulonglong2 xA = xq2[t * 2];
        ulonglong2 xB = xq2[t * 2 + 1];
        fma2(a[0], xA.x, wv); fma2(a[1], xA.y, wv);
        fma2(a[2], xB.x, wv); fma2(a[3], xB.y, wv);
    }
    float m[4], s2[4];
#pragma unroll
    for (int q = 0; q < 4; q++) { m[q] = pairsum(a[q]); s2[q] = m[q] * m[q]; }
    wsum4(s2);
    float nv = fmaxf(sel4(n, s), MINN);
    float ml = sqrtf(sel4(s2, s));
    float mx = fmaxf(ml, MINN);
    float r = fast_tanh(__fdividef(mx, nv) * fast_atanh(nv));
    float sc = __fdividef(r, mx);
    float nn = fmaxf(r * __fdividef(ml, mx), MINN);
    if (nn > MAXN) { sc *= __fdividef(MAXN, nn); nn = MAXN; }
    float SC[4];
    bcast4(sc, SC);
#pragma unroll
    for (int q = 0; q < 4; q++) o[q] = m[q] * SC[q];
    float e0 = eb[j];
    float xy[4];
#pragma unroll
    for (int q = 0; q < 4; q++) xy[q] = o[q] * e0;
    wsum4(xy);
    float xyv = sel4(xy, s);
    float x2v = nn * nn;
    float c1 = 1.f + 2.f * xyv + ebn2;
    float c2 = 1.f - x2v;
    float inv = __fdividef(1.f, fmaxf(1.f + 2.f * xyv + x2v * ebn2, MINN));
    float C1[4], C2[4];
    bcast4(c1 * inv, C1);
    bcast4(c2 * inv, C2);
    float q2[4];
#pragma unroll
    for (int q = 0; q < 4; q++) {
        o[q] = C1[q] * o[q] + C2[q] * e0;
        q2[q] = o[q] * o[q];
    }
    wsum4(q2);
    float nf = fmaxf(sqrtf(sel4(q2, s)), MINN);
    float ps = 1.f;
    if (nf > MAXN) ps = __fdividef(MAXN, nf);
    float PS[4];
    bcast4(ps, PS);
#pragma unroll
    for (int q = 0; q < 4; q++) o[q] *= PS[q];
}

// bias -> eb = expmap0(b) in natural component order, |eb|^2 (dim 64), one warp
__device__ __forceinline__ void compute_eb64(const float* __restrict__ b,
                                             float* eb, float* ebn2, int j) {
    float v0 = b[j], v1 = b[32 + j];
    float s2[4] = {v0 * v0 + v1 * v1, 0.f, 0.f, 0.f};
    wsum4(s2);
    float bn = sqrtf(s2[0]), bc = fmaxf(bn, MINN);
    float se = __fdividef(fast_tanh(bc), bc);
    eb[j] = v0 * se;
    eb[32 + j] = v1 * se;
    if (j == 0) *ebn2 = (se * bn) * (se * bn);
}

// CSR gather-aggregate for one node; lane j sums comps (2j, 2j+1) via float2.
__device__ __forceinline__ void csr_agg(const float* __restrict__ tsrc, int node,
                                        int j, float& o0, float& o1, int& deg) {
    int s = g_off[node], e = g_off[node + 1];
    deg = e - s;
    float a0 = 0.f, a1 = 0.f, b0 = 0.f, b1 = 0.f;
    for (int base = s; base < e; base += 32) {
        int nh = min(32, e - base);
        int idx = (j < nh) ? g_col[base + j] : 0;
        int t = 0;
        for (; t + 8 <= nh; t += 8) {
#pragma unroll
            for (int u = 0; u < 8; u += 2) {
                int sa = __shfl_sync(0xffffffffu, idx, t + u);
                int sb = __shfl_sync(0xffffffffu, idx, t + u + 1);
                float2 va = __ldg((const float2*)(tsrc + (size_t)sa * 64) + j);
                float2 vb = __ldg((const float2*)(tsrc + (size_t)sb * 64) + j);
                a0 += va.x; a1 += va.y;
                b0 += vb.x; b1 += vb.y;
            }
        }
        for (; t < nh; t++) {
            int sx = __shfl_sync(0xffffffffu, idx, t);
            float2 v = __ldg((const float2*)(tsrc + (size_t)sx * 64) + j);
            a0 += v.x; a1 += v.y;
        }
    }
    o0 = a0 + b0; o1 = a1 + b1;
}

// mean + expmap0 + proj for 4 nodes via CSR gather, slot form
__device__ __forceinline__ void load_agg4_csr(const float* __restrict__ tsrc,
                                              int iBase, int j,
                                              float h0[4], float h1[4], float n[4]) {
    int s = j & 3;
    float n2[4];
#pragma unroll
    for (int q = 0; q < 4; q++) {
        int deg;
        float a0, a1;
        csr_agg(tsrc, iBase + q, j, a0, a1, deg);
        float inv = __fdividef(1.f, fmaxf((float)deg, 1.f));
        h0[q] = a0 * inv;
        h1[q] = a1 * inv;
        n2[q] = h0[q] * h0[q] + h1[q] * h1[q];
    }
    wsum4(n2);
    float un = sqrtf(sel4(n2, s));
    float uc = fmaxf(un, MINN);
    float se = __fdividef(fast_tanh(uc), uc);
    float nn = fmaxf(se * un, MINN);
    if (nn > MAXN) { se *= __fdividef(MAXN, nn); nn = MAXN; }
    float SE[4];
    bcast4(se, SE);
    bcast4(nn, n);
#pragma unroll
    for (int q = 0; q < 4; q++) { h0[q] *= SE[q]; h1[q] *= SE[q]; }
}

// load weights: Wq[t*32+j] = {pack2(W[2j][2t],W[2j][2t+1]), pack2(W[2j+1][2t],W[2j+1][2t+1])}
__device__ __forceinline__ void load_Wq(ulonglong2* Wq, const float* __restrict__ W,
                                        int K, int tid) {
    for (int i = tid; i < 1024; i += 256) {
        int t = i >> 5, jj = i & 31;
        int k0 = 2 * t, k1 = 2 * t + 1;
        int r0 = 2 * jj, r1 = 2 * jj + 1;
        float w00 = W[r0 * K + k0];
        float w01 = (k1 < K) ? W[r0 * K + k1] : 0.f;
        float w10 = W[r1 * K + k0];
        float w11 = (k1 < K) ? W[r1 * K + k1] : 0.f;
        ulonglong2 v;
        v.x = pack2(w00, w01);
        v.y = pack2(w10, w11);
        Wq[t * 32 + jj] = v;
    }
}

// ---------------- kernel A: poincare + layers 1..4 + logmap -> g_t ----------
__global__ void __launch_bounds__(256) nodeA_kernel(
    const float* __restrict__ x,
    const float* __restrict__ W1, const float* __restrict__ b1,
    const float* __restrict__ W2, const float* __restrict__ b2,
    const float* __restrict__ W3, const float* __restrict__ b3,
    const float* __restrict__ W4, const float* __restrict__ b4) {
    extern __shared__ unsigned char smem_raw[];
    ulonglong2* Wq = (ulonglong2*)smem_raw;      // 4*1024 entries = 64KB
    float* xall = (float*)(Wq + 4 * 1024);       // 8 warps * 256 floats
    float* eb = xall + 8 * 256;                  // 4*64
    float* ebn2 = eb + 256;                      // 4
    int tid = threadIdx.x;

    load_Wq(Wq,        W1, 63, tid);
    load_Wq(Wq + 1024, W2, 64, tid);
    load_Wq(Wq + 2048, W3, 64, tid);
    load_Wq(Wq + 3072, W4, 64, tid);
    int w = tid >> 5, j = tid & 31;
    if (w < 4) {
        const float* bp[4] = {b1, b2, b3, b4};
        compute_eb64(bp[w], eb + w * 64, ebn2 + w, j);
    }
    __syncthreads();

    int iBase = blockIdx.x * 32 + w * 4;
    float* x2f = xall + w * 256;
    int s = j & 3;
    float h0[4], h1[4], n[4], n2[4];
#pragma unroll
    for (int q = 0; q < 4; q++) {
        const float* xp = x + (size_t)(iBase + q) * 64;
        float inv = __fdividef(1.f, xp[0] + 1.f);
        h0[q] = xp[1 + 2 * j] * inv;
        h1[q] = (j < 31) ? xp[2 + 2 * j] * inv : 0.f;
        n2[q] = h0[q] * h0[q] + h1[q] * h1[q];
    }
    wsum4(n2);
    {
        float nf = fmaxf(sqrtf(sel4(n2, s)), MINN);
        float ps = 1.f;
        if (nf > MAXN) { ps = __fdividef(MAXN, nf); nf = MAXN; }
        float PS[4];
        bcast4(ps, PS);
        bcast4(nf, n);
#pragma unroll
        for (int q = 0; q < 4; q++) { h0[q] *= PS[q]; h1[q] *= PS[q]; }
    }

    layer64_4(h0, h1, n, Wq,        eb,       ebn2[0], x2f, j, true);
    layer64_4(h0, h1, n, Wq + 1024, eb + 64,  ebn2[1], x2f, j, true);
    layer64_4(h0, h1, n, Wq + 2048, eb + 128, ebn2[2], x2f, j, true);
    layer64_4(h0, h1, n, Wq + 3072, eb + 192, ebn2[3], x2f, j, false);

    // t = logmap0(h), paired store
    float lv = fmaxf(sel4(n, s), MINN);
    float sl = __fdividef(fast_atanh(lv), lv);
    float SL[4];
    bcast4(sl, SL);
#pragma unroll
    for (int q = 0; q < 4; q++) {
        float2 v = make_float2(h0[q] * SL[q], h1[q] * SL[q]);
        *((float2*)(g_t + (size_t)(iBase + q) * 64) + j) = v;
    }
}

// ---------------- kernel B: csr-agg(g_t) + act + layer5 + logmap -> g_t2 ----
__global__ void __launch_bounds__(256) nodeB_kernel(
    const float* __restrict__ W5, const float* __restrict__ b5) {
    extern __shared__ unsigned char smem_raw[];
    ulonglong2* Wq = (ulonglong2*)smem_raw;      // 1024 entries = 16KB
    float* xall = (float*)(Wq + 1024);           // 8 * 256 floats
    float* eb = xall + 8 * 256;                  // 64
    float* ebn2 = eb + 64;
    int tid = threadIdx.x;
    load_Wq(Wq, W5, 64, tid);
    int w = tid >> 5, j = tid & 31;
    if (w == 0) compute_eb64(b5, eb, ebn2, j);
    __syncthreads();

    int iBase = blockIdx.x * 32 + w * 4;
    float* x2f = xall + w * 256;
    int s = j & 3;
    float h0[4], h1[4], n[4];
    load_agg4_csr(g_t, iBase, j, h0, h1, n);
    act4s(h0, h1, n, s);                                  // layer-4 activation
    layer64_4(h0, h1, n, Wq, eb, ebn2[0], x2f, j, false); // layer-5 matvec+bias
    float lv = fmaxf(sel4(n, s), MINN);
    float sl = __fdividef(fast_atanh(lv), lv);
    float SL[4];
    bcast4(sl, SL);
#pragma unroll
    for (int q = 0; q < 4; q++) {
        float2 v = make_float2(h0[q] * SL[q], h1[q] * SL[q]);
        *((float2*)(g_t2 + (size_t)(iBase + q) * 64) + j) = v;
    }
}

// ---------------- kernel C: csr-agg(g_t2) + act + layer6 -> out -------------
__global__ void __launch_bounds__(256) nodeC_kernel(
    const float* __restrict__ W6, const float* __restrict__ b6,
    float* __restrict__ out) {
    extern __shared__ unsigned char smem_raw[];
    ull* W6q = (ull*)smem_raw;                   // 1024 entries = 8KB
    float* xall = (float*)(W6q + 1024);          // 8 * 256 floats
    float* eb = xall + 8 * 256;                  // 32
    float* ebn2 = eb + 32;
    int tid = threadIdx.x;
    for (int i = tid; i < 1024; i += 256) {
        int t = i >> 5, jj = i & 31;
        W6q[t * 32 + jj] = pack2(W6[jj * 64 + 2 * t], W6[jj * 64 + 2 * t + 1]);
    }
    int w = tid >> 5, j = tid & 31;
    if (w == 0) {
        float v0 = b6[j];
        float s2[4] = {v0 * v0, 0.f, 0.f, 0.f};
        wsum4(s2);
        float bn = sqrtf(s2[0]), bc = fmaxf(bn, MINN);
        float se = __fdividef(fast_tanh(bc), bc);
        eb[j] = v0 * se;
        if (j == 0) *ebn2 = (se * bn) * (se * bn);
    }
    __syncthreads();

    int iBase = blockIdx.x * 32 + w * 4;
    float* x2f = xall + w * 256;
    int s = j & 3;
    float h0[4], h1[4], n[4], o[4];
    load_agg4_csr(g_t2, iBase, j, h0, h1, n);
    act4s(h0, h1, n, s);                               // layer-5 activation
    layer_out_4(h0, h1, n, o, W6q, eb, ebn2[0], x2f, j);
#pragma unroll
    for (int q = 0; q < 4; q++)
        out[(size_t)(iBase + q) * 32 + j] = o[q];
}

// ---------------- CSR build kernels ----------------
// zero g_cnt everywhere; block 0 also detects int64 vs int32 edge dtype
__global__ void __launch_bounds__(1024) detect_zero_kernel(const int* __restrict__ e32) {
    int i = blockIdx.x * 1024 + threadIdx.x;
    if (i < NN) g_cnt[i] = 0;
    if (blockIdx.x == 0) {
        __shared__ int nz;
        if (threadIdx.x == 0) nz = 0;
        __syncthreads();
        if (e32[2 * threadIdx.x + 1] != 0) atomicAdd(&nz, 1);
        __syncthreads();
        if (threadIdx.x == 0) g_idx64 = (nz == 0) ? 1 : 0;
    }
}

__global__ void __launch_bounds__(256) hist_kernel(const void* __restrict__ edges) {
    int i = blockIdx.x * 256 + threadIdx.x;
    if (i >= EE) return;
    int d = g_idx64 ? (int)__ldg((const long long*)edges + EE + i)
                    : __ldg((const int*)edges + EE + i);
    atomicAdd(&g_cnt[d], 1);
}

__global__ void __launch_bounds__(1024) scan_part_kernel() {
    __shared__ int sm[1024];
    int gi = blockIdx.x * 1024 + threadIdx.x;
    int v = (gi < NN) ? g_cnt[gi] : 0;
    sm[threadIdx.x] = v;
    __syncthreads();
#pragma unroll
    for (int o = 1; o < 1024; o <<= 1) {
        int t = (threadIdx.x >= o) ? sm[threadIdx.x - o] : 0;
        __syncthreads();
        sm[threadIdx.x] += t;
        __syncthreads();
    }
    int incl = sm[threadIdx.x];
    if (gi < NN) g_off[gi] = incl - v;  // exclusive within block
    if (threadIdx.x == 1023) g_bsum[blockIdx.x] = incl;
}

// add block-prefix (each block recomputes the 98-entry prefix itself)
__global__ void __launch_bounds__(1024) scan_add_kernel() {
    __shared__ int base_s;
    if (threadIdx.x < 32) {
        int acc = 0;
        for (int i = (int)threadIdx.x; i < SCAN_BLOCKS; i += 32)
            if (i < (int)blockIdx.x) acc += g_bsum[i];
#pragma unroll
        for (int o = 16; o > 0; o >>= 1) acc += __shfl_xor_sync(0xffffffffu, acc, o);
        if (threadIdx.x == 0) base_s = acc;
    }
    __syncthreads();
    int gi = blockIdx.x * 1024 + threadIdx.x;
    if (gi < NN) {
        int o = g_off[gi] + base_s;
        g_off[gi] = o;
        g_cursor[gi] = o;
    }
    if (gi == 0) g_off[NN] = EE;
}

__global__ void __launch_bounds__(256) fill_kernel(const void* __restrict__ edges) {
    int i = blockIdx.x * 256 + threadIdx.x;
    if (i >= EE) return;
    int sV, dV;
    if (g_idx64) {
        sV = (int)__ldg((const long long*)edges + i);
        dV = (int)__ldg((const long long*)edges + EE + i);
    } else {
        sV = __ldg((const int*)edges + i);
        dV = __ldg((const int*)edges + EE + i);
    }
    int pos = atomicAdd(&g_cursor[dV], 1);
    g_col[pos] = sV;
}

// ---------------- launch ----------------
extern "C" void kernel_launch(void* const* d_in, const int* in_sizes, int n_in,
                              void* d_out, int out_size) {
    const float* x = (const float*)d_in[0];
    const float* W1 = (const float*)d_in[1];
    const float* b1 = (const float*)d_in[2];
    const float* W2 = (const float*)d_in[3];
    const float* b2 = (const float*)d_in[4];
    const float* W3 = (const float*)d_in[5];
    const float* b3 = (const float*)d_in[6];
    const float* W4 = (const float*)d_in[7];
    const float* b4 = (const float*)d_in[8];
    const float* W5 = (const float*)d_in[9];
    const float* b5 = (const float*)d_in[10];
    const float* W6 = (const float*)d_in[11];
    const float* b6 = (const float*)d_in[12];
    const void* edges = d_in[13];
    float* out = (float*)d_out;

    const int SMEM_A = 4 * 1024 * 16 + 8 * 256 * 4 + 256 * 4 + 16;  // 74768
    const int SMEM_B = 1024 * 16 + 8 * 256 * 4 + 64 * 4 + 16;
    const int SMEM_C = 1024 * 8 + 8 * 256 * 4 + 32 * 4 + 16;

    cudaFuncSetAttribute(nodeA_kernel, cudaFuncAttributeMaxDynamicSharedMemorySize, SMEM_A);

    const int NODE_BLOCKS = NN / 32;          // 3125
    const int EDGE_BLOCKS = (EE + 255) / 256; // 6250

    // Try to fork nodeA (no CSR dependency) onto a side stream so it overlaps
    // the CSR build. Falls back to sequential if stream/event creation is
    // rejected (e.g. strict capture mode).
    cudaStream_t s2;
    cudaEvent_t ev0, evA;
    bool forked = (cudaStreamCreateWithFlags(&s2, cudaStreamNonBlocking) == cudaSuccess);
    if (forked) forked = (cudaEventCreateWithFlags(&ev0, cudaEventDisableTiming) == cudaSuccess);
    if (forked) forked = (cudaEventCreateWithFlags(&evA, cudaEventDisableTiming) == cudaSuccess);

    if (forked) {
        cudaEventRecord(ev0, 0);
        cudaStreamWaitEvent(s2, ev0, 0);
        nodeA_kernel<<<NODE_BLOCKS, 256, SMEM_A, s2>>>(x, W1, b1, W2, b2, W3, b3, W4, b4);
        cudaEventRecord(evA, s2);

        detect_zero_kernel<<<SCAN_BLOCKS, 1024>>>((const int*)edges);
        hist_kernel<<<EDGE_BLOCKS, 256>>>(edges);
        scan_part_kernel<<<SCAN_BLOCKS, 1024>>>();
        scan_add_kernel<<<SCAN_BLOCKS, 1024>>>();
        fill_kernel<<<EDGE_BLOCKS, 256>>>(edges);

        cudaStreamWaitEvent(0, evA, 0);   // join: nodeB needs g_t AND the CSR
    } else {
        detect_zero_kernel<<<SCAN_BLOCKS, 1024>>>((const int*)edges);
        hist_kernel<<<EDGE_BLOCKS, 256>>>(edges);
        scan_part_kernel<<<SCAN_BLOCKS, 1024>>>();
        scan_add_kernel<<<SCAN_BLOCKS, 1024>>>();
        fill_kernel<<<EDGE_BLOCKS, 256>>>(edges);
        nodeA_kernel<<<NODE_BLOCKS, 256, SMEM_A>>>(x, W1, b1, W2, b2, W3, b3, W4, b4);
    }

    nodeB_kernel<<<NODE_BLOCKS, 256, SMEM_B>>>(W5, b5);
    nodeC_kernel<<<NODE_BLOCKS, 256, SMEM_C>>>(W6, b6, out);
}

// round 6
// speedup vs baseline: 1.9136x; 1.0366x over previous
#include <cuda_runtime.h>
#include <cstdint>

#define NN 100000
#define EE 1600000
#define MINN 1e-15f
#define MAXN ((float)(1.0 - 1e-5))
#define SCAN_BLOCKS 98   // 98*1024 >= NN; 98 <= #SMs so all blocks co-resident
#define NODE_BLOCKS ((NN + 63) / 64)   // 64 nodes per block (8 per warp)

typedef unsigned long long ull;

// ---------------- scratch (device globals; no allocs allowed) ----------------
__device__ __align__(16) float g_t[(size_t)NN * 64];
__device__ __align__(16) float g_t2[(size_t)NN * 64];
__device__ int g_col[EE];
__device__ int g_cnt[NN];
__device__ int g_off[NN + 1];
__device__ int g_cursor[NN];
__device__ int g_bsum[SCAN_BLOCKS];
__device__ int g_scan_done;
__device__ int g_idx64;

// ---------------- packed f32x2 helpers ----------------
__device__ __forceinline__ ull pack2(float lo, float hi) {
    ull r;
    asm("mov.b64 %0, {%1, %2};" : "=l"(r) : "f"(lo), "f"(hi));
    return r;
}
__device__ __forceinline__ void fma2(ull& d, ull a, ull b) {
    asm("fma.rn.f32x2 %0, %1, %2, %0;" : "+l"(d) : "l"(a), "l"(b));
}
__device__ __forceinline__ float pairsum(ull v) {
    float lo, hi;
    asm("mov.b64 {%0, %1}, %2;" : "=f"(lo), "=f"(hi) : "l"(v));
    return lo + hi;
}

// ---------------- fast math (args nonnegative here) ----------------
__device__ __forceinline__ float fast_tanh(float x) {   // x >= 0
    float e = __expf(-2.f * x);
    return __fdividef(1.f - e, 1.f + e);
}
__device__ __forceinline__ float fast_atanh(float x) {  // 0 <= x < 1
    x = fminf(x, MAXN);
    return 0.5f * __logf(__fdividef(1.f + x, 1.f - x));
}

__device__ __forceinline__ void wsum8(float* v) {
#pragma unroll
    for (int o = 16; o > 0; o >>= 1) {
#pragma unroll
        for (int q = 0; q < 8; q++) v[q] += __shfl_xor_sync(0xffffffffu, v[q], o);
    }
}

// select entry s of a warp-uniform 8-array (s = j&7)
__device__ __forceinline__ float sel8(const float a[8], int s) {
    float x0 = (s & 1) ? a[1] : a[0];
    float x1 = (s & 1) ? a[3] : a[2];
    float x2 = (s & 1) ? a[5] : a[4];
    float x3 = (s & 1) ? a[7] : a[6];
    float y0 = (s & 2) ? x1 : x0;
    float y1 = (s & 2) ? x3 : x2;
    return (s & 4) ? y1 : y0;
}
// broadcast node-q values from lanes 0..7
__device__ __forceinline__ void bcast8(float v, float o[8]) {
#pragma unroll
    for (int q = 0; q < 8; q++) o[q] = __shfl_sync(0xffffffffu, v, q);
}

// act: h = proj(expmap0(relu(logmap0(h)))), slot form; n_s = lane's slot norm
__device__ __forceinline__ void act8s(float h0[8], float h1[8], float& n_s, int s) {
    float lv = fmaxf(n_s, MINN);
    float sa = __fdividef(fast_atanh(lv), lv);
    float SA[8];
    bcast8(sa, SA);
    float t2[8];
#pragma unroll
    for (int q = 0; q < 8; q++) {
        h0[q] = fmaxf(h0[q] * SA[q], 0.f);
        h1[q] = fmaxf(h1[q] * SA[q], 0.f);
        t2[q] = h0[q] * h0[q] + h1[q] * h1[q];
    }
    wsum8(t2);
    float tn = sqrtf(sel8(t2, s));
    float tc = fmaxf(tn, MINN);
    float se = __fdividef(fast_tanh(tc), tc);
    float nn = fmaxf(se * tn, MINN);
    if (nn > MAXN) { se *= __fdividef(MAXN, nn); nn = MAXN; }
    float SE[8];
    bcast8(se, SE);
    n_s = nn;
#pragma unroll
    for (int q = 0; q < 8; q++) { h0[q] *= SE[q]; h1[q] *= SE[q]; }
}

// stage 8 nodes: lane j owns pair j; xs[j*10 + q] = pack2(h0[q], h1[q])
// (80B-padded rows: aligned LDS.128 reads, 4-way-conflict writes)
__device__ __forceinline__ void stage_x8(ull* xs, const float h0[8],
                                         const float h1[8], int j) {
    __syncwarp();
#pragma unroll
    for (int q = 0; q < 8; q++) xs[j * 10 + q] = pack2(h0[q], h1[q]);
    __syncwarp();
}

// One 64->64 hyperbolic layer for 8 nodes held across the warp.
// Lane j owns output comps (2j, 2j+1); n_s = lane's slot norm (node j&7).
// Wq[t*32+j] = {pack2(W[2j][2t],W[2j][2t+1]), pack2(W[2j+1][2t],W[2j+1][2t+1])}
__device__ __forceinline__ void layer64_8(
    float h0[8], float h1[8], float& n_s,
    const ulonglong2* __restrict__ Wq, const float* __restrict__ eb, float ebn2,
    ull* xs, int j, bool act) {
    int s = j & 7;
    stage_x8(xs, h0, h1, j);
    ull a0[8] = {0, 0, 0, 0, 0, 0, 0, 0}, a1[8] = {0, 0, 0, 0, 0, 0, 0, 0};
#pragma unroll
    for (int t = 0; t < 32; t++) {
        ulonglong2 wv = Wq[t * 32 + j];
        const ulonglong2* xt = (const ulonglong2*)(xs + t * 10);
        ulonglong2 xA = xt[0], xB = xt[1], xC = xt[2], xD = xt[3];
        fma2(a0[0], xA.x, wv.x); fma2(a1[0], xA.x, wv.y);
        fma2(a0[1], xA.y, wv.x); fma2(a1[1], xA.y, wv.y);
        fma2(a0[2], xB.x, wv.x); fma2(a1[2], xB.x, wv.y);
        fma2(a0[3], xB.y, wv.x); fma2(a1[3], xB.y, wv.y);
        fma2(a0[4], xC.x, wv.x); fma2(a1[4], xC.x, wv.y);
        fma2(a0[5], xC.y, wv.x); fma2(a1[5], xC.y, wv.y);
        fma2(a0[6], xD.x, wv.x); fma2(a1[6], xD.x, wv.y);
        fma2(a0[7], xD.y, wv.x); fma2(a1[7], xD.y, wv.y);
    }
    float m0[8], m1[8], s2[8];
#pragma unroll
    for (int q = 0; q < 8; q++) {
        m0[q] = pairsum(a0[q]);
        m1[q] = pairsum(a1[q]);
        s2[q] = m0[q] * m0[q] + m1[q] * m1[q];
    }
    wsum8(s2);
    // mobius_matvec scale + proj, slot form
    float nv = fmaxf(n_s, MINN);
    float ml = sqrtf(sel8(s2, s));
    float mx = fmaxf(ml, MINN);
    float r = fast_tanh(__fdividef(mx, nv) * fast_atanh(nv));
    float sc = __fdividef(r, mx);
    float nn = fmaxf(r * __fdividef(ml, mx), MINN);
    if (nn > MAXN) { sc *= __fdividef(MAXN, nn); nn = MAXN; }
    float SC[8];
    bcast8(sc, SC);
#pragma unroll
    for (int q = 0; q < 8; q++) { h0[q] = m0[q] * SC[q]; h1[q] = m1[q] * SC[q]; }
    // mobius_add(h, expmap0(b))
    float2 ev = *(const float2*)(eb + 2 * j);
    float e0 = ev.x, e1 = ev.y;
    float xy[8];
#pragma unroll
    for (int q = 0; q < 8; q++) xy[q] = h0[q] * e0 + h1[q] * e1;
    wsum8(xy);
    float xyv = sel8(xy, s);
    float x2v = nn * nn;
    float c1 = 1.f + 2.f * xyv + ebn2;
    float c2 = 1.f - x2v;
    float inv = __fdividef(1.f, fmaxf(1.f + 2.f * xyv + x2v * ebn2, MINN));
    float C1[8], C2[8];
    bcast8(c1 * inv, C1);
    bcast8(c2 * inv, C2);
    float q2[8];
#pragma unroll
    for (int q = 0; q < 8; q++) {
        h0[q] = C1[q] * h0[q] + C2[q] * e0;
        h1[q] = C1[q] * h1[q] + C2[q] * e1;
        q2[q] = h0[q] * h0[q] + h1[q] * h1[q];
    }
    wsum8(q2);
    float nf = fmaxf(sqrtf(sel8(q2, s)), MINN);
    float ps = 1.f;
    if (nf > MAXN) { ps = __fdividef(MAXN, nf); nf = MAXN; }
    if (act) {
        float sa = ps * __fdividef(fast_atanh(nf), nf);   // proj + logmap0 fused
        float SA[8];
        bcast8(sa, SA);
        float t2[8];
#pragma unroll
        for (int q = 0; q < 8; q++) {
            h0[q] = fmaxf(h0[q] * SA[q], 0.f);
            h1[q] = fmaxf(h1[q] * SA[q], 0.f);
            t2[q] = h0[q] * h0[q] + h1[q] * h1[q];
        }
        wsum8(t2);
        float tn = sqrtf(sel8(t2, s));
        float tc = fmaxf(tn, MINN);
        float se = __fdividef(fast_tanh(tc), tc);
        float nfin = fmaxf(se * tn, MINN);
        if (nfin > MAXN) { se *= __fdividef(MAXN, nfin); nfin = MAXN; }
        float SE[8];
        bcast8(se, SE);
        n_s = nfin;
#pragma unroll
        for (int q = 0; q < 8; q++) { h0[q] *= SE[q]; h1[q] *= SE[q]; }
    } else {
        float PS[8];
        bcast8(ps, PS);
        n_s = nf;
#pragma unroll
        for (int q = 0; q < 8; q++) { h0[q] *= PS[q]; h1[q] *= PS[q]; }
    }
}

// Final 64->32 layer (no act). Lane j owns out comp j.
// W6q[t*32+j] = pack2(W6[j][2t], W6[j][2t+1]).
__device__ __forceinline__ void layer_out_8(
    float h0[8], float h1[8], float& n_s, float o[8],
    const ull* __restrict__ W6q, const float* __restrict__ eb, float ebn2,
    ull* xs, int j) {
    int s = j & 7;
    stage_x8(xs, h0, h1, j);
    ull a[8] = {0, 0, 0, 0, 0, 0, 0, 0};
#pragma unroll
    for (int t = 0; t < 32; t++) {
        ull wv = W6q[t * 32 + j];
        const ulonglong2* xt = (const ulonglong2*)(xs + t * 10);
        ulonglong2 xA = xt[0], xB = xt[1], xC = xt[2], xD = xt[3];
        fma2(a[0], xA.x, wv); fma2(a[1], xA.y, wv);
        fma2(a[2], xB.x, wv); fma2(a[3], xB.y, wv);
        fma2(a[4], xC.x, wv); fma2(a[5], xC.y, wv);
        fma2(a[6], xD.x, wv); fma2(a[7], xD.y, wv);
    }
    float m[8], s2[8];
#pragma unroll
    for (int q = 0; q < 8; q++) { m[q] = pairsum(a[q]); s2[q] = m[q] * m[q]; }
    wsum8(s2);
    float nv = fmaxf(n_s, MINN);
    float ml = sqrtf(sel8(s2, s));
    float mx = fmaxf(ml, MINN);
    float r = fast_tanh(__fdividef(mx, nv) * fast_atanh(nv));
    float sc = __fdividef(r, mx);
    float nn = fmaxf(r * __fdividef(ml, mx), MINN);
    if (nn > MAXN) { sc *= __fdividef(MAXN, nn); nn = MAXN; }
    float SC[8];
    bcast8(sc, SC);
#pragma unroll
    for (int q = 0; q < 8; q++) o[q] = m[q] * SC[q];
    float e0 = eb[j];
    float xy[8];
#pragma unroll
    for (int q = 0; q < 8; q++) xy[q] = o[q] * e0;
    wsum8(xy);
    float xyv = sel8(xy, s);
    float x2v = nn * nn;
    float c1 = 1.f + 2.f * xyv + ebn2;
    float c2 = 1.f - x2v;
    float inv = __fdividef(1.f, fmaxf(1.f + 2.f * xyv + x2v * ebn2, MINN));
    float C1[8], C2[8];
    bcast8(c1 * inv, C1);
    bcast8(c2 * inv, C2);
    float q2[8];
#pragma unroll
    for (int q = 0; q < 8; q++) {
        o[q] = C1[q] * o[q] + C2[q] * e0;
        q2[q] = o[q] * o[q];
    }
    wsum8(q2);
    float nf = fmaxf(sqrtf(sel8(q2, s)), MINN);
    float ps = 1.f;
    if (nf > MAXN) ps = __fdividef(MAXN, nf);
    float PS[8];
    bcast8(ps, PS);
#pragma unroll
    for (int q = 0; q < 8; q++) o[q] *= PS[q];
}

// bias -> eb = expmap0(b) (natural comp order), |eb|^2 (dim 64), one warp
__device__ __forceinline__ void compute_eb64(const float* __restrict__ b,
                                             float* eb, float* ebn2, int j) {
    float v0 = b[j], v1 = b[32 + j];
    float s2 = v0 * v0 + v1 * v1;
#pragma unroll
    for (int o = 16; o > 0; o >>= 1) s2 += __shfl_xor_sync(0xffffffffu, s2, o);
    float bn = sqrtf(s2), bc = fmaxf(bn, MINN);
    float se = __fdividef(fast_tanh(bc), bc);
    eb[j] = v0 * se;
    eb[32 + j] = v1 * se;
    if (j == 0) *ebn2 = (se * bn) * (se * bn);
}

// CSR gather-aggregate for one node; lane j sums comps (2j, 2j+1) via float2.
__device__ __forceinline__ void csr_agg(const float* __restrict__ tsrc, int node,
                                        int j, float& o0, float& o1, int& deg) {
    int s = g_off[node], e = g_off[node + 1];
    deg = e - s;
    float a0 = 0.f, a1 = 0.f, b0 = 0.f, b1 = 0.f;
    for (int base = s; base < e; base += 32) {
        int nh = min(32, e - base);
        int idx = (j < nh) ? g_col[base + j] : 0;
        int t = 0;
        for (; t + 8 <= nh; t += 8) {
#pragma unroll
            for (int u = 0; u < 8; u += 2) {
                int sa = __shfl_sync(0xffffffffu, idx, t + u);
                int sb = __shfl_sync(0xffffffffu, idx, t + u + 1);
                float2 va = __ldg((const float2*)(tsrc + (size_t)sa * 64) + j);
                float2 vb = __ldg((const float2*)(tsrc + (size_t)sb * 64) + j);
                a0 += va.x; a1 += va.y;
                b0 += vb.x; b1 += vb.y;
            }
        }
        for (; t < nh; t++) {
            int sx = __shfl_sync(0xffffffffu, idx, t);
            float2 v = __ldg((const float2*)(tsrc + (size_t)sx * 64) + j);
            a0 += v.x; a1 += v.y;
        }
    }
    o0 = a0 + b0; o1 = a1 + b1;
}

// mean + expmap0 + proj for 8 nodes via CSR gather, slot form
__device__ __forceinline__ void load_agg8_csr(const float* __restrict__ tsrc,
                                              int iBase, int j,
                                              float h0[8], float h1[8], float& n_s) {
    int s = j & 7;
    float n2[8];
#pragma unroll
    for (int q = 0; q < 8; q++) {
        int node = min(iBase + q, NN - 1);
        int deg;
        float a0, a1;
        csr_agg(tsrc, node, j, a0, a1, deg);
        float inv = __fdividef(1.f, fmaxf((float)deg, 1.f));
        h0[q] = a0 * inv;
        h1[q] = a1 * inv;
        n2[q] = h0[q] * h0[q] + h1[q] * h1[q];
    }
    wsum8(n2);
    float un = sqrtf(sel8(n2, s));
    float uc = fmaxf(un, MINN);
    float se = __fdividef(fast_tanh(uc), uc);
    float nn = fmaxf(se * un, MINN);
    if (nn > MAXN) { se *= __fdividef(MAXN, nn); nn = MAXN; }
    float SE[8];
    bcast8(se, SE);
    n_s = nn;
#pragma unroll
    for (int q = 0; q < 8; q++) { h0[q] *= SE[q]; h1[q] *= SE[q]; }
}

// load weights: Wq[t*32+j] = {pack2(W[2j][2t],W[2j][2t+1]), pack2(W[2j+1][2t],W[2j+1][2t+1])}
__device__ __forceinline__ void load_Wq(ulonglong2* Wq, const float* __restrict__ W,
                                        int K, int tid) {
    for (int i = tid; i < 1024; i += 256) {
        int t = i >> 5, jj = i & 31;
        int k0 = 2 * t, k1 = 2 * t + 1;
        int r0 = 2 * jj, r1 = 2 * jj + 1;
        float w00 = W[r0 * K + k0];
        float w01 = (k1 < K) ? W[r0 * K + k1] : 0.f;
        float w10 = W[r1 * K + k0];
        float w11 = (k1 < K) ? W[r1 * K + k1] : 0.f;
        ulonglong2 v;
        v.x = pack2(w00, w01);
        v.y = pack2(w10, w11);
        Wq[t * 32 + jj] = v;
    }
}

// ---------------- kernel A: poincare + layers 1..4 + logmap -> g_t ----------
__global__ void __launch_bounds__(256, 2) nodeA_kernel(
    const float* __restrict__ x,
    const float* __restrict__ W1, const float* __restrict__ b1,
    const float* __restrict__ W2, const float* __restrict__ b2,
    const float* __restrict__ W3, const float* __restrict__ b3,
    const float* __restrict__ W4, const float* __restrict__ b4) {
    extern __shared__ unsigned char smem_raw[];
    ulonglong2* Wq = (ulonglong2*)smem_raw;      // 4*1024 entries = 64KB
    ull* xall = (ull*)(Wq + 4 * 1024);           // 8 warps * 320 ull = 20KB
    float* eb = (float*)(xall + 8 * 320);        // 4*64
    float* ebn2 = eb + 256;                      // 4
    int tid = threadIdx.x;

    load_Wq(Wq,        W1, 63, tid);
    load_Wq(Wq + 1024, W2, 64, tid);
    load_Wq(Wq + 2048, W3, 64, tid);
    load_Wq(Wq + 3072, W4, 64, tid);
    int w = tid >> 5, j = tid & 31;
    if (w < 4) {
        const float* bp[4] = {b1, b2, b3, b4};
        compute_eb64(bp[w], eb + w * 64, ebn2 + w, j);
    }
    __syncthreads();

    int iBase = blockIdx.x * 64 + w * 8;
    ull* xs = xall + w * 320;
    int s = j & 7;
    float h0[8], h1[8], n_s, n2[8];
#pragma unroll
    for (int q = 0; q < 8; q++) {
        const float* xp = x + (size_t)min(iBase + q, NN - 1) * 64;
        float inv = __fdividef(1.f, xp[0] + 1.f);
        h0[q] = xp[1 + 2 * j] * inv;
        h1[q] = (j < 31) ? xp[2 + 2 * j] * inv : 0.f;
        n2[q] = h0[q] * h0[q] + h1[q] * h1[q];
    }
    wsum8(n2);
    {
        float nf = fmaxf(sqrtf(sel8(n2, s)), MINN);
        float ps = 1.f;
        if (nf > MAXN) { ps = __fdividef(MAXN, nf); nf = MAXN; }
        float PS[8];
        bcast8(ps, PS);
        n_s = nf;
#pragma unroll
        for (int q = 0; q < 8; q++) { h0[q] *= PS[q]; h1[q] *= PS[q]; }
    }

    layer64_8(h0, h1, n_s, Wq,        eb,       ebn2[0], xs, j, true);
    layer64_8(h0, h1, n_s, Wq + 1024, eb + 64,  ebn2[1], xs, j, true);
    layer64_8(h0, h1, n_s, Wq + 2048, eb + 128, ebn2[2], xs, j, true);
    layer64_8(h0, h1, n_s, Wq + 3072, eb + 192, ebn2[3], xs, j, false);

    // t = logmap0(h), paired store
    float lv = fmaxf(n_s, MINN);
    float sl = __fdividef(fast_atanh(lv), lv);
    float SL[8];
    bcast8(sl, SL);
#pragma unroll
    for (int q = 0; q < 8; q++) {
        if (iBase + q < NN) {
            float2 v = make_float2(h0[q] * SL[q], h1[q] * SL[q]);
            *((float2*)(g_t + (size_t)(iBase + q) * 64) + j) = v;
        }
    }
}

// ---------------- kernel B: csr-agg(g_t) + act + layer5 + logmap -> g_t2 ----
__global__ void __launch_bounds__(256, 2) nodeB_kernel(
    const float* __restrict__ W5, const float* __restrict__ b5) {
    extern __shared__ unsigned char smem_raw[];
    ulonglong2* Wq = (ulonglong2*)smem_raw;      // 1024 entries = 16KB
    ull* xall = (ull*)(Wq + 1024);               // 8 * 320 ull = 20KB
    float* eb = (float*)(xall + 8 * 320);        // 64
    float* ebn2 = eb + 64;
    int tid = threadIdx.x;
    load_Wq(Wq, W5, 64, tid);
    int w = tid >> 5, j = tid & 31;
    if (w == 0) compute_eb64(b5, eb, ebn2, j);
    __syncthreads();

    int iBase = blockIdx.x * 64 + w * 8;
    ull* xs = xall + w * 320;
    int s = j & 7;
    float h0[8], h1[8], n_s;
    load_agg8_csr(g_t, iBase, j, h0, h1, n_s);
    act8s(h0, h1, n_s, s);                                 // layer-4 activation
    layer64_8(h0, h1, n_s, Wq, eb, ebn2[0], xs, j, false); // layer-5 matvec+bias
    float lv = fmaxf(n_s, MINN);
    float sl = __fdividef(fast_atanh(lv), lv);
    float SL[8];
    bcast8(sl, SL);
#pragma unroll
    for (int q = 0; q < 8; q++) {
        if (iBase + q < NN) {
            float2 v = make_float2(h0[q] * SL[q], h1[q] * SL[q]);
            *((float2*)(g_t2 + (size_t)(iBase + q) * 64) + j) = v;
        }
    }
}

// ---------------- kernel C: csr-agg(g_t2) + act + layer6 -> out -------------
__global__ void __launch_bounds__(256, 2) nodeC_kernel(
    const float* __restrict__ W6, const float* __restrict__ b6,
    float* __restrict__ out) {
    extern __shared__ unsigned char smem_raw[];
    ull* W6q = (ull*)smem_raw;                   // 1024 entries = 8KB
    ull* xall = W6q + 1024;                      // 8 * 320 ull = 20KB
    float* eb = (float*)(xall + 8 * 320);        // 32
    float* ebn2 = eb + 32;
    int tid = threadIdx.x;
    for (int i = tid; i < 1024; i += 256) {
        int t = i >> 5, jj = i & 31;
        W6q[t * 32 + jj] = pack2(W6[jj * 64 + 2 * t], W6[jj * 64 + 2 * t + 1]);
    }
    int w = tid >> 5, j = tid & 31;
    if (w == 0) {
        float v0 = b6[j];
        float s2 = v0 * v0;
#pragma unroll
        for (int o = 16; o > 0; o >>= 1) s2 += __shfl_xor_sync(0xffffffffu, s2, o);
        float bn = sqrtf(s2), bc = fmaxf(bn, MINN);
        float se = __fdividef(fast_tanh(bc), bc);
        eb[j] = v0 * se;
        if (j == 0) *ebn2 = (se * bn) * (se * bn);
    }
    __syncthreads();

    int iBase = blockIdx.x * 64 + w * 8;
    ull* xs = xall + w * 320;
    int s = j & 7;
    float h0[8], h1[8], n_s, o[8];
    load_agg8_csr(g_t2, iBase, j, h0, h1, n_s);
    act8s(h0, h1, n_s, s);                             // layer-5 activation
    layer_out_8(h0, h1, n_s, o, W6q, eb, ebn2[0], xs, j);
#pragma unroll
    for (int q = 0; q < 8; q++)
        if (iBase + q < NN) out[(size_t)(iBase + q) * 32 + j] = o[q];
}

// ---------------- CSR build kernels ----------------
// zero g_cnt; block 0 also detects edge dtype and resets the scan counter
__global__ void __launch_bounds__(1024) detect_zero_kernel(const int* __restrict__ e32) {
    int i = blockIdx.x * 1024 + threadIdx.x;
    if (i < NN) g_cnt[i] = 0;
    if (blockIdx.x == 0) {
        __shared__ int nz;
        if (threadIdx.x == 0) { nz = 0; g_scan_done = 0; }
        __syncthreads();
        if (e32[2 * threadIdx.x + 1] != 0) atomicAdd(&nz, 1);
        __syncthreads();
        if (threadIdx.x == 0) g_idx64 = (nz == 0) ? 1 : 0;
    }
}

__global__ void __launch_bounds__(256) hist_kernel(const void* __restrict__ edges) {
    int i = blockIdx.x * 256 + threadIdx.x;
    if (i >= EE) return;
    int d = g_idx64 ? (int)__ldg((const long long*)edges + EE + i)
                    : __ldg((const int*)edges + EE + i);
    atomicAdd(&g_cnt[d], 1);
}

// single-kernel exclusive scan: 98 co-resident blocks + spin barrier
__global__ void __launch_bounds__(1024) scan_kernel() {
    __shared__ int sm[1024];
    __shared__ int base_s;
    int gi = blockIdx.x * 1024 + threadIdx.x;
    int v = (gi < NN) ? g_cnt[gi] : 0;
    sm[threadIdx.x] = v;
    __syncthreads();
#pragma unroll
    for (int o = 1; o < 1024; o <<= 1) {
        int t = (threadIdx.x >= o) ? sm[threadIdx.x - o] : 0;
        __syncthreads();
        sm[threadIdx.x] += t;
        __syncthreads();
    }
    int incl = sm[threadIdx.x];
    int excl = incl - v;
    if (threadIdx.x == 1023) {
        g_bsum[blockIdx.x] = incl;
        __threadfence();
        atomicAdd(&g_scan_done, 1);
    }
    if (threadIdx.x == 0) {
        while (*(volatile int*)&g_scan_done < SCAN_BLOCKS) {}
        __threadfence();
    }
    __syncthreads();
    if (threadIdx.x < 32) {
        int acc = 0;
        for (int i = (int)threadIdx.x; i < SCAN_BLOCKS; i += 32)
            if (i < (int)blockIdx.x) acc += g_bsum[i];
#pragma unroll
        for (int o = 16; o > 0; o >>= 1) acc += __shfl_xor_sync(0xffffffffu, acc, o);
        if (threadIdx.x == 0) base_s = acc;
    }
    __syncthreads();
    if (gi < NN) {
        int o = excl + base_s;
        g_off[gi] = o;
        g_cursor[gi] = o;
    }
    if (gi == 0) g_off[NN] = EE;
}

__global__ void __launch_bounds__(256) fill_kernel(const void* __restrict__ edges) {
    int i = blockIdx.x * 256 + threadIdx.x;
    if (i >= EE) return;
    int sV, dV;
    if (g_idx64) {
        sV = (int)__ldg((const long long*)edges + i);
        dV = (int)__ldg((const long long*)edges + EE + i);
    } else {
        sV = __ldg((const int*)edges + i);
        dV = __ldg((const int*)edges + EE + i);
    }
    int pos = atomicAdd(&g_cursor[dV], 1);
    g_col[pos] = sV;
}

// ---------------- launch ----------------
extern "C" void kernel_launch(void* const* d_in, const int* in_sizes, int n_in,
                              void* d_out, int out_size) {
    const float* x = (const float*)d_in[0];
    const float* W1 = (const float*)d_in[1];
    const float* b1 = (const float*)d_in[2];
    const float* W2 = (const float*)d_in[3];
    const float* b2 = (const float*)d_in[4];
    const float* W3 = (const float*)d_in[5];
    const float* b3 = (const float*)d_in[6];
    const float* W4 = (const float*)d_in[7];
    const float* b4 = (const float*)d_in[8];
    const float* W5 = (const float*)d_in[9];
    const float* b5 = (const float*)d_in[10];
    const float* W6 = (const float*)d_in[11];
    const float* b6 = (const float*)d_in[12];
    const void* edges = d_in[13];
    float* out = (float*)d_out;

    const int SMEM_A = 4 * 1024 * 16 + 8 * 320 * 8 + 256 * 4 + 16;  // 87072
    const int SMEM_B = 1024 * 16 + 8 * 320 * 8 + 64 * 4 + 16;       // 37136
    const int SMEM_C = 1024 * 8 + 8 * 320 * 8 + 32 * 4 + 16;        // 29008

    cudaFuncSetAttribute(nodeA_kernel, cudaFuncAttributeMaxDynamicSharedMemorySize, SMEM_A);
    cudaFuncSetAttribute(nodeB_kernel, cudaFuncAttributeMaxDynamicSharedMemorySize, SMEM_B);
    cudaFuncSetAttribute(nodeC_kernel, cudaFuncAttributeMaxDynamicSharedMemorySize, SMEM_C);

    const int EDGE_BLOCKS = (EE + 255) / 256; // 6250

    // Fork nodeA (no CSR dependency) onto a side stream to overlap the CSR
    // build; fall back to sequential if stream/event creation fails.
    cudaStream_t s2;
    cudaEvent_t ev0, evA;
    bool forked = (cudaStreamCreateWithFlags(&s2, cudaStreamNonBlocking) == cudaSuccess);
    if (forked) forked = (cudaEventCreateWithFlags(&ev0, cudaEventDisableTiming) == cudaSuccess);
    if (forked) forked = (cudaEventCreateWithFlags(&evA, cudaEventDisableTiming) == cudaSuccess);

    if (forked) {
        cudaEventRecord(ev0, 0);
        cudaStreamWaitEvent(s2, ev0, 0);
        nodeA_kernel<<<NODE_BLOCKS, 256, SMEM_A, s2>>>(x, W1, b1, W2, b2, W3, b3, W4, b4);
        cudaEventRecord(evA, s2);

        detect_zero_kernel<<<SCAN_BLOCKS, 1024>>>((const int*)edges);
        hist_kernel<<<EDGE_BLOCKS, 256>>>(edges);
        scan_kernel<<<SCAN_BLOCKS, 1024>>>();
        fill_kernel<<<EDGE_BLOCKS, 256>>>(edges);

        cudaStreamWaitEvent(0, evA, 0);   // join: nodeB needs g_t AND the CSR
    } else {
        detect_zero_kernel<<<SCAN_BLOCKS, 1024>>>((const int*)edges);
        hist_kernel<<<EDGE_BLOCKS, 256>>>(edges);
        scan_kernel<<<SCAN_BLOCKS, 1024>>>();
        fill_kernel<<<EDGE_BLOCKS, 256>>>(edges);
        nodeA_kernel<<<NODE_BLOCKS, 256, SMEM_A>>>(x, W1, b1, W2, b2, W3, b3, W4, b4);
    }

    nodeB_kernel<<<NODE_BLOCKS, 256, SMEM_B>>>(W5, b5);
    nodeC_kernel<<<NODE_BLOCKS, 256, SMEM_C>>>(W6, b6, out);
}

// round 7
// speedup vs baseline: 2.0882x; 1.0912x over previous
#include <cuda_runtime.h>
#include <cstdint>

#define NN 100000
#define EE 1600000
#define MINN 1e-15f
#define MAXN ((float)(1.0 - 1e-5))
#define SCAN_BLOCKS 98
#define NODE_BLOCKS ((NN + 63) / 64)   // 64 nodes per block (8 per warp)

typedef unsigned long long ull;

// ---------------- scratch ----------------
__device__ __align__(16) float g_t[(size_t)NN * 64];
__device__ __align__(16) float g_t2[(size_t)NN * 64];
__device__ int g_col[EE];
__device__ int g_cnt[NN];
__device__ int g_off[NN + 1];
__device__ int g_cursor[NN];
__device__ int g_bsum[SCAN_BLOCKS];
__device__ int g_scan_done;
__device__ int g_idx64;

// ---------------- packed f32x2 ----------------
__device__ __forceinline__ ull pack2(float lo, float hi) {
    ull r;
    asm("mov.b64 %0, {%1, %2};" : "=l"(r) : "f"(lo), "f"(hi));
    return r;
}
__device__ __forceinline__ void fma2(ull& d, ull a, ull b) {
    asm("fma.rn.f32x2 %0, %1, %2, %0;" : "+l"(d) : "l"(a), "l"(b));
}
__device__ __forceinline__ float pairsum(ull v) {
    float lo, hi;
    asm("mov.b64 {%0, %1}, %2;" : "=f"(lo), "=f"(hi) : "l"(v));
    return lo + hi;
}

// ---------------- fast math (args nonnegative) ----------------
__device__ __forceinline__ float fast_tanh(float x) {
    float e = __expf(-2.f * x);
    return __fdividef(1.f - e, 1.f + e);
}
__device__ __forceinline__ float fast_atanh(float x) {
    x = fminf(x, MAXN);
    return 0.5f * __logf(__fdividef(1.f + x, 1.f - x));
}

// reduce v[8] across warp -> lane j gets total of slot (j&7). 9 SHFL.
__device__ __forceinline__ float rsum8(const float v[8], int j) {
    bool p1 = j & 1;
    float a[4];
#pragma unroll
    for (int i = 0; i < 4; i++) {
        float m = p1 ? v[2 * i + 1] : v[2 * i];
        float o = p1 ? v[2 * i] : v[2 * i + 1];
        a[i] = m + __shfl_xor_sync(0xffffffffu, o, 1);
    }
    bool p2 = j & 2;
    float b0, b1;
    {
        float m = p2 ? a[1] : a[0], o = p2 ? a[0] : a[1];
        b0 = m + __shfl_xor_sync(0xffffffffu, o, 2);
    }
    {
        float m = p2 ? a[3] : a[2], o = p2 ? a[2] : a[3];
        b1 = m + __shfl_xor_sync(0xffffffffu, o, 2);
    }
    bool p4 = j & 4;
    float m = p4 ? b1 : b0, o = p4 ? b0 : b1;
    float c = m + __shfl_xor_sync(0xffffffffu, o, 4);
    c += __shfl_xor_sync(0xffffffffu, c, 8);
    c += __shfl_xor_sync(0xffffffffu, c, 16);
    return c;
}

// broadcast slot values held in lanes 0..7 to arrays
__device__ __forceinline__ void bcast8(float v, float o[8]) {
#pragma unroll
    for (int q = 0; q < 8; q++) o[q] = __shfl_sync(0xffffffffu, v, q);
}

// stage 8 nodes: xs[j*10 + q] = pack2(h0[q], h1[q]) (80B padded rows)
__device__ __forceinline__ void stage_x8(ull* xs, const float h0[8],
                                         const float h1[8], int j) {
    __syncwarp();
#pragma unroll
    for (int q = 0; q < 8; q++) xs[j * 10 + q] = pack2(h0[q], h1[q]);
    __syncwarp();
}

#define MODE_ACT 0
#define MODE_LOGMAP 1

// One 64->64 hyperbolic layer for 8 nodes held across the warp.
// Lane j owns output comps (2j,2j+1); n_s = this lane's slot (j&7) norm.
// MODE_ACT: h <- proj(expmap0(relu(logmap0(proj(mobius_add(...)))))), n_s updated.
// MODE_LOGMAP: h <- logmap0(proj(mobius_add(...))); n_s dead afterwards.
__device__ __forceinline__ void layer64_8(
    float h0[8], float h1[8], float& n_s,
    const ulonglong2* __restrict__ Wq, const float* __restrict__ eb, float ebn2,
    ull* xs, int j, int mode) {
    stage_x8(xs, h0, h1, j);
    ull a0[8] = {0, 0, 0, 0, 0, 0, 0, 0}, a1[8] = {0, 0, 0, 0, 0, 0, 0, 0};
#pragma unroll
    for (int t = 0; t < 32; t++) {
        ulonglong2 wv = Wq[t * 32 + j];
        const ulonglong2* xt = (const ulonglong2*)(xs + t * 10);
        ulonglong2 xA = xt[0], xB = xt[1], xC = xt[2], xD = xt[3];
        fma2(a0[0], xA.x, wv.x); fma2(a1[0], xA.x, wv.y);
        fma2(a0[1], xA.y, wv.x); fma2(a1[1], xA.y, wv.y);
        fma2(a0[2], xB.x, wv.x); fma2(a1[2], xB.x, wv.y);
        fma2(a0[3], xB.y, wv.x); fma2(a1[3], xB.y, wv.y);
        fma2(a0[4], xC.x, wv.x); fma2(a1[4], xC.x, wv.y);
        fma2(a0[5], xC.y, wv.x); fma2(a1[5], xC.y, wv.y);
        fma2(a0[6], xD.x, wv.x); fma2(a1[6], xD.x, wv.y);
        fma2(a0[7], xD.y, wv.x); fma2(a1[7], xD.y, wv.y);
    }
    float2 ev = *(const float2*)(eb + 2 * j);
    float m0[8], m1[8], s2[8], d[8];
#pragma unroll
    for (int q = 0; q < 8; q++) {
        m0[q] = pairsum(a0[q]);
        m1[q] = pairsum(a1[q]);
        s2[q] = m0[q] * m0[q] + m1[q] * m1[q];
        d[q] = m0[q] * ev.x + m1[q] * ev.y;
    }
    float s2s = rsum8(s2, j);
    float ds = rsum8(d, j);
    // ---- scalar (slot) chain ----
    float xn = fmaxf(n_s, MINN);
    float ml = sqrtf(s2s);
    float mx = fmaxf(ml, MINN);
    float r = fast_tanh(__fdividef(mx, xn) * fast_atanh(xn));
    float sc = __fdividef(r, mx);
    float n1 = fmaxf(r * __fdividef(ml, mx), MINN);
    if (n1 > MAXN) { sc *= __fdividef(MAXN, n1); n1 = MAXN; }
    float xyv = sc * ds;                       // <x, e> after scaling
    float x2 = n1 * n1;
    float c1 = 1.f + 2.f * xyv + ebn2;
    float c2 = 1.f - x2;
    float iv = __fdividef(1.f, fmaxf(1.f + 2.f * xyv + x2 * ebn2, MINN));
    // analytic |mobius_add|^2
    float q2 = iv * iv * (c1 * c1 * x2 + 2.f * c1 * c2 * xyv + c2 * c2 * ebn2);
    float nf = fmaxf(sqrtf(q2), MINN);
    float ps = 1.f;
    if (nf > MAXN) { ps = __fdividef(MAXN, nf); nf = MAXN; }
    float sl = __fdividef(fast_atanh(nf), nf);   // logmap0 scale (both modes)
    float A = ps * iv * c1 * sc * sl;
    float B = ps * iv * c2 * sl;
    float AA[8], BB[8];
    bcast8(A, AA);
    bcast8(B, BB);
    if (mode == MODE_LOGMAP) {
#pragma unroll
        for (int q = 0; q < 8; q++) {
            h0[q] = AA[q] * m0[q] + BB[q] * ev.x;
            h1[q] = AA[q] * m1[q] + BB[q] * ev.y;
        }
        return;
    }
    // MODE_ACT: relu in tangent space, expmap0, proj
    float t2[8];
#pragma unroll
    for (int q = 0; q < 8; q++) {
        float u0 = fmaxf(AA[q] * m0[q] + BB[q] * ev.x, 0.f);
        float u1 = fmaxf(AA[q] * m1[q] + BB[q] * ev.y, 0.f);
        h0[q] = u0; h1[q] = u1;
        t2[q] = u0 * u0 + u1 * u1;
    }
    float t2s = rsum8(t2, j);
    float tn = sqrtf(t2s);
    float tc = fmaxf(tn, MINN);
    float se = __fdividef(fast_tanh(tc), tc);
    float nn = fmaxf(se * tn, MINN);
    if (nn > MAXN) { se *= __fdividef(MAXN, nn); nn = MAXN; }
    float SE[8];
    bcast8(se, SE);
    n_s = nn;
#pragma unroll
    for (int q = 0; q < 8; q++) { h0[q] *= SE[q]; h1[q] *= SE[q]; }
}

// Final 64->32 layer (no act): out = proj(mobius_add(matvec, eb)).
__device__ __forceinline__ void layer_out_8(
    float h0[8], float h1[8], float n_s, float o[8],
    const ull* __restrict__ W6q, const float* __restrict__ eb, float ebn2,
    ull* xs, int j) {
    stage_x8(xs, h0, h1, j);
    ull a[8] = {0, 0, 0, 0, 0, 0, 0, 0};
#pragma unroll
    for (int t = 0; t < 32; t++) {
        ull wv = W6q[t * 32 + j];
        const ulonglong2* xt = (const ulonglong2*)(xs + t * 10);
        ulonglong2 xA = xt[0], xB = xt[1], xC = xt[2], xD = xt[3];
        fma2(a[0], xA.x, wv); fma2(a[1], xA.y, wv);
        fma2(a[2], xB.x, wv); fma2(a[3], xB.y, wv);
        fma2(a[4], xC.x, wv); fma2(a[5], xC.y, wv);
        fma2(a[6], xD.x, wv); fma2(a[7], xD.y, wv);
    }
    float e0 = eb[j];
    float m[8], s2[8], d[8];
#pragma unroll
    for (int q = 0; q < 8; q++) {
        m[q] = pairsum(a[q]);
        s2[q] = m[q] * m[q];
        d[q] = m[q] * e0;
    }
    float s2s = rsum8(s2, j);
    float ds = rsum8(d, j);
    float xn = fmaxf(n_s, MINN);
    float ml = sqrtf(s2s);
    float mx = fmaxf(ml, MINN);
    float r = fast_tanh(__fdividef(mx, xn) * fast_atanh(xn));
    float sc = __fdividef(r, mx);
    float n1 = fmaxf(r * __fdividef(ml, mx), MINN);
    if (n1 > MAXN) { sc *= __fdividef(MAXN, n1); n1 = MAXN; }
    float xyv = sc * ds;
    float x2 = n1 * n1;
    float c1 = 1.f + 2.f * xyv + ebn2;
    float c2 = 1.f - x2;
    float iv = __fdividef(1.f, fmaxf(1.f + 2.f * xyv + x2 * ebn2, MINN));
    float q2 = iv * iv * (c1 * c1 * x2 + 2.f * c1 * c2 * xyv + c2 * c2 * ebn2);
    float nf = fmaxf(sqrtf(q2), MINN);
    float ps = 1.f;
    if (nf > MAXN) ps = __fdividef(MAXN, nf);
    float A = ps * iv * c1 * sc;
    float B = ps * iv * c2;
    float AA[8], BB[8];
    bcast8(A, AA);
    bcast8(B, BB);
#pragma unroll
    for (int q = 0; q < 8; q++) o[q] = AA[q] * m[q] + BB[q] * e0;
}

// bias -> eb = expmap0(b), |eb|^2, one warp
__device__ __forceinline__ void compute_eb64(const float* __restrict__ b,
                                             float* eb, float* ebn2, int j) {
    float v0 = b[j], v1 = b[32 + j];
    float s2 = v0 * v0 + v1 * v1;
#pragma unroll
    for (int o = 16; o > 0; o >>= 1) s2 += __shfl_xor_sync(0xffffffffu, s2, o);
    float bn = sqrtf(s2), bc = fmaxf(bn, MINN);
    float se = __fdividef(fast_tanh(bc), bc);
    eb[j] = v0 * se;
    eb[32 + j] = v1 * se;
    if (j == 0) *ebn2 = (se * bn) * (se * bn);
}

// CSR gather for one node; lane j sums comps (2j,2j+1) via float2
__device__ __forceinline__ void csr_agg(const float* __restrict__ tsrc, int node,
                                        int j, float& o0, float& o1, int& deg) {
    int s = g_off[node], e = g_off[node + 1];
    deg = e - s;
    float a0 = 0.f, a1 = 0.f, b0 = 0.f, b1 = 0.f;
    for (int base = s; base < e; base += 32) {
        int nh = min(32, e - base);
        int idx = (j < nh) ? g_col[base + j] : 0;
        int t = 0;
        for (; t + 8 <= nh; t += 8) {
#pragma unroll
            for (int u = 0; u < 8; u += 2) {
                int sa = __shfl_sync(0xffffffffu, idx, t + u);
                int sb = __shfl_sync(0xffffffffu, idx, t + u + 1);
                float2 va = __ldg((const float2*)(tsrc + (size_t)sa * 64) + j);
                float2 vb = __ldg((const float2*)(tsrc + (size_t)sb * 64) + j);
                a0 += va.x; a1 += va.y;
                b0 += vb.x; b1 += vb.y;
            }
        }
        for (; t < nh; t++) {
            int sx = __shfl_sync(0xffffffffu, idx, t);
            float2 v = __ldg((const float2*)(tsrc + (size_t)sx * 64) + j);
            a0 += v.x; a1 += v.y;
        }
    }
    o0 = a0 + b0; o1 = a1 + b1;
}

// agg mean + expmap0 + proj + activation, all scales folded.
// Result: h (post-act, post-proj), n_s = slot norm.
__device__ __forceinline__ void agg_act8(const float* __restrict__ tsrc,
                                         int iBase, int j,
                                         float h0[8], float h1[8], float& n_s) {
    float n2[8];
#pragma unroll
    for (int q = 0; q < 8; q++) {
        int node = min(iBase + q, NN - 1);
        int deg;
        float a0, a1;
        csr_agg(tsrc, node, j, a0, a1, deg);
        float inv = __fdividef(1.f, fmaxf((float)deg, 1.f));
        h0[q] = a0 * inv;
        h1[q] = a1 * inv;
        n2[q] = h0[q] * h0[q] + h1[q] * h1[q];
    }
    float n2s = rsum8(n2, j);
    // expmap0 scale + proj + logmap0 scale (for the act), folded
    float un = sqrtf(n2s);
    float uc = fmaxf(un, MINN);
    float se = __fdividef(fast_tanh(uc), uc);
    float nn = fmaxf(se * un, MINN);
    if (nn > MAXN) { se *= __fdividef(MAXN, nn); nn = MAXN; }
    float comb = se * __fdividef(fast_atanh(nn), nn);   // into relu input
    float CB[8];
    bcast8(comb, CB);
    float t2[8];
#pragma unroll
    for (int q = 0; q < 8; q++) {
        float u0 = fmaxf(h0[q] * CB[q], 0.f);
        float u1 = fmaxf(h1[q] * CB[q], 0.f);
        h0[q] = u0; h1[q] = u1;
        t2[q] = u0 * u0 + u1 * u1;
    }
    float t2s = rsum8(t2, j);
    float tn = sqrtf(t2s);
    float tc = fmaxf(tn, MINN);
    float se2 = __fdividef(fast_tanh(tc), tc);
    float nn2 = fmaxf(se2 * tn, MINN);
    if (nn2 > MAXN) { se2 *= __fdividef(MAXN, nn2); nn2 = MAXN; }
    float SE[8];
    bcast8(se2, SE);
    n_s = nn2;
#pragma unroll
    for (int q = 0; q < 8; q++) { h0[q] *= SE[q]; h1[q] *= SE[q]; }
}

// load weights: Wq[t*32+j] = {pack2(W[2j][2t],W[2j][2t+1]), pack2(W[2j+1][2t],W[2j+1][2t+1])}
__device__ __forceinline__ void load_Wq(ulonglong2* Wq, const float* __restrict__ W,
                                        int K, int tid) {
    for (int i = tid; i < 1024; i += 256) {
        int t = i >> 5, jj = i & 31;
        int k0 = 2 * t, k1 = 2 * t + 1;
        int r0 = 2 * jj, r1 = 2 * jj + 1;
        float w00 = W[r0 * K + k0];
        float w01 = (k1 < K) ? W[r0 * K + k1] : 0.f;
        float w10 = W[r1 * K + k0];
        float w11 = (k1 < K) ? W[r1 * K + k1] : 0.f;
        ulonglong2 v;
        v.x = pack2(w00, w01);
        v.y = pack2(w10, w11);
        Wq[t * 32 + jj] = v;
    }
}

// ---------------- kernel A: poincare + layers 1..4 + logmap -> g_t ----------
__global__ void __launch_bounds__(256, 2) nodeA_kernel(
    const float* __restrict__ x,
    const float* __restrict__ W1, const float* __restrict__ b1,
    const float* __restrict__ W2, const float* __restrict__ b2,
    const float* __restrict__ W3, const float* __restrict__ b3,
    const float* __restrict__ W4, const float* __restrict__ b4) {
    extern __shared__ unsigned char smem_raw[];
    ulonglong2* Wq = (ulonglong2*)smem_raw;      // 64KB
    ull* xall = (ull*)(Wq + 4 * 1024);           // 8 * 320 ull
    float* eb = (float*)(xall + 8 * 320);
    float* ebn2 = eb + 256;
    int tid = threadIdx.x;

    load_Wq(Wq,        W1, 63, tid);
    load_Wq(Wq + 1024, W2, 64, tid);
    load_Wq(Wq + 2048, W3, 64, tid);
    load_Wq(Wq + 3072, W4, 64, tid);
    int w = tid >> 5, j = tid & 31;
    if (w < 4) {
        const float* bp[4] = {b1, b2, b3, b4};
        compute_eb64(bp[w], eb + w * 64, ebn2 + w, j);
    }
    __syncthreads();

    int iBase = blockIdx.x * 64 + w * 8;
    ull* xs = xall + w * 320;
    float h0[8], h1[8], n_s, n2[8];
#pragma unroll
    for (int q = 0; q < 8; q++) {
        const float* xp = x + (size_t)min(iBase + q, NN - 1) * 64;
        float inv = __fdividef(1.f, xp[0] + 1.f);
        h0[q] = xp[1 + 2 * j] * inv;
        h1[q] = (j < 31) ? xp[2 + 2 * j] * inv : 0.f;
        n2[q] = h0[q] * h0[q] + h1[q] * h1[q];
    }
    {
        float n2s = rsum8(n2, j);
        float nf = fmaxf(sqrtf(n2s), MINN);
        float ps = 1.f;
        if (nf > MAXN) { ps = __fdividef(MAXN, nf); nf = MAXN; }
        float PS[8];
        bcast8(ps, PS);
        n_s = nf;
#pragma unroll
        for (int q = 0; q < 8; q++) { h0[q] *= PS[q]; h1[q] *= PS[q]; }
    }

    layer64_8(h0, h1, n_s, Wq,        eb,       ebn2[0], xs, j, MODE_ACT);
    layer64_8(h0, h1, n_s, Wq + 1024, eb + 64,  ebn2[1], xs, j, MODE_ACT);
    layer64_8(h0, h1, n_s, Wq + 2048, eb + 128, ebn2[2], xs, j, MODE_ACT);
    layer64_8(h0, h1, n_s, Wq + 3072, eb + 192, ebn2[3], xs, j, MODE_LOGMAP);

#pragma unroll
    for (int q = 0; q < 8; q++) {
        if (iBase + q < NN) {
            float2 v = make_float2(h0[q], h1[q]);
            *((float2*)(g_t + (size_t)(iBase + q) * 64) + j) = v;
        }
    }
}

// ---------------- kernel B: agg(g_t)+act + layer5(logmap) -> g_t2 -----------
__global__ void __launch_bounds__(256, 2) nodeB_kernel(
    const float* __restrict__ W5, const float* __restrict__ b5) {
    extern __shared__ unsigned char smem_raw[];
    ulonglong2* Wq = (ulonglong2*)smem_raw;
    ull* xall = (ull*)(Wq + 1024);
    float* eb = (float*)(xall + 8 * 320);
    float* ebn2 = eb + 64;
    int tid = threadIdx.x;
    load_Wq(Wq, W5, 64, tid);
    int w = tid >> 5, j = tid & 31;
    if (w == 0) compute_eb64(b5, eb, ebn2, j);
    __syncthreads();

    int iBase = blockIdx.x * 64 + w * 8;
    ull* xs = xall + w * 320;
    float h0[8], h1[8], n_s;
    agg_act8(g_t, iBase, j, h0, h1, n_s);
    layer64_8(h0, h1, n_s, Wq, eb, ebn2[0], xs, j, MODE_LOGMAP);
#pragma unroll
    for (int q = 0; q < 8; q++) {
        if (iBase + q < NN) {
            float2 v = make_float2(h0[q], h1[q]);
            *((float2*)(g_t2 + (size_t)(iBase + q) * 64) + j) = v;
        }
    }
}

// ---------------- kernel C: agg(g_t2)+act + layer6 -> out -------------------
__global__ void __launch_bounds__(256, 2) nodeC_kernel(
    const float* __restrict__ W6, const float* __restrict__ b6,
    float* __restrict__ out) {
    extern __shared__ unsigned char smem_raw[];
    ull* W6q = (ull*)smem_raw;
    ull* xall = W6q + 1024;
    float* eb = (float*)(xall + 8 * 320);
    float* ebn2 = eb + 32;
    int tid = threadIdx.x;
    for (int i = tid; i < 1024; i += 256) {
        int t = i >> 5, jj = i & 31;
        W6q[t * 32 + jj] = pack2(W6[jj * 64 + 2 * t], W6[jj * 64 + 2 * t + 1]);
    }
    int w = tid >> 5, j = tid & 31;
    if (w == 0) {
        float v0 = b6[j];
        float s2 = v0 * v0;
#pragma unroll
        for (int o = 16; o > 0; o >>= 1) s2 += __shfl_xor_sync(0xffffffffu, s2, o);
        float bn = sqrtf(s2), bc = fmaxf(bn, MINN);
        float se = __fdividef(fast_tanh(bc), bc);
        eb[j] = v0 * se;
        if (j == 0) *ebn2 = (se * bn) * (se * bn);
    }
    __syncthreads();

    int iBase = blockIdx.x * 64 + w * 8;
    ull* xs = xall + w * 320;
    float h0[8], h1[8], n_s, o[8];
    agg_act8(g_t2, iBase, j, h0, h1, n_s);
    layer_out_8(h0, h1, n_s, o, W6q, eb, ebn2[0], xs, j);
#pragma unroll
    for (int q = 0; q < 8; q++)
        if (iBase + q < NN) out[(size_t)(iBase + q) * 32 + j] = o[q];
}

// ---------------- CSR build ----------------
__global__ void __launch_bounds__(1024) detect_zero_kernel(const int* __restrict__ e32) {
    int i = blockIdx.x * 1024 + threadIdx.x;
    if (i < NN) g_cnt[i] = 0;
    if (blockIdx.x == 0) {
        __shared__ int nz;
        if (threadIdx.x == 0) { nz = 0; g_scan_done = 0; }
        __syncthreads();
        if (e32[2 * threadIdx.x + 1] != 0) atomicAdd(&nz, 1);
        __syncthreads();
        if (threadIdx.x == 0) g_idx64 = (nz == 0) ? 1 : 0;
    }
}

__global__ void __launch_bounds__(256) hist_kernel(const void* __restrict__ edges) {
    int i = blockIdx.x * 256 + threadIdx.x;
    if (i >= EE) return;
    int d = g_idx64 ? (int)__ldg((const long long*)edges + EE + i)
                    : __ldg((const int*)edges + EE + i);
    atomicAdd(&g_cnt[d], 1);
}

__global__ void __launch_bounds__(1024) scan_kernel() {
    __shared__ int sm[1024];
    __shared__ int base_s;
    int gi = blockIdx.x * 1024 + threadIdx.x;
    int v = (gi < NN) ? g_cnt[gi] : 0;
    sm[threadIdx.x] = v;
    __syncthreads();
#pragma unroll
    for (int o = 1; o < 1024; o <<= 1) {
        int t = (threadIdx.x >= o) ? sm[threadIdx.x - o] : 0;
        __syncthreads();
        sm[threadIdx.x] += t;
        __syncthreads();
    }
    int incl = sm[threadIdx.x];
    int excl = incl - v;
    if (threadIdx.x == 1023) {
        g_bsum[blockIdx.x] = incl;
        __threadfence();
        atomicAdd(&g_scan_done, 1);
    }
    if (threadIdx.x == 0) {
        while (*(volatile int*)&g_scan_done < SCAN_BLOCKS) {}
        __threadfence();
    }
    __syncthreads();
    if (threadIdx.x < 32) {
        int acc = 0;
        for (int i = (int)threadIdx.x; i < SCAN_BLOCKS; i += 32)
            if (i < (int)blockIdx.x) acc += g_bsum[i];
#pragma unroll
        for (int o = 16; o > 0; o >>= 1) acc += __shfl_xor_sync(0xffffffffu, acc, o);
        if (threadIdx.x == 0) base_s = acc;
    }
    __syncthreads();
    if (gi < NN) {
        int o = excl + base_s;
        g_off[gi] = o;
        g_cursor[gi] = o;
    }
    if (gi == 0) g_off[NN] = EE;
}

__global__ void __launch_bounds__(256) fill_kernel(const void* __restrict__ edges) {
    int i = blockIdx.x * 256 + threadIdx.x;
    if (i >= EE) return;
    int sV, dV;
    if (g_idx64) {
        sV = (int)__ldg((const long long*)edges + i);
        dV = (int)__ldg((const long long*)edges + EE + i);
    } else {
        sV = __ldg((const int*)edges + i);
        dV = __ldg((const int*)edges + EE + i);
    }
    int pos = atomicAdd(&g_cursor[dV], 1);
    g_col[pos] = sV;
}

// ---------------- launch ----------------
extern "C" void kernel_launch(void* const* d_in, const int* in_sizes, int n_in,
                              void* d_out, int out_size) {
    const float* x = (const float*)d_in[0];
    const float* W1 = (const float*)d_in[1];
    const float* b1 = (const float*)d_in[2];
    const float* W2 = (const float*)d_in[3];
    const float* b2 = (const float*)d_in[4];
    const float* W3 = (const float*)d_in[5];
    const float* b3 = (const float*)d_in[6];
    const float* W4 = (const float*)d_in[7];
    const float* b4 = (const float*)d_in[8];
    const float* W5 = (const float*)d_in[9];
    const float* b5 = (const float*)d_in[10];
    const float* W6 = (const float*)d_in[11];
    const float* b6 = (const float*)d_in[12];
    const void* edges = d_in[13];
    float* out = (float*)d_out;

    const int SMEM_A = 4 * 1024 * 16 + 8 * 320 * 8 + 256 * 4 + 16;
    const int SMEM_B = 1024 * 16 + 8 * 320 * 8 + 64 * 4 + 16;
    const int SMEM_C = 1024 * 8 + 8 * 320 * 8 + 32 * 4 + 16;

    cudaFuncSetAttribute(nodeA_kernel, cudaFuncAttributeMaxDynamicSharedMemorySize, SMEM_A);
    cudaFuncSetAttribute(nodeB_kernel, cudaFuncAttributeMaxDynamicSharedMemorySize, SMEM_B);
    cudaFuncSetAttribute(nodeC_kernel, cudaFuncAttributeMaxDynamicSharedMemorySize, SMEM_C);

    const int EDGE_BLOCKS = (EE + 255) / 256;

    cudaStream_t s2;
    cudaEvent_t ev0, evA;
    bool forked = (cudaStreamCreateWithFlags(&s2, cudaStreamNonBlocking) == cudaSuccess);
    if (forked) forked = (cudaEventCreateWithFlags(&ev0, cudaEventDisableTiming) == cudaSuccess);
    if (forked) forked = (cudaEventCreateWithFlags(&evA, cudaEventDisableTiming) == cudaSuccess);

    if (forked) {
        cudaEventRecord(ev0, 0);
        cudaStreamWaitEvent(s2, ev0, 0);
        nodeA_kernel<<<NODE_BLOCKS, 256, SMEM_A, s2>>>(x, W1, b1, W2, b2, W3, b3, W4, b4);
        cudaEventRecord(evA, s2);

        detect_zero_kernel<<<SCAN_BLOCKS, 1024>>>((const int*)edges);
        hist_kernel<<<EDGE_BLOCKS, 256>>>(edges);
        scan_kernel<<<SCAN_BLOCKS, 1024>>>();
        fill_kernel<<<EDGE_BLOCKS, 256>>>(edges);

        cudaStreamWaitEvent(0, evA, 0);
    } else {
        detect_zero_kernel<<<SCAN_BLOCKS, 1024>>>((const int*)edges);
        hist_kernel<<<EDGE_BLOCKS, 256>>>(edges);
        scan_kernel<<<SCAN_BLOCKS, 1024>>>();
        fill_kernel<<<EDGE_BLOCKS, 256>>>(edges);
        nodeA_kernel<<<NODE_BLOCKS, 256, SMEM_A>>>(x, W1, b1, W2, b2, W3, b3, W4, b4);
    }

    nodeB_kernel<<<NODE_BLOCKS, 256, SMEM_B>>>(W5, b5);
    nodeC_kernel<<<NODE_BLOCKS, 256, SMEM_C>>>(W6, b6, out);
}

// round 8
// speedup vs baseline: 2.0952x; 1.0033x over previous
#include <cuda_runtime.h>
#include <cstdint>

#define NN 100000
#define EE 1600000
#define MINN 1e-15f
#define MAXN ((float)(1.0 - 1e-5))
#define SCAN_BLOCKS 98
#define NODE_BLOCKS ((NN + 63) / 64)   // 64 nodes per block (8 per warp)

typedef unsigned long long ull;

// ---------------- scratch ----------------
__device__ __align__(16) float g_t[(size_t)NN * 64];
__device__ __align__(16) float g_t2[(size_t)NN * 64];
__device__ int g_col[EE];
__device__ int g_cnt[NN];
__device__ int g_off[NN + 1];
__device__ int g_cursor[NN];
__device__ int g_bsum[SCAN_BLOCKS];
__device__ int g_scan_done;
__device__ int g_idx64;

// ---------------- packed f32x2 ----------------
__device__ __forceinline__ ull pack2(float lo, float hi) {
    ull r;
    asm("mov.b64 %0, {%1, %2};" : "=l"(r) : "f"(lo), "f"(hi));
    return r;
}
__device__ __forceinline__ void fma2(ull& d, ull a, ull b) {
    asm("fma.rn.f32x2 %0, %1, %2, %0;" : "+l"(d) : "l"(a), "l"(b));
}
__device__ __forceinline__ float pairsum(ull v) {
    float lo, hi;
    asm("mov.b64 {%0, %1}, %2;" : "=f"(lo), "=f"(hi) : "l"(v));
    return lo + hi;
}

// ---------------- fast math (args nonnegative) ----------------
__device__ __forceinline__ float fast_tanh(float x) {
    float e = __expf(-2.f * x);
    return __fdividef(1.f - e, 1.f + e);
}
__device__ __forceinline__ float fast_atanh(float x) {
    x = fminf(x, MAXN);
    return 0.5f * __logf(__fdividef(1.f + x, 1.f - x));
}

// reduce v[8] across warp -> lane j gets total of slot (j&7). 9 SHFL, depth 5.
__device__ __forceinline__ float rsum8(const float v[8], int j) {
    bool p1 = j & 1;
    float a[4];
#pragma unroll
    for (int i = 0; i < 4; i++) {
        float m = p1 ? v[2 * i + 1] : v[2 * i];
        float o = p1 ? v[2 * i] : v[2 * i + 1];
        a[i] = m + __shfl_xor_sync(0xffffffffu, o, 1);
    }
    bool p2 = j & 2;
    float b0, b1;
    {
        float m = p2 ? a[1] : a[0], o = p2 ? a[0] : a[1];
        b0 = m + __shfl_xor_sync(0xffffffffu, o, 2);
    }
    {
        float m = p2 ? a[3] : a[2], o = p2 ? a[2] : a[3];
        b1 = m + __shfl_xor_sync(0xffffffffu, o, 2);
    }
    bool p4 = j & 4;
    float m = p4 ? b1 : b0, o = p4 ? b0 : b1;
    float c = m + __shfl_xor_sync(0xffffffffu, o, 4);
    c += __shfl_xor_sync(0xffffffffu, c, 8);
    c += __shfl_xor_sync(0xffffffffu, c, 16);
    return c;
}

__device__ __forceinline__ void bcast8(float v, float o[8]) {
#pragma unroll
    for (int q = 0; q < 8; q++) o[q] = __shfl_sync(0xffffffffu, v, q);
}

// stage 8 nodes: xs[j*10 + q] = pack2(h0[q], h1[q]) (80B padded rows)
__device__ __forceinline__ void stage_x8(ull* xs, const float h0[8],
                                         const float h1[8], int j) {
    __syncwarp();
#pragma unroll
    for (int q = 0; q < 8; q++) xs[j * 10 + q] = pack2(h0[q], h1[q]);
    __syncwarp();
}

// 64x64 matvec block: M (raw, unscaled) for 8 nodes. Lane j owns comps (2j,2j+1).
__device__ __forceinline__ void fma_block64(const ulonglong2* __restrict__ Wq,
                                            const ull* xs, int j,
                                            float m0[8], float m1[8]) {
    ull a0[8] = {0, 0, 0, 0, 0, 0, 0, 0}, a1[8] = {0, 0, 0, 0, 0, 0, 0, 0};
#pragma unroll
    for (int t = 0; t < 32; t++) {
        ulonglong2 wv = Wq[t * 32 + j];
        const ulonglong2* xt = (const ulonglong2*)(xs + t * 10);
        ulonglong2 xA = xt[0], xB = xt[1], xC = xt[2], xD = xt[3];
        fma2(a0[0], xA.x, wv.x); fma2(a1[0], xA.x, wv.y);
        fma2(a0[1], xA.y, wv.x); fma2(a1[1], xA.y, wv.y);
        fma2(a0[2], xB.x, wv.x); fma2(a1[2], xB.x, wv.y);
        fma2(a0[3], xB.y, wv.x); fma2(a1[3], xB.y, wv.y);
        fma2(a0[4], xC.x, wv.x); fma2(a1[4], xC.x, wv.y);
        fma2(a0[5], xC.y, wv.x); fma2(a1[5], xC.y, wv.y);
        fma2(a0[6], xD.x, wv.x); fma2(a1[6], xD.x, wv.y);
        fma2(a0[7], xD.y, wv.x); fma2(a1[7], xD.y, wv.y);
    }
#pragma unroll
    for (int q = 0; q < 8; q++) {
        m0[q] = pairsum(a0[q]);
        m1[q] = pairsum(a1[q]);
    }
}

// post-matvec scalar chain. Inputs: raw M (m0,m1), carried scale c (true x = c*u),
// xn (true clamped input norm), ratio = atanh(xn)/xn. Produces broadcast coeffs
// AA,BB such that true output (logmap0 of proj(mobius_add)) = AA*M + BB*e.
// with_sl=false omits the final logmap scale (kernel C output layer).
__device__ __forceinline__ void layer_post(
    const float m0[8], const float m1[8], float c, float ratio,
    float2 ev, float ebn2, bool with_sl, float AA[8], float BB[8], int j) {
    float s2[8], d[8];
#pragma unroll
    for (int q = 0; q < 8; q++) {
        s2[q] = m0[q] * m0[q] + m1[q] * m1[q];
        d[q] = m0[q] * ev.x + m1[q] * ev.y;
    }
    float s2s = rsum8(s2, j);
    float ds = rsum8(d, j);
    float ml = c * sqrtf(s2s);
    float mx = fmaxf(ml, MINN);
    float r = fast_tanh(mx * ratio);
    float sc = c * __fdividef(r, mx);          // applies to raw M
    float n1 = fmaxf(r * __fdividef(ml, mx), MINN);
    if (n1 > MAXN) { sc *= __fdividef(MAXN, n1); n1 = MAXN; }
    float xyv = sc * ds;
    float x2 = n1 * n1;
    float c1 = 1.f + 2.f * xyv + ebn2;
    float c2 = 1.f - x2;
    float iv = __fdividef(1.f, fmaxf(1.f + 2.f * xyv + x2 * ebn2, MINN));
    float q2v = iv * iv * (c1 * c1 * x2 + 2.f * c1 * c2 * xyv + c2 * c2 * ebn2);
    float nf = fmaxf(sqrtf(q2v), MINN);
    float ps = 1.f;
    if (nf > MAXN) { ps = __fdividef(MAXN, nf); nf = MAXN; }
    float sl = with_sl ? __fdividef(fast_atanh(nf), nf) : 1.f;
    float A = ps * iv * c1 * sc * sl;
    float B = ps * iv * c2 * sl;
    bcast8(A, AA);
    bcast8(B, BB);
}

// act prelude for the NEXT layer: from t2 partials of staged unscaled u,
// compute carried scale c (= expmap+proj scale), xn, ratio. Sits before the
// next fma block so its shfl/MUFU latency hides under FMA issue.
__device__ __forceinline__ void act_pre(const float t2[8], int j,
                                        float& c, float& ratio) {
    float t2s = rsum8(t2, j);
    float tn = sqrtf(t2s);
    float tc = fmaxf(tn, MINN);
    float se = __fdividef(fast_tanh(tc), tc);
    float nn = fmaxf(se * tn, MINN);
    if (nn > MAXN) { se *= __fdividef(MAXN, nn); nn = MAXN; }
    c = se;
    ratio = __fdividef(fast_atanh(nn), nn);
}

// relu(A*M + B*e) -> u (unscaled), t2 partials, stage
__device__ __forceinline__ void relu_stage(const float m0[8], const float m1[8],
                                           const float AA[8], const float BB[8],
                                           float2 ev, ull* xs, int j,
                                           float h0[8], float h1[8], float t2[8]) {
#pragma unroll
    for (int q = 0; q < 8; q++) {
        float u0 = fmaxf(AA[q] * m0[q] + BB[q] * ev.x, 0.f);
        float u1 = fmaxf(AA[q] * m1[q] + BB[q] * ev.y, 0.f);
        h0[q] = u0; h1[q] = u1;
        t2[q] = u0 * u0 + u1 * u1;
    }
    stage_x8(xs, h0, h1, j);
}

// bias -> eb = expmap0(b), |eb|^2, one warp
__device__ __forceinline__ void compute_eb64(const float* __restrict__ b,
                                             float* eb, float* ebn2, int j) {
    float v0 = b[j], v1 = b[32 + j];
    float s2 = v0 * v0 + v1 * v1;
#pragma unroll
    for (int o = 16; o > 0; o >>= 1) s2 += __shfl_xor_sync(0xffffffffu, s2, o);
    float bn = sqrtf(s2), bc = fmaxf(bn, MINN);
    float se = __fdividef(fast_tanh(bc), bc);
    eb[j] = v0 * se;
    eb[32 + j] = v1 * se;
    if (j == 0) *ebn2 = (se * bn) * (se * bn);
}

// CSR gather for one node; lane j sums comps (2j,2j+1) via float2
__device__ __forceinline__ void csr_agg(const float* __restrict__ tsrc, int node,
                                        int j, float& o0, float& o1, int& deg) {
    int s = g_off[node], e = g_off[node + 1];
    deg = e - s;
    float a0 = 0.f, a1 = 0.f, b0 = 0.f, b1 = 0.f;
    for (int base = s; base < e; base += 32) {
        int nh = min(32, e - base);
        int idx = (j < nh) ? g_col[base + j] : 0;
        int t = 0;
        for (; t + 8 <= nh; t += 8) {
#pragma unroll
            for (int u = 0; u < 8; u += 2) {
                int sa = __shfl_sync(0xffffffffu, idx, t + u);
                int sb = __shfl_sync(0xffffffffu, idx, t + u + 1);
                float2 va = __ldg((const float2*)(tsrc + (size_t)sa * 64) + j);
                float2 vb = __ldg((const float2*)(tsrc + (size_t)sb * 64) + j);
                a0 += va.x; a1 += va.y;
                b0 += vb.x; b1 += vb.y;
            }
        }
        for (; t < nh; t++) {
            int sx = __shfl_sync(0xffffffffu, idx, t);
            float2 v = __ldg((const float2*)(tsrc + (size_t)sx * 64) + j);
            a0 += v.x; a1 += v.y;
        }
    }
    o0 = a0 + b0; o1 = a1 + b1;
}

// agg mean + (expmap0,proj,logmap0 folded) + relu -> unscaled u staged + t2
__device__ __forceinline__ void agg_relu_stage(const float* __restrict__ tsrc,
                                               int iBase, int j, ull* xs,
                                               float h0[8], float h1[8],
                                               float t2[8]) {
    float n2[8];
#pragma unroll
    for (int q = 0; q < 8; q++) {
        int node = min(iBase + q, NN - 1);
        int deg;
        float a0, a1;
        csr_agg(tsrc, node, j, a0, a1, deg);
        float inv = __fdividef(1.f, fmaxf((float)deg, 1.f));
        h0[q] = a0 * inv;
        h1[q] = a1 * inv;
        n2[q] = h0[q] * h0[q] + h1[q] * h1[q];
    }
    float n2s = rsum8(n2, j);
    float un = sqrtf(n2s);
    float uc = fmaxf(un, MINN);
    float se = __fdividef(fast_tanh(uc), uc);
    float nn = fmaxf(se * un, MINN);
    if (nn > MAXN) { se *= __fdividef(MAXN, nn); nn = MAXN; }
    float comb = se * __fdividef(fast_atanh(nn), nn);
    float CB[8];
    bcast8(comb, CB);
#pragma unroll
    for (int q = 0; q < 8; q++) {
        float u0 = fmaxf(h0[q] * CB[q], 0.f);
        float u1 = fmaxf(h1[q] * CB[q], 0.f);
        h0[q] = u0; h1[q] = u1;
        t2[q] = u0 * u0 + u1 * u1;
    }
    stage_x8(xs, h0, h1, j);
}

// load weights: Wq[t*32+j] = {pack2(W[2j][2t],W[2j][2t+1]), pack2(W[2j+1][2t],W[2j+1][2t+1])}
__device__ __forceinline__ void load_Wq(ulonglong2* Wq, const float* __restrict__ W,
                                        int K, int tid) {
    for (int i = tid; i < 1024; i += 256) {
        int t = i >> 5, jj = i & 31;
        int k0 = 2 * t, k1 = 2 * t + 1;
        int r0 = 2 * jj, r1 = 2 * jj + 1;
        float w00 = W[r0 * K + k0];
        float w01 = (k1 < K) ? W[r0 * K + k1] : 0.f;
        float w10 = W[r1 * K + k0];
        float w11 = (k1 < K) ? W[r1 * K + k1] : 0.f;
        ulonglong2 v;
        v.x = pack2(w00, w01);
        v.y = pack2(w10, w11);
        Wq[t * 32 + jj] = v;
    }
}

// ---------------- kernel A: poincare + layers 1..4 + logmap -> g_t ----------
__global__ void __launch_bounds__(256, 2) nodeA_kernel(
    const float* __restrict__ x,
    const float* __restrict__ W1, const float* __restrict__ b1,
    const float* __restrict__ W2, const float* __restrict__ b2,
    const float* __restrict__ W3, const float* __restrict__ b3,
    const float* __restrict__ W4, const float* __restrict__ b4) {
    extern __shared__ unsigned char smem_raw[];
    ulonglong2* Wq = (ulonglong2*)smem_raw;      // 64KB
    ull* xall = (ull*)(Wq + 4 * 1024);           // 8 * 320 ull
    float* eb = (float*)(xall + 8 * 320);
    float* ebn2 = eb + 256;
    int tid = threadIdx.x;

    load_Wq(Wq,        W1, 63, tid);
    load_Wq(Wq + 1024, W2, 64, tid);
    load_Wq(Wq + 2048, W3, 64, tid);
    load_Wq(Wq + 3072, W4, 64, tid);
    int w = tid >> 5, j = tid & 31;
    if (w < 4) {
        const float* bp[4] = {b1, b2, b3, b4};
        compute_eb64(bp[w], eb + w * 64, ebn2 + w, j);
    }
    __syncthreads();

    int iBase = blockIdx.x * 64 + w * 8;
    ull* xs = xall + w * 320;
    float h0[8], h1[8], t2[8], m0[8], m1[8], AA[8], BB[8];
    float c, ratio;

    // poincare map (raw; proj scale deferred into c)
    {
        float n2[8];
#pragma unroll
        for (int q = 0; q < 8; q++) {
            const float* xp = x + (size_t)min(iBase + q, NN - 1) * 64;
            float inv = __fdividef(1.f, xp[0] + 1.f);
            h0[q] = xp[1 + 2 * j] * inv;
            h1[q] = (j < 31) ? xp[2 + 2 * j] * inv : 0.f;
            n2[q] = h0[q] * h0[q] + h1[q] * h1[q];
        }
        stage_x8(xs, h0, h1, j);
        float n2s = rsum8(n2, j);
        float nf = fmaxf(sqrtf(n2s), MINN);
        float ps = 1.f;
        if (nf > MAXN) { ps = __fdividef(MAXN, nf); nf = MAXN; }
        c = ps;
        ratio = __fdividef(fast_atanh(nf), nf);
    }

    float2 ev;
    // layer 1 (act)
    ev = *(const float2*)(eb + 2 * j);
    fma_block64(Wq, xs, j, m0, m1);
    layer_post(m0, m1, c, ratio, ev, ebn2[0], true, AA, BB, j);
    relu_stage(m0, m1, AA, BB, ev, xs, j, h0, h1, t2);
    act_pre(t2, j, c, ratio);
    // layer 2 (act)
    ev = *(const float2*)(eb + 64 + 2 * j);
    fma_block64(Wq + 1024, xs, j, m0, m1);
    layer_post(m0, m1, c, ratio, ev, ebn2[1], true, AA, BB, j);
    relu_stage(m0, m1, AA, BB, ev, xs, j, h0, h1, t2);
    act_pre(t2, j, c, ratio);
    // layer 3 (act)
    ev = *(const float2*)(eb + 128 + 2 * j);
    fma_block64(Wq + 2048, xs, j, m0, m1);
    layer_post(m0, m1, c, ratio, ev, ebn2[2], true, AA, BB, j);
    relu_stage(m0, m1, AA, BB, ev, xs, j, h0, h1, t2);
    act_pre(t2, j, c, ratio);
    // layer 4 (logmap out)
    ev = *(const float2*)(eb + 192 + 2 * j);
    fma_block64(Wq + 3072, xs, j, m0, m1);
    layer_post(m0, m1, c, ratio, ev, ebn2[3], true, AA, BB, j);
#pragma unroll
    for (int q = 0; q < 8; q++) {
        if (iBase + q < NN) {
            float2 v = make_float2(AA[q] * m0[q] + BB[q] * ev.x,
                                   AA[q] * m1[q] + BB[q] * ev.y);
            *((float2*)(g_t + (size_t)(iBase + q) * 64) + j) = v;
        }
    }
}

// ---------------- kernel B: agg(g_t)+act + layer5(logmap) -> g_t2 -----------
__global__ void __launch_bounds__(256, 2) nodeB_kernel(
    const float* __restrict__ W5, const float* __restrict__ b5) {
    extern __shared__ unsigned char smem_raw[];
    ulonglong2* Wq = (ulonglong2*)smem_raw;
    ull* xall = (ull*)(Wq + 1024);
    float* eb = (float*)(xall + 8 * 320);
    float* ebn2 = eb + 64;
    int tid = threadIdx.x;
    load_Wq(Wq, W5, 64, tid);
    int w = tid >> 5, j = tid & 31;
    if (w == 0) compute_eb64(b5, eb, ebn2, j);
    __syncthreads();

    int iBase = blockIdx.x * 64 + w * 8;
    ull* xs = xall + w * 320;
    float h0[8], h1[8], t2[8], m0[8], m1[8], AA[8], BB[8];
    float c, ratio;
    agg_relu_stage(g_t, iBase, j, xs, h0, h1, t2);
    act_pre(t2, j, c, ratio);
    float2 ev = *(const float2*)(eb + 2 * j);
    fma_block64(Wq, xs, j, m0, m1);
    layer_post(m0, m1, c, ratio, ev, ebn2[0], true, AA, BB, j);
#pragma unroll
    for (int q = 0; q < 8; q++) {
        if (iBase + q < NN) {
            float2 v = make_float2(AA[q] * m0[q] + BB[q] * ev.x,
                                   AA[q] * m1[q] + BB[q] * ev.y);
            *((float2*)(g_t2 + (size_t)(iBase + q) * 64) + j) = v;
        }
    }
}

// ---------------- kernel C: agg(g_t2)+act + layer6 -> out -------------------
__global__ void __launch_bounds__(256, 2) nodeC_kernel(
    const float* __restrict__ W6, const float* __restrict__ b6,
    float* __restrict__ out) {
    extern __shared__ unsigned char smem_raw[];
    ull* W6q = (ull*)smem_raw;
    ull* xall = W6q + 1024;
    float* eb = (float*)(xall + 8 * 320);
    float* ebn2 = eb + 32;
    int tid = threadIdx.x;
    for (int i = tid; i < 1024; i += 256) {
        int t = i >> 5, jj = i & 31;
        W6q[t * 32 + jj] = pack2(W6[jj * 64 + 2 * t], W6[jj * 64 + 2 * t + 1]);
    }
    int w = tid >> 5, j = tid & 31;
    if (w == 0) {
        float v0 = b6[j];
        float s2 = v0 * v0;
#pragma unroll
        for (int o = 16; o > 0; o >>= 1) s2 += __shfl_xor_sync(0xffffffffu, s2, o);
        float bn = sqrtf(s2), bc = fmaxf(bn, MINN);
        float se = __fdividef(fast_tanh(bc), bc);
        eb[j] = v0 * se;
        if (j == 0) *ebn2 = (se * bn) * (se * bn);
    }
    __syncthreads();

    int iBase = blockIdx.x * 64 + w * 8;
    ull* xs = xall + w * 320;
    float h0[8], h1[8], t2[8], AA[8], BB[8];
    float c, ratio;
    agg_relu_stage(g_t2, iBase, j, xs, h0, h1, t2);
    act_pre(t2, j, c, ratio);
    float e0 = eb[j];
    // 64->32 matvec (single output comp per lane)
    float m[8];
    {
        ull a[8] = {0, 0, 0, 0, 0, 0, 0, 0};
#pragma unroll
        for (int t = 0; t < 32; t++) {
            ull wv = W6q[t * 32 + j];
            const ulonglong2* xt = (const ulonglong2*)(xs + t * 10);
            ulonglong2 xA = xt[0], xB = xt[1], xC = xt[2], xD = xt[3];
            fma2(a[0], xA.x, wv); fma2(a[1], xA.y, wv);
            fma2(a[2], xB.x, wv); fma2(a[3], xB.y, wv);
            fma2(a[4], xC.x, wv); fma2(a[5], xC.y, wv);
            fma2(a[6], xD.x, wv); fma2(a[7], xD.y, wv);
        }
#pragma unroll
        for (int q = 0; q < 8; q++) m[q] = pairsum(a[q]);
    }
    {
        float s2[8], d[8];
#pragma unroll
        for (int q = 0; q < 8; q++) { s2[q] = m[q] * m[q]; d[q] = m[q] * e0; }
        float s2s = rsum8(s2, j);
        float ds = rsum8(d, j);
        float ml = c * sqrtf(s2s);
        float mx = fmaxf(ml, MINN);
        float r = fast_tanh(mx * ratio);
        float sc = c * __fdividef(r, mx);
        float n1 = fmaxf(r * __fdividef(ml, mx), MINN);
        if (n1 > MAXN) { sc *= __fdividef(MAXN, n1); n1 = MAXN; }
        float xyv = sc * ds;
        float x2 = n1 * n1;
        float c1 = 1.f + 2.f * xyv + ebn2[0];
        float c2 = 1.f - x2;
        float iv = __fdividef(1.f, fmaxf(1.f + 2.f * xyv + x2 * ebn2[0], MINN));
        float q2v = iv * iv * (c1 * c1 * x2 + 2.f * c1 * c2 * xyv + c2 * c2 * ebn2[0]);
        float nf = fmaxf(sqrtf(q2v), MINN);
        float ps = 1.f;
        if (nf > MAXN) ps = __fdividef(MAXN, nf);
        float A = ps * iv * c1 * sc;
        float B = ps * iv * c2;
        bcast8(A, AA);
        bcast8(B, BB);
    }
#pragma unroll
    for (int q = 0; q < 8; q++)
        if (iBase + q < NN) out[(size_t)(iBase + q) * 32 + j] = AA[q] * m[q] + BB[q] * e0;
}

// ---------------- CSR build ----------------
__global__ void __launch_bounds__(1024) detect_zero_kernel(const int* __restrict__ e32) {
    int i = blockIdx.x * 1024 + threadIdx.x;
    if (i < NN) g_cnt[i] = 0;
    if (blockIdx.x == 0) {
        __shared__ int nz;
        if (threadIdx.x == 0) { nz = 0; g_scan_done = 0; }
        __syncthreads();
        if (e32[2 * threadIdx.x + 1] != 0) atomicAdd(&nz, 1);
        __syncthreads();
        if (threadIdx.x == 0) g_idx64 = (nz == 0) ? 1 : 0;
    }
}

__global__ void __launch_bounds__(256) hist_kernel(const void* __restrict__ edges) {
    int i = blockIdx.x * 256 + threadIdx.x;
    if (i >= EE) return;
    int d = g_idx64 ? (int)__ldg((const long long*)edges + EE + i)
                    : __ldg((const int*)edges + EE + i);
    atomicAdd(&g_cnt[d], 1);
}

__global__ void __launch_bounds__(1024) scan_kernel() {
    __shared__ int sm[1024];
    __shared__ int base_s;
    int gi = blockIdx.x * 1024 + threadIdx.x;
    int v = (gi < NN) ? g_cnt[gi] : 0;
    sm[threadIdx.x] = v;
    __syncthreads();
#pragma unroll
    for (int o = 1; o < 1024; o <<= 1) {
        int t = (threadIdx.x >= o) ? sm[threadIdx.x - o] : 0;
        __syncthreads();
        sm[threadIdx.x] += t;
        __syncthreads();
    }
    int incl = sm[threadIdx.x];
    int excl = incl - v;
    if (threadIdx.x == 1023) {
        g_bsum[blockIdx.x] = incl;
        __threadfence();
        atomicAdd(&g_scan_done, 1);
    }
    if (threadIdx.x == 0) {
        while (*(volatile int*)&g_scan_done < SCAN_BLOCKS) {}
        __threadfence();
    }
    __syncthreads();
    if (threadIdx.x < 32) {
        int acc = 0;
        for (int i = (int)threadIdx.x; i < SCAN_BLOCKS; i += 32)
            if (i < (int)blockIdx.x) acc += g_bsum[i];
#pragma unroll
        for (int o = 16; o > 0; o >>= 1) acc += __shfl_xor_sync(0xffffffffu, acc, o);
        if (threadIdx.x == 0) base_s = acc;
    }
    __syncthreads();
    if (gi < NN) {
        int o = excl + base_s;
        g_off[gi] = o;
        g_cursor[gi] = o;
    }
    if (gi == 0) g_off[NN] = EE;
}

__global__ void __launch_bounds__(256) fill_kernel(const void* __restrict__ edges) {
    int i = blockIdx.x * 256 + threadIdx.x;
    if (i >= EE) return;
    int sV, dV;
    if (g_idx64) {
        sV = (int)__ldg((const long long*)edges + i);
        dV = (int)__ldg((const long long*)edges + EE + i);
    } else {
        sV = __ldg((const int*)edges + i);
        dV = __ldg((const int*)edges + EE + i);
    }
    int pos = atomicAdd(&g_cursor[dV], 1);
    g_col[pos] = sV;
}

// ---------------- launch ----------------
extern "C" void kernel_launch(void* const* d_in, const int* in_sizes, int n_in,
                              void* d_out, int out_size) {
    const float* x = (const float*)d_in[0];
    const float* W1 = (const float*)d_in[1];
    const float* b1 = (const float*)d_in[2];
    const float* W2 = (const float*)d_in[3];
    const float* b2 = (const float*)d_in[4];
    const float* W3 = (const float*)d_in[5];
    const float* b3 = (const float*)d_in[6];
    const float* W4 = (const float*)d_in[7];
    const float* b4 = (const float*)d_in[8];
    const float* W5 = (const float*)d_in[9];
    const float* b5 = (const float*)d_in[10];
    const float* W6 = (const float*)d_in[11];
    const float* b6 = (const float*)d_in[12];
    const void* edges = d_in[13];
    float* out = (float*)d_out;

    const int SMEM_A = 4 * 1024 * 16 + 8 * 320 * 8 + 256 * 4 + 16;
    const int SMEM_B = 1024 * 16 + 8 * 320 * 8 + 64 * 4 + 16;
    const int SMEM_C = 1024 * 8 + 8 * 320 * 8 + 32 * 4 + 16;

    cudaFuncSetAttribute(nodeA_kernel, cudaFuncAttributeMaxDynamicSharedMemorySize, SMEM_A);
    cudaFuncSetAttribute(nodeB_kernel, cudaFuncAttributeMaxDynamicSharedMemorySize, SMEM_B);
    cudaFuncSetAttribute(nodeC_kernel, cudaFuncAttributeMaxDynamicSharedMemorySize, SMEM_C);

    const int EDGE_BLOCKS = (EE + 255) / 256;

    cudaStream_t s2;
    cudaEvent_t ev0, evA;
    bool forked = (cudaStreamCreateWithFlags(&s2, cudaStreamNonBlocking) == cudaSuccess);
    if (forked) forked = (cudaEventCreateWithFlags(&ev0, cudaEventDisableTiming) == cudaSuccess);
    if (forked) forked = (cudaEventCreateWithFlags(&evA, cudaEventDisableTiming) == cudaSuccess);

    if (forked) {
        cudaEventRecord(ev0, 0);
        cudaStreamWaitEvent(s2, ev0, 0);
        nodeA_kernel<<<NODE_BLOCKS, 256, SMEM_A, s2>>>(x, W1, b1, W2, b2, W3, b3, W4, b4);
        cudaEventRecord(evA, s2);

        detect_zero_kernel<<<SCAN_BLOCKS, 1024>>>((const int*)edges);
        hist_kernel<<<EDGE_BLOCKS, 256>>>(edges);
        scan_kernel<<<SCAN_BLOCKS, 1024>>>();
        fill_kernel<<<EDGE_BLOCKS, 256>>>(edges);

        cudaStreamWaitEvent(0, evA, 0);
    } else {
        detect_zero_kernel<<<SCAN_BLOCKS, 1024>>>((const int*)edges);
        hist_kernel<<<EDGE_BLOCKS, 256>>>(edges);
        scan_kernel<<<SCAN_BLOCKS, 1024>>>();
        fill_kernel<<<EDGE_BLOCKS, 256>>>(edges);
        nodeA_kernel<<<NODE_BLOCKS, 256, SMEM_A>>>(x, W1, b1, W2, b2, W3, b3, W4, b4);
    }

    nodeB_kernel<<<NODE_BLOCKS, 256, SMEM_B>>>(W5, b5);
    nodeC_kernel<<<NODE_BLOCKS, 256, SMEM_C>>>(W6, b6, out);
}

// round 9
// speedup vs baseline: 2.1189x; 1.0113x over previous
#include <cuda_runtime.h>
#include <cstdint>

#define NN 100000
#define EE 1600000
#define MINN 1e-15f
#define MAXN ((float)(1.0 - 1e-5))
#define SCAN_BLOCKS 98
#define NODE_BLOCKS ((NN + 63) / 64)   // 64 nodes per block (8 per warp)

typedef unsigned long long ull;

// ---------------- scratch ----------------
__device__ __align__(16) float g_t[(size_t)NN * 64];
__device__ __align__(16) float g_t2[(size_t)NN * 64];
__device__ int g_col[EE];
__device__ int g_cnt[NN];          // zero at load; re-zeroed by nodeC tail
__device__ int g_off[NN + 1];
__device__ int g_cursor[NN];
__device__ int g_bsum[SCAN_BLOCKS];
__device__ int g_scan_done;        // zero at load; reset by nodeC tail
__device__ int g_idx64;

// ---------------- packed f32x2 ----------------
__device__ __forceinline__ ull pack2(float lo, float hi) {
    ull r;
    asm("mov.b64 %0, {%1, %2};" : "=l"(r) : "f"(lo), "f"(hi));
    return r;
}
__device__ __forceinline__ void fma2(ull& d, ull a, ull b) {
    asm("fma.rn.f32x2 %0, %1, %2, %0;" : "+l"(d) : "l"(a), "l"(b));
}
__device__ __forceinline__ float pairsum(ull v) {
    float lo, hi;
    asm("mov.b64 {%0, %1}, %2;" : "=f"(lo), "=f"(hi) : "l"(v));
    return lo + hi;
}

// ---------------- fast math (args nonnegative) ----------------
__device__ __forceinline__ float fast_tanh(float x) {
    float e = __expf(-2.f * x);
    return __fdividef(1.f - e, 1.f + e);
}
__device__ __forceinline__ float fast_atanh(float x) {
    x = fminf(x, MAXN);
    return 0.5f * __logf(__fdividef(1.f + x, 1.f - x));
}

// reduce v[8] across warp -> lane j gets total of slot (j&7). 9 SHFL, depth 5.
__device__ __forceinline__ float rsum8(const float v[8], int j) {
    bool p1 = j & 1;
    float a[4];
#pragma unroll
    for (int i = 0; i < 4; i++) {
        float m = p1 ? v[2 * i + 1] : v[2 * i];
        float o = p1 ? v[2 * i] : v[2 * i + 1];
        a[i] = m + __shfl_xor_sync(0xffffffffu, o, 1);
    }
    bool p2 = j & 2;
    float b0, b1;
    {
        float m = p2 ? a[1] : a[0], o = p2 ? a[0] : a[1];
        b0 = m + __shfl_xor_sync(0xffffffffu, o, 2);
    }
    {
        float m = p2 ? a[3] : a[2], o = p2 ? a[2] : a[3];
        b1 = m + __shfl_xor_sync(0xffffffffu, o, 2);
    }
    bool p4 = j & 4;
    float m = p4 ? b1 : b0, o = p4 ? b0 : b1;
    float c = m + __shfl_xor_sync(0xffffffffu, o, 4);
    c += __shfl_xor_sync(0xffffffffu, c, 8);
    c += __shfl_xor_sync(0xffffffffu, c, 16);
    return c;
}

// two independent rsum8's interleaved (half the exposed shfl-chain depth)
__device__ __forceinline__ void rsum8x2(const float va[8], const float vb[8],
                                        int j, float& ra, float& rb) {
    bool p1 = j & 1;
    float A[4], B[4];
#pragma unroll
    for (int i = 0; i < 4; i++) {
        float am = p1 ? va[2 * i + 1] : va[2 * i];
        float ao = p1 ? va[2 * i] : va[2 * i + 1];
        float bm = p1 ? vb[2 * i + 1] : vb[2 * i];
        float bo = p1 ? vb[2 * i] : vb[2 * i + 1];
        A[i] = am + __shfl_xor_sync(0xffffffffu, ao, 1);
        B[i] = bm + __shfl_xor_sync(0xffffffffu, bo, 1);
    }
    bool p2 = j & 2;
    float a0, a1, b0, b1;
    { float m = p2 ? A[1] : A[0], o = p2 ? A[0] : A[1]; a0 = m + __shfl_xor_sync(0xffffffffu, o, 2); }
    { float m = p2 ? B[1] : B[0], o = p2 ? B[0] : B[1]; b0 = m + __shfl_xor_sync(0xffffffffu, o, 2); }
    { float m = p2 ? A[3] : A[2], o = p2 ? A[2] : A[3]; a1 = m + __shfl_xor_sync(0xffffffffu, o, 2); }
    { float m = p2 ? B[3] : B[2], o = p2 ? B[2] : B[3]; b1 = m + __shfl_xor_sync(0xffffffffu, o, 2); }
    bool p4 = j & 4;
    { float m = p4 ? a1 : a0, o = p4 ? a0 : a1; ra = m + __shfl_xor_sync(0xffffffffu, o, 4); }
    { float m = p4 ? b1 : b0, o = p4 ? b0 : b1; rb = m + __shfl_xor_sync(0xffffffffu, o, 4); }
    ra += __shfl_xor_sync(0xffffffffu, ra, 8);
    rb += __shfl_xor_sync(0xffffffffu, rb, 8);
    ra += __shfl_xor_sync(0xffffffffu, ra, 16);
    rb += __shfl_xor_sync(0xffffffffu, rb, 16);
}

__device__ __forceinline__ void bcast8(float v, float o[8]) {
#pragma unroll
    for (int q = 0; q < 8; q++) o[q] = __shfl_sync(0xffffffffu, v, q);
}

// stage 8 nodes: xs[j*10 + q] = pack2(h0[q], h1[q]) (80B padded rows)
__device__ __forceinline__ void stage_x8(ull* xs, const float h0[8],
                                         const float h1[8], int j) {
    __syncwarp();
#pragma unroll
    for (int q = 0; q < 8; q++) xs[j * 10 + q] = pack2(h0[q], h1[q]);
    __syncwarp();
}

// 64x64 matvec block: raw M for 8 nodes. Lane j owns comps (2j,2j+1).
__device__ __forceinline__ void fma_block64(const ulonglong2* __restrict__ Wq,
                                            const ull* xs, int j,
                                            float m0[8], float m1[8]) {
    ull a0[8] = {0, 0, 0, 0, 0, 0, 0, 0}, a1[8] = {0, 0, 0, 0, 0, 0, 0, 0};
#pragma unroll
    for (int t = 0; t < 32; t++) {
        ulonglong2 wv = Wq[t * 32 + j];
        const ulonglong2* xt = (const ulonglong2*)(xs + t * 10);
        ulonglong2 xA = xt[0], xB = xt[1], xC = xt[2], xD = xt[3];
        fma2(a0[0], xA.x, wv.x); fma2(a1[0], xA.x, wv.y);
        fma2(a0[1], xA.y, wv.x); fma2(a1[1], xA.y, wv.y);
        fma2(a0[2], xB.x, wv.x); fma2(a1[2], xB.x, wv.y);
        fma2(a0[3], xB.y, wv.x); fma2(a1[3], xB.y, wv.y);
        fma2(a0[4], xC.x, wv.x); fma2(a1[4], xC.x, wv.y);
        fma2(a0[5], xC.y, wv.x); fma2(a1[5], xC.y, wv.y);
        fma2(a0[6], xD.x, wv.x); fma2(a1[6], xD.x, wv.y);
        fma2(a0[7], xD.y, wv.x); fma2(a1[7], xD.y, wv.y);
    }
#pragma unroll
    for (int q = 0; q < 8; q++) {
        m0[q] = pairsum(a0[q]);
        m1[q] = pairsum(a1[q]);
    }
}

// post-matvec scalar chain -> broadcast coeffs AA,BB (out = AA*M + BB*e).
__device__ __forceinline__ void layer_post(
    const float m0[8], const float m1[8], float c, float ratio,
    float2 ev, float ebn2, bool with_sl, float AA[8], float BB[8], int j) {
    float s2[8], d[8];
#pragma unroll
    for (int q = 0; q < 8; q++) {
        s2[q] = m0[q] * m0[q] + m1[q] * m1[q];
        d[q] = m0[q] * ev.x + m1[q] * ev.y;
    }
    float s2s, ds;
    rsum8x2(s2, d, j, s2s, ds);
    float ml = c * sqrtf(s2s);
    float mx = fmaxf(ml, MINN);
    float r = fast_tanh(mx * ratio);
    float sc = c * __fdividef(r, mx);          // applies to raw M
    float n1 = fmaxf(r * __fdividef(ml, mx), MINN);
    if (n1 > MAXN) { sc *= __fdividef(MAXN, n1); n1 = MAXN; }
    float xyv = sc * ds;
    float x2 = n1 * n1;
    float c1 = 1.f + 2.f * xyv + ebn2;
    float c2 = 1.f - x2;
    float iv = __fdividef(1.f, fmaxf(1.f + 2.f * xyv + x2 * ebn2, MINN));
    float q2v = iv * iv * (c1 * c1 * x2 + 2.f * c1 * c2 * xyv + c2 * c2 * ebn2);
    float nf = fmaxf(sqrtf(q2v), MINN);
    float ps = 1.f;
    if (nf > MAXN) { ps = __fdividef(MAXN, nf); nf = MAXN; }
    float sl = with_sl ? __fdividef(fast_atanh(nf), nf) : 1.f;
    float A = ps * iv * c1 * sc * sl;
    float B = ps * iv * c2 * sl;
    bcast8(A, AA);
    bcast8(B, BB);
}

// act prelude for the NEXT layer from staged-u t2 partials.
__device__ __forceinline__ void act_pre(const float t2[8], int j,
                                        float& c, float& ratio) {
    float t2s = rsum8(t2, j);
    float tn = sqrtf(t2s);
    float tc = fmaxf(tn, MINN);
    float se = __fdividef(fast_tanh(tc), tc);
    float nn = fmaxf(se * tn, MINN);
    if (nn > MAXN) { se *= __fdividef(MAXN, nn); nn = MAXN; }
    c = se;
    ratio = __fdividef(fast_atanh(nn), nn);
}

// relu(A*M + B*e) -> unscaled u staged + t2 partials
__device__ __forceinline__ void relu_stage(const float m0[8], const float m1[8],
                                           const float AA[8], const float BB[8],
                                           float2 ev, ull* xs, int j, float t2[8]) {
    __syncwarp();
#pragma unroll
    for (int q = 0; q < 8; q++) {
        float u0 = fmaxf(AA[q] * m0[q] + BB[q] * ev.x, 0.f);
        float u1 = fmaxf(AA[q] * m1[q] + BB[q] * ev.y, 0.f);
        t2[q] = u0 * u0 + u1 * u1;
        xs[j * 10 + q] = pack2(u0, u1);
    }
    __syncwarp();
}

// bias -> eb = expmap0(b), |eb|^2, one warp
__device__ __forceinline__ void compute_eb64(const float* __restrict__ b,
                                             float* eb, float* ebn2, int j) {
    float v0 = b[j], v1 = b[32 + j];
    float s2 = v0 * v0 + v1 * v1;
#pragma unroll
    for (int o = 16; o > 0; o >>= 1) s2 += __shfl_xor_sync(0xffffffffu, s2, o);
    float bn = sqrtf(s2), bc = fmaxf(bn, MINN);
    float se = __fdividef(fast_tanh(bc), bc);
    eb[j] = v0 * se;
    eb[32 + j] = v1 * se;
    if (j == 0) *ebn2 = (se * bn) * (se * bn);
}

// CSR gather for one node; lane j sums comps (2j,2j+1) via float2
__device__ __forceinline__ void csr_agg(const float* __restrict__ tsrc, int node,
                                        int j, float& o0, float& o1, int& deg) {
    int s = g_off[node], e = g_off[node + 1];
    deg = e - s;
    float a0 = 0.f, a1 = 0.f, b0 = 0.f, b1 = 0.f;
    for (int base = s; base < e; base += 32) {
        int nh = min(32, e - base);
        int idx = (j < nh) ? g_col[base + j] : 0;
        int t = 0;
        for (; t + 8 <= nh; t += 8) {
#pragma unroll
            for (int u = 0; u < 8; u += 2) {
                int sa = __shfl_sync(0xffffffffu, idx, t + u);
                int sb = __shfl_sync(0xffffffffu, idx, t + u + 1);
                float2 va = __ldg((const float2*)(tsrc + (size_t)sa * 64) + j);
                float2 vb = __ldg((const float2*)(tsrc + (size_t)sb * 64) + j);
                a0 += va.x; a1 += va.y;
                b0 += vb.x; b1 += vb.y;
            }
        }
        for (; t < nh; t++) {
            int sx = __shfl_sync(0xffffffffu, idx, t);
            float2 v = __ldg((const float2*)(tsrc + (size_t)sx * 64) + j);
            a0 += v.x; a1 += v.y;
        }
    }
    o0 = a0 + b0; o1 = a1 + b1;
}

// agg mean + (expmap0,proj,logmap0 folded) + relu -> unscaled u staged + t2
__device__ __forceinline__ void agg_relu_stage(const float* __restrict__ tsrc,
                                               int iBase, int j, ull* xs,
                                               float t2[8]) {
    float h0[8], h1[8], n2[8];
#pragma unroll
    for (int q = 0; q < 8; q++) {
        int node = min(iBase + q, NN - 1);
        int deg;
        float a0, a1;
        csr_agg(tsrc, node, j, a0, a1, deg);
        float inv = __fdividef(1.f, fmaxf((float)deg, 1.f));
        h0[q] = a0 * inv;
        h1[q] = a1 * inv;
        n2[q] = h0[q] * h0[q] + h1[q] * h1[q];
    }
    float n2s = rsum8(n2, j);
    float un = sqrtf(n2s);
    float uc = fmaxf(un, MINN);
    float se = __fdividef(fast_tanh(uc), uc);
    float nn = fmaxf(se * un, MINN);
    if (nn > MAXN) { se *= __fdividef(MAXN, nn); nn = MAXN; }
    float comb = se * __fdividef(fast_atanh(nn), nn);
    float CB[8];
    bcast8(comb, CB);
    __syncwarp();
#pragma unroll
    for (int q = 0; q < 8; q++) {
        float u0 = fmaxf(h0[q] * CB[q], 0.f);
        float u1 = fmaxf(h1[q] * CB[q], 0.f);
        t2[q] = u0 * u0 + u1 * u1;
        xs[j * 10 + q] = pack2(u0, u1);
    }
    __syncwarp();
}

// load weights: Wq[t*32+j] = {pack2(W[2j][2t],W[2j][2t+1]), pack2(W[2j+1][2t],W[2j+1][2t+1])}
__device__ __forceinline__ void load_Wq(ulonglong2* Wq, const float* __restrict__ W,
                                        int K, int tid) {
    for (int i = tid; i < 1024; i += 256) {
        int t = i >> 5, jj = i & 31;
        int k0 = 2 * t, k1 = 2 * t + 1;
        int r0 = 2 * jj, r1 = 2 * jj + 1;
        float w00 = W[r0 * K + k0];
        float w01 = (k1 < K) ? W[r0 * K + k1] : 0.f;
        float w10 = W[r1 * K + k0];
        float w11 = (k1 < K) ? W[r1 * K + k1] : 0.f;
        ulonglong2 v;
        v.x = pack2(w00, w01);
        v.y = pack2(w10, w11);
        Wq[t * 32 + jj] = v;
    }
}

// ---------------- kernel A: poincare + layers 1..4 + logmap -> g_t ----------
__global__ void __launch_bounds__(256, 2) nodeA_kernel(
    const float* __restrict__ x,
    const float* __restrict__ W1, const float* __restrict__ b1,
    const float* __restrict__ W2, const float* __restrict__ b2,
    const float* __restrict__ W3, const float* __restrict__ b3,
    const float* __restrict__ W4, const float* __restrict__ b4) {
    extern __shared__ unsigned char smem_raw[];
    ulonglong2* Wq = (ulonglong2*)smem_raw;      // 64KB
    ull* xall = (ull*)(Wq + 4 * 1024);           // 8 * 320 ull
    float* eb = (float*)(xall + 8 * 320);
    float* ebn2 = eb + 256;
    int tid = threadIdx.x;

    load_Wq(Wq,        W1, 63, tid);
    load_Wq(Wq + 1024, W2, 64, tid);
    load_Wq(Wq + 2048, W3, 64, tid);
    load_Wq(Wq + 3072, W4, 64, tid);
    int w = tid >> 5, j = tid & 31;
    if (w < 4) {
        const float* bp[4] = {b1, b2, b3, b4};
        compute_eb64(bp[w], eb + w * 64, ebn2 + w, j);
    }
    __syncthreads();

    int iBase = blockIdx.x * 64 + w * 8;
    ull* xs = xall + w * 320;
    float t2[8], m0[8], m1[8], AA[8], BB[8];
    float c, ratio;

    // poincare map (raw; proj scale deferred into c)
    {
        float h0[8], h1[8], n2[8];
#pragma unroll
        for (int q = 0; q < 8; q++) {
            const float* xp = x + (size_t)min(iBase + q, NN - 1) * 64;
            float inv = __fdividef(1.f, xp[0] + 1.f);
            h0[q] = xp[1 + 2 * j] * inv;
            h1[q] = (j < 31) ? xp[2 + 2 * j] * inv : 0.f;
            n2[q] = h0[q] * h0[q] + h1[q] * h1[q];
        }
        stage_x8(xs, h0, h1, j);
        float n2s = rsum8(n2, j);
        float nf = fmaxf(sqrtf(n2s), MINN);
        float ps = 1.f;
        if (nf > MAXN) { ps = __fdividef(MAXN, nf); nf = MAXN; }
        c = ps;
        ratio = __fdividef(fast_atanh(nf), nf);
    }

    float2 ev;
    ev = *(const float2*)(eb + 2 * j);
    fma_block64(Wq, xs, j, m0, m1);
    layer_post(m0, m1, c, ratio, ev, ebn2[0], true, AA, BB, j);
    relu_stage(m0, m1, AA, BB, ev, xs, j, t2);
    act_pre(t2, j, c, ratio);

    ev = *(const float2*)(eb + 64 + 2 * j);
    fma_block64(Wq + 1024, xs, j, m0, m1);
    layer_post(m0, m1, c, ratio, ev, ebn2[1], true, AA, BB, j);
    relu_stage(m0, m1, AA, BB, ev, xs, j, t2);
    act_pre(t2, j, c, ratio);

    ev = *(const float2*)(eb + 128 + 2 * j);
    fma_block64(Wq + 2048, xs, j, m0, m1);
    layer_post(m0, m1, c, ratio, ev, ebn2[2], true, AA, BB, j);
    relu_stage(m0, m1, AA, BB, ev, xs, j, t2);
    act_pre(t2, j, c, ratio);

    ev = *(const float2*)(eb + 192 + 2 * j);
    fma_block64(Wq + 3072, xs, j, m0, m1);
    layer_post(m0, m1, c, ratio, ev, ebn2[3], true, AA, BB, j);
#pragma unroll
    for (int q = 0; q < 8; q++) {
        if (iBase + q < NN) {
            float2 v = make_float2(AA[q] * m0[q] + BB[q] * ev.x,
                                   AA[q] * m1[q] + BB[q] * ev.y);
            *((float2*)(g_t + (size_t)(iBase + q) * 64) + j) = v;
        }
    }
}

// ---------------- kernel B: agg(g_t)+act + layer5(logmap) -> g_t2 -----------
__global__ void __launch_bounds__(256, 2) nodeB_kernel(
    const float* __restrict__ W5, const float* __restrict__ b5) {
    extern __shared__ unsigned char smem_raw[];
    ulonglong2* Wq = (ulonglong2*)smem_raw;
    ull* xall = (ull*)(Wq + 1024);
    float* eb = (float*)(xall + 8 * 320);
    float* ebn2 = eb + 64;
    int tid = threadIdx.x;
    load_Wq(Wq, W5, 64, tid);
    int w = tid >> 5, j = tid & 31;
    if (w == 0) compute_eb64(b5, eb, ebn2, j);
    __syncthreads();

    int iBase = blockIdx.x * 64 + w * 8;
    ull* xs = xall + w * 320;
    float t2[8], m0[8], m1[8], AA[8], BB[8];
    float c, ratio;
    agg_relu_stage(g_t, iBase, j, xs, t2);
    act_pre(t2, j, c, ratio);
    float2 ev = *(const float2*)(eb + 2 * j);
    fma_block64(Wq, xs, j, m0, m1);
    layer_post(m0, m1, c, ratio, ev, ebn2[0], true, AA, BB, j);
#pragma unroll
    for (int q = 0; q < 8; q++) {
        if (iBase + q < NN) {
            float2 v = make_float2(AA[q] * m0[q] + BB[q] * ev.x,
                                   AA[q] * m1[q] + BB[q] * ev.y);
            *((float2*)(g_t2 + (size_t)(iBase + q) * 64) + j) = v;
        }
    }
    // PDL: signal dependents (nodeC) that our g_t2 writes are done
    asm volatile("griddepcontrol.launch_dependents;");
}

// ---------------- kernel C: agg(g_t2)+act + layer6 -> out -------------------
__global__ void __launch_bounds__(256, 2) nodeC_kernel(
    const float* __restrict__ W6, const float* __restrict__ b6,
    float* __restrict__ out) {
    extern __shared__ unsigned char smem_raw[];
    ull* W6q = (ull*)smem_raw;
    ull* xall = W6q + 1024;
    float* eb = (float*)(xall + 8 * 320);
    float* ebn2 = eb + 32;
    int tid = threadIdx.x;
    for (int i = tid; i < 1024; i += 256) {
        int t = i >> 5, jj = i & 31;
        W6q[t * 32 + jj] = pack2(W6[jj * 64 + 2 * t], W6[jj * 64 + 2 * t + 1]);
    }
    int w = tid >> 5, j = tid & 31;
    if (w == 0) {
        float v0 = b6[j];
        float s2 = v0 * v0;
#pragma unroll
        for (int o = 16; o > 0; o >>= 1) s2 += __shfl_xor_sync(0xffffffffu, s2, o);
        float bn = sqrtf(s2), bc = fmaxf(bn, MINN);
        float se = __fdividef(fast_tanh(bc), bc);
        eb[j] = v0 * se;
        if (j == 0) *ebn2 = (se * bn) * (se * bn);
    }
    __syncthreads();
    // PDL: prologue above is independent of nodeB; wait before touching g_t2
    asm volatile("griddepcontrol.wait;" ::: "memory");

    int iBase = blockIdx.x * 64 + w * 8;
    ull* xs = xall + w * 320;
    float t2[8], AA[8], BB[8];
    float c, ratio;
    agg_relu_stage(g_t2, iBase, j, xs, t2);
    act_pre(t2, j, c, ratio);
    float e0 = eb[j];
    float m[8];
    {
        ull a[8] = {0, 0, 0, 0, 0, 0, 0, 0};
#pragma unroll
        for (int t = 0; t < 32; t++) {
            ull wv = W6q[t * 32 + j];
            const ulonglong2* xt = (const ulonglong2*)(xs + t * 10);
            ulonglong2 xA = xt[0], xB = xt[1], xC = xt[2], xD = xt[3];
            fma2(a[0], xA.x, wv); fma2(a[1], xA.y, wv);
            fma2(a[2], xB.x, wv); fma2(a[3], xB.y, wv);
            fma2(a[4], xC.x, wv); fma2(a[5], xC.y, wv);
            fma2(a[6], xD.x, wv); fma2(a[7], xD.y, wv);
        }
#pragma unroll
        for (int q = 0; q < 8; q++) m[q] = pairsum(a[q]);
    }
    {
        float s2[8], d[8];
#pragma unroll
        for (int q = 0; q < 8; q++) { s2[q] = m[q] * m[q]; d[q] = m[q] * e0; }
        float s2s, ds;
        rsum8x2(s2, d, j, s2s, ds);
        float ml = c * sqrtf(s2s);
        float mx = fmaxf(ml, MINN);
        float r = fast_tanh(mx * ratio);
        float sc = c * __fdividef(r, mx);
        float n1 = fmaxf(r * __fdividef(ml, mx), MINN);
        if (n1 > MAXN) { sc *= __fdividef(MAXN, n1); n1 = MAXN; }
        float xyv = sc * ds;
        float x2 = n1 * n1;
        float c1 = 1.f + 2.f * xyv + ebn2[0];
        float c2 = 1.f - x2;
        float iv = __fdividef(1.f, fmaxf(1.f + 2.f * xyv + x2 * ebn2[0], MINN));
        float q2v = iv * iv * (c1 * c1 * x2 + 2.f * c1 * c2 * xyv + c2 * c2 * ebn2[0]);
        float nf = fmaxf(sqrtf(q2v), MINN);
        float ps = 1.f;
        if (nf > MAXN) ps = __fdividef(MAXN, nf);
        float A = ps * iv * c1 * sc;
        float B = ps * iv * c2;
        bcast8(A, AA);
        bcast8(B, BB);
    }
#pragma unroll
    for (int q = 0; q < 8; q++)
        if (iBase + q < NN) out[(size_t)(iBase + q) * 32 + j] = AA[q] * m[q] + BB[q] * e0;

    // tail: prepare scratch for the NEXT invocation (g_cnt zero-init holds for
    // call 1 from module load; thereafter nodeC is always the last kernel)
    int zb = blockIdx.x * 64 + tid;
    if (tid < 64 && zb < NN) g_cnt[zb] = 0;
    if (blockIdx.x == 0 && tid == 0) g_scan_done = 0;
}

// ---------------- CSR build ----------------
__global__ void detect_kernel(const int* __restrict__ e32) {
    __shared__ int nz;
    if (threadIdx.x == 0) nz = 0;
    __syncthreads();
    for (int i = threadIdx.x; i < 1024; i += 256)
        if (e32[2 * i + 1] != 0) atomicAdd(&nz, 1);
    __syncthreads();
    if (threadIdx.x == 0) g_idx64 = (nz == 0) ? 1 : 0;
}

__global__ void __launch_bounds__(256) hist_kernel(const void* __restrict__ edges) {
    int i = blockIdx.x * 256 + threadIdx.x;   // over EE/2 pairs
    if (i >= EE / 2) return;
    int d0, d1;
    if (g_idx64) {
        longlong2 p = __ldg((const longlong2*)edges + EE / 2 + i);
        d0 = (int)p.x; d1 = (int)p.y;
    } else {
        int2 p = __ldg((const int2*)((const int*)edges + EE) + i);
        d0 = p.x; d1 = p.y;
    }
    atomicAdd(&g_cnt[d0], 1);
    atomicAdd(&g_cnt[d1], 1);
}

__global__ void __launch_bounds__(1024) scan_kernel() {
    __shared__ int sm[1024];
    __shared__ int base_s;
    int gi = blockIdx.x * 1024 + threadIdx.x;
    int v = (gi < NN) ? g_cnt[gi] : 0;
    sm[threadIdx.x] = v;
    __syncthreads();
#pragma unroll
    for (int o = 1; o < 1024; o <<= 1) {
        int t = (threadIdx.x >= o) ? sm[threadIdx.x - o] : 0;
        __syncthreads();
        sm[threadIdx.x] += t;
        __syncthreads();
    }
    int incl = sm[threadIdx.x];
    int excl = incl - v;
    if (threadIdx.x == 1023) {
        g_bsum[blockIdx.x] = incl;
        __threadfence();
        atomicAdd(&g_scan_done, 1);
    }
    if (threadIdx.x == 0) {
        while (*(volatile int*)&g_scan_done < SCAN_BLOCKS) {}
        __threadfence();
    }
    __syncthreads();
    if (threadIdx.x < 32) {
        int acc = 0;
        for (int i = (int)threadIdx.x; i < SCAN_BLOCKS; i += 32)
            if (i < (int)blockIdx.x) acc += g_bsum[i];
#pragma unroll
        for (int o = 16; o > 0; o >>= 1) acc += __shfl_xor_sync(0xffffffffu, acc, o);
        if (threadIdx.x == 0) base_s = acc;
    }
    __syncthreads();
    if (gi < NN) {
        int o = excl + base_s;
        g_off[gi] = o;
        g_cursor[gi] = o;
    }
    if (gi == 0) g_off[NN] = EE;
}

__global__ void __launch_bounds__(256) fill_kernel(const void* __restrict__ edges) {
    int i = blockIdx.x * 256 + threadIdx.x;   // over EE/2 pairs
    if (i >= EE / 2) return;
    int s0, s1, d0, d1;
    if (g_idx64) {
        longlong2 ps = __ldg((const longlong2*)edges + i);
        longlong2 pd = __ldg((const longlong2*)edges + EE / 2 + i);
        s0 = (int)ps.x; s1 = (int)ps.y;
        d0 = (int)pd.x; d1 = (int)pd.y;
    } else {
        int2 ps = __ldg((const int2*)edges + i);
        int2 pd = __ldg((const int2*)((const int*)edges + EE) + i);
        s0 = ps.x; s1 = ps.y;
        d0 = pd.x; d1 = pd.y;
    }
    g_col[atomicAdd(&g_cursor[d0], 1)] = s0;
    g_col[atomicAdd(&g_cursor[d1], 1)] = s1;
}

// ---------------- launch ----------------
extern "C" void kernel_launch(void* const* d_in, const int* in_sizes, int n_in,
                              void* d_out, int out_size) {
    const float* x = (const float*)d_in[0];
    const float* W1 = (const float*)d_in[1];
    const float* b1 = (const float*)d_in[2];
    const float* W2 = (const float*)d_in[3];
    const float* b2 = (const float*)d_in[4];
    const float* W3 = (const float*)d_in[5];
    const float* b3 = (const float*)d_in[6];
    const float* W4 = (const float*)d_in[7];
    const float* b4 = (const float*)d_in[8];
    const float* W5 = (const float*)d_in[9];
    const float* b5 = (const float*)d_in[10];
    const float* W6 = (const float*)d_in[11];
    const float* b6 = (const float*)d_in[12];
    const void* edges = d_in[13];
    float* out = (float*)d_out;

    const int SMEM_A = 4 * 1024 * 16 + 8 * 320 * 8 + 256 * 4 + 16;
    const int SMEM_B = 1024 * 16 + 8 * 320 * 8 + 64 * 4 + 16;
    const int SMEM_C = 1024 * 8 + 8 * 320 * 8 + 32 * 4 + 16;

    cudaFuncSetAttribute(nodeA_kernel, cudaFuncAttributeMaxDynamicSharedMemorySize, SMEM_A);
    cudaFuncSetAttribute(nodeB_kernel, cudaFuncAttributeMaxDynamicSharedMemorySize, SMEM_B);
    cudaFuncSetAttribute(nodeC_kernel, cudaFuncAttributeMaxDynamicSharedMemorySize, SMEM_C);

    const int PAIR_BLOCKS = (EE / 2 + 255) / 256;   // 3125

    cudaStream_t s2;
    cudaEvent_t ev0, evA;
    bool forked = (cudaStreamCreateWithFlags(&s2, cudaStreamNonBlocking) == cudaSuccess);
    if (forked) forked = (cudaEventCreateWithFlags(&ev0, cudaEventDisableTiming) == cudaSuccess);
    if (forked) forked = (cudaEventCreateWithFlags(&evA, cudaEventDisableTiming) == cudaSuccess);

    if (forked) {
        cudaEventRecord(ev0, 0);
        cudaStreamWaitEvent(s2, ev0, 0);
        nodeA_kernel<<<NODE_BLOCKS, 256, SMEM_A, s2>>>(x, W1, b1, W2, b2, W3, b3, W4, b4);
        cudaEventRecord(evA, s2);

        detect_kernel<<<1, 256>>>((const int*)edges);
        hist_kernel<<<PAIR_BLOCKS, 256>>>(edges);
        scan_kernel<<<SCAN_BLOCKS, 1024>>>();
        fill_kernel<<<PAIR_BLOCKS, 256>>>(edges);

        cudaStreamWaitEvent(0, evA, 0);
    } else {
        detect_kernel<<<1, 256>>>((const int*)edges);
        hist_kernel<<<PAIR_BLOCKS, 256>>>(edges);
        scan_kernel<<<SCAN_BLOCKS, 1024>>>();
        fill_kernel<<<PAIR_BLOCKS, 256>>>(edges);
        nodeA_kernel<<<NODE_BLOCKS, 256, SMEM_A>>>(x, W1, b1, W2, b2, W3, b3, W4, b4);
    }

    nodeB_kernel<<<NODE_BLOCKS, 256, SMEM_B>>>(W5, b5);

    // nodeC with programmatic dependent launch (prologue overlaps nodeB tail);
    // falls back to a plain launch if the attribute isn't accepted.
    {
        cudaLaunchConfig_t cfg = {};
        cfg.gridDim = dim3(NODE_BLOCKS);
        cfg.blockDim = dim3(256);
        cfg.dynamicSmemBytes = SMEM_C;
        cfg.stream = 0;
        cudaLaunchAttribute at[1];
        at[0].id = cudaLaunchAttributeProgrammaticStreamSerialization;
        at[0].val.programmaticStreamSerializationAllowed = 1;
        cfg.attrs = at;
        cfg.numAttrs = 1;
        if (cudaLaunchKernelEx(&cfg, nodeC_kernel, W6, b6, out) != cudaSuccess)
            nodeC_kernel<<<NODE_BLOCKS, 256, SMEM_C>>>(W6, b6, out);
    }
}

// round 10
// speedup vs baseline: 2.3508x; 1.1095x over previous
#include <cuda_runtime.h>
#include <cstdint>

#define NN 100000
#define EE 1600000
#define MINN 1e-15f
#define MAXN ((float)(1.0 - 1e-5))
#define SCAN_BLOCKS 98
#define NODE_BLOCKS ((NN + 63) / 64)   // 64 nodes per block (8 per warp)

// ---------------- scratch ----------------
__device__ __align__(16) float g_t[(size_t)NN * 64];
__device__ __align__(16) float g_t2[(size_t)NN * 64];
__device__ int g_col[EE];
__device__ int g_cnt[NN];          // zero at load; re-zeroed by nodeC tail
__device__ int g_off[NN + 1];
__device__ int g_cursor[NN];
__device__ int g_bsum[SCAN_BLOCKS];
__device__ int g_scan_done;        // zero at load; reset by nodeC tail
__device__ int g_idx64;

// ---------------- fast math (args nonnegative) ----------------
__device__ __forceinline__ float fast_tanh(float x) {
    float e = __expf(-2.f * x);
    return __fdividef(1.f - e, 1.f + e);
}
__device__ __forceinline__ float fast_atanh(float x) {
    x = fminf(x, MAXN);
    return 0.5f * __logf(__fdividef(1.f + x, 1.f - x));
}

// reduce v[8] across warp -> lane j gets total of slot (j&7). 9 SHFL, depth 5.
__device__ __forceinline__ float rsum8(const float v[8], int j) {
    bool p1 = j & 1;
    float a[4];
#pragma unroll
    for (int i = 0; i < 4; i++) {
        float m = p1 ? v[2 * i + 1] : v[2 * i];
        float o = p1 ? v[2 * i] : v[2 * i + 1];
        a[i] = m + __shfl_xor_sync(0xffffffffu, o, 1);
    }
    bool p2 = j & 2;
    float b0, b1;
    {
        float m = p2 ? a[1] : a[0], o = p2 ? a[0] : a[1];
        b0 = m + __shfl_xor_sync(0xffffffffu, o, 2);
    }
    {
        float m = p2 ? a[3] : a[2], o = p2 ? a[2] : a[3];
        b1 = m + __shfl_xor_sync(0xffffffffu, o, 2);
    }
    bool p4 = j & 4;
    float m = p4 ? b1 : b0, o = p4 ? b0 : b1;
    float c = m + __shfl_xor_sync(0xffffffffu, o, 4);
    c += __shfl_xor_sync(0xffffffffu, c, 8);
    c += __shfl_xor_sync(0xffffffffu, c, 16);
    return c;
}

// two independent rsum8's interleaved (half the exposed shfl-chain depth)
__device__ __forceinline__ void rsum8x2(const float va[8], const float vb[8],
                                        int j, float& ra, float& rb) {
    bool p1 = j & 1;
    float A[4], B[4];
#pragma unroll
    for (int i = 0; i < 4; i++) {
        float am = p1 ? va[2 * i + 1] : va[2 * i];
        float ao = p1 ? va[2 * i] : va[2 * i + 1];
        float bm = p1 ? vb[2 * i + 1] : vb[2 * i];
        float bo = p1 ? vb[2 * i] : vb[2 * i + 1];
        A[i] = am + __shfl_xor_sync(0xffffffffu, ao, 1);
        B[i] = bm + __shfl_xor_sync(0xffffffffu, bo, 1);
    }
    bool p2 = j & 2;
    float a0, a1, b0, b1;
    { float m = p2 ? A[1] : A[0], o = p2 ? A[0] : A[1]; a0 = m + __shfl_xor_sync(0xffffffffu, o, 2); }
    { float m = p2 ? B[1] : B[0], o = p2 ? B[0] : B[1]; b0 = m + __shfl_xor_sync(0xffffffffu, o, 2); }
    { float m = p2 ? A[3] : A[2], o = p2 ? A[2] : A[3]; a1 = m + __shfl_xor_sync(0xffffffffu, o, 2); }
    { float m = p2 ? B[3] : B[2], o = p2 ? B[2] : B[3]; b1 = m + __shfl_xor_sync(0xffffffffu, o, 2); }
    bool p4 = j & 4;
    { float m = p4 ? a1 : a0, o = p4 ? a0 : a1; ra = m + __shfl_xor_sync(0xffffffffu, o, 4); }
    { float m = p4 ? b1 : b0, o = p4 ? b0 : b1; rb = m + __shfl_xor_sync(0xffffffffu, o, 4); }
    ra += __shfl_xor_sync(0xffffffffu, ra, 8);
    rb += __shfl_xor_sync(0xffffffffu, rb, 8);
    ra += __shfl_xor_sync(0xffffffffu, ra, 16);
    rb += __shfl_xor_sync(0xffffffffu, rb, 16);
}

__device__ __forceinline__ void bcast8(float v, float o[8]) {
#pragma unroll
    for (int q = 0; q < 8; q++) o[q] = __shfl_sync(0xffffffffu, v, q);
}

// stage 8 nodes: xs[j*10 + q] = float2(h0[q], h1[q]) (80B padded rows)
__device__ __forceinline__ void stage_x8(float2* xs, const float h0[8],
                                         const float h1[8], int j) {
    __syncwarp();
#pragma unroll
    for (int q = 0; q < 8; q++) xs[j * 10 + q] = make_float2(h0[q], h1[q]);
    __syncwarp();
}

// 64x64 matvec block: raw M for 8 nodes, plain scalar FFMA.
// Lane j owns output comps (2j,2j+1).
// Wf[t*32+j] = (W[2j][2t], W[2j][2t+1], W[2j+1][2t], W[2j+1][2t+1])
__device__ __forceinline__ void fma_block64(const float4* __restrict__ Wf,
                                            const float2* xs, int j,
                                            float m0[8], float m1[8]) {
#pragma unroll
    for (int q = 0; q < 8; q++) { m0[q] = 0.f; m1[q] = 0.f; }
#pragma unroll
    for (int t = 0; t < 32; t++) {
        float4 wv = Wf[t * 32 + j];
        const float4* xt = (const float4*)(xs + t * 10);
        float4 xA = xt[0], xB = xt[1], xC = xt[2], xD = xt[3];
        m0[0] = fmaf(xA.x, wv.x, fmaf(xA.y, wv.y, m0[0]));
        m1[0] = fmaf(xA.x, wv.z, fmaf(xA.y, wv.w, m1[0]));
        m0[1] = fmaf(xA.z, wv.x, fmaf(xA.w, wv.y, m0[1]));
        m1[1] = fmaf(xA.z, wv.z, fmaf(xA.w, wv.w, m1[1]));
        m0[2] = fmaf(xB.x, wv.x, fmaf(xB.y, wv.y, m0[2]));
        m1[2] = fmaf(xB.x, wv.z, fmaf(xB.y, wv.w, m1[2]));
        m0[3] = fmaf(xB.z, wv.x, fmaf(xB.w, wv.y, m0[3]));
        m1[3] = fmaf(xB.z, wv.z, fmaf(xB.w, wv.w, m1[3]));
        m0[4] = fmaf(xC.x, wv.x, fmaf(xC.y, wv.y, m0[4]));
        m1[4] = fmaf(xC.x, wv.z, fmaf(xC.y, wv.w, m1[4]));
        m0[5] = fmaf(xC.z, wv.x, fmaf(xC.w, wv.y, m0[5]));
        m1[5] = fmaf(xC.z, wv.z, fmaf(xC.w, wv.w, m1[5]));
        m0[6] = fmaf(xD.x, wv.x, fmaf(xD.y, wv.y, m0[6]));
        m1[6] = fmaf(xD.x, wv.z, fmaf(xD.y, wv.w, m1[6]));
        m0[7] = fmaf(xD.z, wv.x, fmaf(xD.w, wv.y, m0[7]));
        m1[7] = fmaf(xD.z, wv.z, fmaf(xD.w, wv.w, m1[7]));
    }
}

// post-matvec scalar chain -> broadcast coeffs AA,BB (out = AA*M + BB*e).
__device__ __forceinline__ void layer_post(
    const float m0[8], const float m1[8], float c, float ratio,
    float2 ev, float ebn2, bool with_sl, float AA[8], float BB[8], int j) {
    float s2[8], d[8];
#pragma unroll
    for (int q = 0; q < 8; q++) {
        s2[q] = m0[q] * m0[q] + m1[q] * m1[q];
        d[q] = m0[q] * ev.x + m1[q] * ev.y;
    }
    float s2s, ds;
    rsum8x2(s2, d, j, s2s, ds);
    float ml = c * sqrtf(s2s);
    float mx = fmaxf(ml, MINN);
    float r = fast_tanh(mx * ratio);
    float sc = c * __fdividef(r, mx);          // applies to raw M
    float n1 = fmaxf(r * __fdividef(ml, mx), MINN);
    if (n1 > MAXN) { sc *= __fdividef(MAXN, n1); n1 = MAXN; }
    float xyv = sc * ds;
    float x2 = n1 * n1;
    float c1 = 1.f + 2.f * xyv + ebn2;
    float c2 = 1.f - x2;
    float iv = __fdividef(1.f, fmaxf(1.f + 2.f * xyv + x2 * ebn2, MINN));
    float q2v = iv * iv * (c1 * c1 * x2 + 2.f * c1 * c2 * xyv + c2 * c2 * ebn2);
    float nf = fmaxf(sqrtf(q2v), MINN);
    float ps = 1.f;
    if (nf > MAXN) { ps = __fdividef(MAXN, nf); nf = MAXN; }
    float sl = with_sl ? __fdividef(fast_atanh(nf), nf) : 1.f;
    float A = ps * iv * c1 * sc * sl;
    float B = ps * iv * c2 * sl;
    bcast8(A, AA);
    bcast8(B, BB);
}

// act prelude for the NEXT layer from staged-u t2 partials.
__device__ __forceinline__ void act_pre(const float t2[8], int j,
                                        float& c, float& ratio) {
    float t2s = rsum8(t2, j);
    float tn = sqrtf(t2s);
    float tc = fmaxf(tn, MINN);
    float se = __fdividef(fast_tanh(tc), tc);
    float nn = fmaxf(se * tn, MINN);
    if (nn > MAXN) { se *= __fdividef(MAXN, nn); nn = MAXN; }
    c = se;
    ratio = __fdividef(fast_atanh(nn), nn);
}

// relu(A*M + B*e) -> unscaled u staged + t2 partials
__device__ __forceinline__ void relu_stage(const float m0[8], const float m1[8],
                                           const float AA[8], const float BB[8],
                                           float2 ev, float2* xs, int j, float t2[8]) {
    __syncwarp();
#pragma unroll
    for (int q = 0; q < 8; q++) {
        float u0 = fmaxf(AA[q] * m0[q] + BB[q] * ev.x, 0.f);
        float u1 = fmaxf(AA[q] * m1[q] + BB[q] * ev.y, 0.f);
        t2[q] = u0 * u0 + u1 * u1;
        xs[j * 10 + q] = make_float2(u0, u1);
    }
    __syncwarp();
}

// bias -> eb = expmap0(b), |eb|^2, one warp
__device__ __forceinline__ void compute_eb64(const float* __restrict__ b,
                                             float* eb, float* ebn2, int j) {
    float v0 = b[j], v1 = b[32 + j];
    float s2 = v0 * v0 + v1 * v1;
#pragma unroll
    for (int o = 16; o > 0; o >>= 1) s2 += __shfl_xor_sync(0xffffffffu, s2, o);
    float bn = sqrtf(s2), bc = fmaxf(bn, MINN);
    float se = __fdividef(fast_tanh(bc), bc);
    eb[j] = v0 * se;
    eb[32 + j] = v1 * se;
    if (j == 0) *ebn2 = (se * bn) * (se * bn);
}

// CSR gather for one node; lane j sums comps (2j,2j+1) via float2
__device__ __forceinline__ void csr_agg(const float* __restrict__ tsrc, int node,
                                        int j, float& o0, float& o1, int& deg) {
    int s = g_off[node], e = g_off[node + 1];
    deg = e - s;
    float a0 = 0.f, a1 = 0.f, b0 = 0.f, b1 = 0.f;
    for (int base = s; base < e; base += 32) {
        int nh = min(32, e - base);
        int idx = (j < nh) ? g_col[base + j] : 0;
        int t = 0;
        for (; t + 8 <= nh; t += 8) {
#pragma unroll
            for (int u = 0; u < 8; u += 2) {
                int sa = __shfl_sync(0xffffffffu, idx, t + u);
                int sb = __shfl_sync(0xffffffffu, idx, t + u + 1);
                float2 va = __ldg((const float2*)(tsrc + (size_t)sa * 64) + j);
                float2 vb = __ldg((const float2*)(tsrc + (size_t)sb * 64) + j);
                a0 += va.x; a1 += va.y;
                b0 += vb.x; b1 += vb.y;
            }
        }
        for (; t < nh; t++) {
            int sx = __shfl_sync(0xffffffffu, idx, t);
            float2 v = __ldg((const float2*)(tsrc + (size_t)sx * 64) + j);
            a0 += v.x; a1 += v.y;
        }
    }
    o0 = a0 + b0; o1 = a1 + b1;
}

// agg mean + (expmap0,proj,logmap0 folded) + relu -> unscaled u staged + t2
__device__ __forceinline__ void agg_relu_stage(const float* __restrict__ tsrc,
                                               int iBase, int j, float2* xs,
                                               float t2[8]) {
    float h0[8], h1[8], n2[8];
#pragma unroll
    for (int q = 0; q < 8; q++) {
        int node = min(iBase + q, NN - 1);
        int deg;
        float a0, a1;
        csr_agg(tsrc, node, j, a0, a1, deg);
        float inv = __fdividef(1.f, fmaxf((float)deg, 1.f));
        h0[q] = a0 * inv;
        h1[q] = a1 * inv;
        n2[q] = h0[q] * h0[q] + h1[q] * h1[q];
    }
    float n2s = rsum8(n2, j);
    float un = sqrtf(n2s);
    float uc = fmaxf(un, MINN);
    float se = __fdividef(fast_tanh(uc), uc);
    float nn = fmaxf(se * un, MINN);
    if (nn > MAXN) { se *= __fdividef(MAXN, nn); nn = MAXN; }
    float comb = se * __fdividef(fast_atanh(nn), nn);
    float CB[8];
    bcast8(comb, CB);
    __syncwarp();
#pragma unroll
    for (int q = 0; q < 8; q++) {
        float u0 = fmaxf(h0[q] * CB[q], 0.f);
        float u1 = fmaxf(h1[q] * CB[q], 0.f);
        t2[q] = u0 * u0 + u1 * u1;
        xs[j * 10 + q] = make_float2(u0, u1);
    }
    __syncwarp();
}

// load weights: Wf[t*32+j] = (W[2j][2t], W[2j][2t+1], W[2j+1][2t], W[2j+1][2t+1])
__device__ __forceinline__ void load_Wq(float4* Wf, const float* __restrict__ W,
                                        int K, int tid) {
    for (int i = tid; i < 1024; i += 256) {
        int t = i >> 5, jj = i & 31;
        int k0 = 2 * t, k1 = 2 * t + 1;
        int r0 = 2 * jj, r1 = 2 * jj + 1;
        float4 v;
        v.x = W[r0 * K + k0];
        v.y = (k1 < K) ? W[r0 * K + k1] : 0.f;
        v.z = W[r1 * K + k0];
        v.w = (k1 < K) ? W[r1 * K + k1] : 0.f;
        Wf[t * 32 + jj] = v;
    }
}

// ---------------- kernel A: poincare + layers 1..4 + logmap -> g_t ----------
__global__ void __launch_bounds__(256, 2) nodeA_kernel(
    const float* __restrict__ x,
    const float* __restrict__ W1, const float* __restrict__ b1,
    const float* __restrict__ W2, const float* __restrict__ b2,
    const float* __restrict__ W3, const float* __restrict__ b3,
    const float* __restrict__ W4, const float* __restrict__ b4) {
    extern __shared__ unsigned char smem_raw[];
    float4* Wf = (float4*)smem_raw;              // 4*1024 float4 = 64KB
    float2* xall = (float2*)(Wf + 4 * 1024);     // 8 warps * 320 float2 = 20KB
    float* eb = (float*)(xall + 8 * 320);
    float* ebn2 = eb + 256;
    int tid = threadIdx.x;

    load_Wq(Wf,        W1, 63, tid);
    load_Wq(Wf + 1024, W2, 64, tid);
    load_Wq(Wf + 2048, W3, 64, tid);
    load_Wq(Wf + 3072, W4, 64, tid);
    int w = tid >> 5, j = tid & 31;
    if (w < 4) {
        const float* bp[4] = {b1, b2, b3, b4};
        compute_eb64(bp[w], eb + w * 64, ebn2 + w, j);
    }
    __syncthreads();

    int iBase = blockIdx.x * 64 + w * 8;
    float2* xs = xall + w * 320;
    float t2[8], m0[8], m1[8], AA[8], BB[8];
    float c, ratio;

    // poincare map (raw; proj scale deferred into c)
    {
        float h0[8], h1[8], n2[8];
#pragma unroll
        for (int q = 0; q < 8; q++) {
            const float* xp = x + (size_t)min(iBase + q, NN - 1) * 64;
            float inv = __fdividef(1.f, xp[0] + 1.f);
            h0[q] = xp[1 + 2 * j] * inv;
            h1[q] = (j < 31) ? xp[2 + 2 * j] * inv : 0.f;
            n2[q] = h0[q] * h0[q] + h1[q] * h1[q];
        }
        stage_x8(xs, h0, h1, j);
        float n2s = rsum8(n2, j);
        float nf = fmaxf(sqrtf(n2s), MINN);
        float ps = 1.f;
        if (nf > MAXN) { ps = __fdividef(MAXN, nf); nf = MAXN; }
        c = ps;
        ratio = __fdividef(fast_atanh(nf), nf);
    }

    float2 ev;
    ev = *(const float2*)(eb + 2 * j);
    fma_block64(Wf, xs, j, m0, m1);
    layer_post(m0, m1, c, ratio, ev, ebn2[0], true, AA, BB, j);
    relu_stage(m0, m1, AA, BB, ev, xs, j, t2);
    act_pre(t2, j, c, ratio);

    ev = *(const float2*)(eb + 64 + 2 * j);
    fma_block64(Wf + 1024, xs, j, m0, m1);
    layer_post(m0, m1, c, ratio, ev, ebn2[1], true, AA, BB, j);
    relu_stage(m0, m1, AA, BB, ev, xs, j, t2);
    act_pre(t2, j, c, ratio);

    ev = *(const float2*)(eb + 128 + 2 * j);
    fma_block64(Wf + 2048, xs, j, m0, m1);
    layer_post(m0, m1, c, ratio, ev, ebn2[2], true, AA, BB, j);
    relu_stage(m0, m1, AA, BB, ev, xs, j, t2);
    act_pre(t2, j, c, ratio);

    ev = *(const float2*)(eb + 192 + 2 * j);
    fma_block64(Wf + 3072, xs, j, m0, m1);
    layer_post(m0, m1, c, ratio, ev, ebn2[3], true, AA, BB, j);
#pragma unroll
    for (int q = 0; q < 8; q++) {
        if (iBase + q < NN) {
            float2 v = make_float2(AA[q] * m0[q] + BB[q] * ev.x,
                                   AA[q] * m1[q] + BB[q] * ev.y);
            *((float2*)(g_t + (size_t)(iBase + q) * 64) + j) = v;
        }
    }
}

// ---------------- kernel B: agg(g_t)+act + layer5(logmap) -> g_t2 -----------
__global__ void __launch_bounds__(256, 2) nodeB_kernel(
    const float* __restrict__ W5, const float* __restrict__ b5) {
    extern __shared__ unsigned char smem_raw[];
    float4* Wf = (float4*)smem_raw;              // 1024 float4 = 16KB
    float2* xall = (float2*)(Wf + 1024);
    float* eb = (float*)(xall + 8 * 320);
    float* ebn2 = eb + 64;
    int tid = threadIdx.x;
    load_Wq(Wf, W5, 64, tid);
    int w = tid >> 5, j = tid & 31;
    if (w == 0) compute_eb64(b5, eb, ebn2, j);
    __syncthreads();

    int iBase = blockIdx.x * 64 + w * 8;
    float2* xs = xall + w * 320;
    float t2[8], m0[8], m1[8], AA[8], BB[8];
    float c, ratio;
    agg_relu_stage(g_t, iBase, j, xs, t2);
    act_pre(t2, j, c, ratio);
    float2 ev = *(const float2*)(eb + 2 * j);
    fma_block64(Wf, xs, j, m0, m1);
    layer_post(m0, m1, c, ratio, ev, ebn2[0], true, AA, BB, j);
#pragma unroll
    for (int q = 0; q < 8; q++) {
        if (iBase + q < NN) {
            float2 v = make_float2(AA[q] * m0[q] + BB[q] * ev.x,
                                   AA[q] * m1[q] + BB[q] * ev.y);
            *((float2*)(g_t2 + (size_t)(iBase + q) * 64) + j) = v;
        }
    }
    // PDL: signal dependents (nodeC) that our g_t2 writes are done
    asm volatile("griddepcontrol.launch_dependents;");
}

// ---------------- kernel C: agg(g_t2)+act + layer6 -> out -------------------
__global__ void __launch_bounds__(256, 2) nodeC_kernel(
    const float* __restrict__ W6, const float* __restrict__ b6,
    float* __restrict__ out) {
    extern __shared__ unsigned char smem_raw[];
    float2* W6f = (float2*)smem_raw;             // 1024 float2 = 8KB
    float2* xall = W6f + 1024;
    float* eb = (float*)(xall + 8 * 320);
    float* ebn2 = eb + 32;
    int tid = threadIdx.x;
    for (int i = tid; i < 1024; i += 256) {
        int t = i >> 5, jj = i & 31;
        W6f[t * 32 + jj] = make_float2(W6[jj * 64 + 2 * t], W6[jj * 64 + 2 * t + 1]);
    }
    int w = tid >> 5, j = tid & 31;
    if (w == 0) {
        float v0 = b6[j];
        float s2 = v0 * v0;
#pragma unroll
        for (int o = 16; o > 0; o >>= 1) s2 += __shfl_xor_sync(0xffffffffu, s2, o);
        float bn = sqrtf(s2), bc = fmaxf(bn, MINN);
        float se = __fdividef(fast_tanh(bc), bc);
        eb[j] = v0 * se;
        if (j == 0) *ebn2 = (se * bn) * (se * bn);
    }
    __syncthreads();
    // PDL: prologue above is independent of nodeB; wait before touching g_t2
    asm volatile("griddepcontrol.wait;" ::: "memory");

    int iBase = blockIdx.x * 64 + w * 8;
    float2* xs = xall + w * 320;
    float t2[8], AA[8], BB[8];
    float c, ratio;
    agg_relu_stage(g_t2, iBase, j, xs, t2);
    act_pre(t2, j, c, ratio);
    float e0 = eb[j];
    float m[8];
    {
#pragma unroll
        for (int q = 0; q < 8; q++) m[q] = 0.f;
#pragma unroll
        for (int t = 0; t < 32; t++) {
            float2 wv = W6f[t * 32 + j];
            const float4* xt = (const float4*)(xs + t * 10);
            float4 xA = xt[0], xB = xt[1], xC = xt[2], xD = xt[3];
            m[0] = fmaf(xA.x, wv.x, fmaf(xA.y, wv.y, m[0]));
            m[1] = fmaf(xA.z, wv.x, fmaf(xA.w, wv.y, m[1]));
            m[2] = fmaf(xB.x, wv.x, fmaf(xB.y, wv.y, m[2]));
            m[3] = fmaf(xB.z, wv.x, fmaf(xB.w, wv.y, m[3]));
            m[4] = fmaf(xC.x, wv.x, fmaf(xC.y, wv.y, m[4]));
            m[5] = fmaf(xC.z, wv.x, fmaf(xC.w, wv.y, m[5]));
            m[6] = fmaf(xD.x, wv.x, fmaf(xD.y, wv.y, m[6]));
            m[7] = fmaf(xD.z, wv.x, fmaf(xD.w, wv.y, m[7]));
        }
    }
    {
        float s2[8], d[8];
#pragma unroll
        for (int q = 0; q < 8; q++) { s2[q] = m[q] * m[q]; d[q] = m[q] * e0; }
        float s2s, ds;
        rsum8x2(s2, d, j, s2s, ds);
        float ml = c * sqrtf(s2s);
        float mx = fmaxf(ml, MINN);
        float r = fast_tanh(mx * ratio);
        float sc = c * __fdividef(r, mx);
        float n1 = fmaxf(r * __fdividef(ml, mx), MINN);
        if (n1 > MAXN) { sc *= __fdividef(MAXN, n1); n1 = MAXN; }
        float xyv = sc * ds;
        float x2 = n1 * n1;
        float c1 = 1.f + 2.f * xyv + ebn2[0];
        float c2 = 1.f - x2;
        float iv = __fdividef(1.f, fmaxf(1.f + 2.f * xyv + x2 * ebn2[0], MINN));
        float q2v = iv * iv * (c1 * c1 * x2 + 2.f * c1 * c2 * xyv + c2 * c2 * ebn2[0]);
        float nf = fmaxf(sqrtf(q2v), MINN);
        float ps = 1.f;
        if (nf > MAXN) ps = __fdividef(MAXN, nf);
        float A = ps * iv * c1 * sc;
        float B = ps * iv * c2;
        bcast8(A, AA);
        bcast8(B, BB);
    }
#pragma unroll
    for (int q = 0; q < 8; q++)
        if (iBase + q < NN) out[(size_t)(iBase + q) * 32 + j] = AA[q] * m[q] + BB[q] * e0;

    // tail: prepare scratch for the NEXT invocation (g_cnt zero-init holds for
    // call 1 from module load; thereafter nodeC is always the last kernel)
    int zb = blockIdx.x * 64 + tid;
    if (tid < 64 && zb < NN) g_cnt[zb] = 0;
    if (blockIdx.x == 0 && tid == 0) g_scan_done = 0;
}

// ---------------- CSR build ----------------
__global__ void detect_kernel(const int* __restrict__ e32) {
    __shared__ int nz;
    if (threadIdx.x == 0) nz = 0;
    __syncthreads();
    for (int i = threadIdx.x; i < 1024; i += 256)
        if (e32[2 * i + 1] != 0) atomicAdd(&nz, 1);
    __syncthreads();
    if (threadIdx.x == 0) g_idx64 = (nz == 0) ? 1 : 0;
}

__global__ void __launch_bounds__(256) hist_kernel(const void* __restrict__ edges) {
    int i = blockIdx.x * 256 + threadIdx.x;   // over EE/2 pairs
    if (i >= EE / 2) return;
    int d0, d1;
    if (g_idx64) {
        longlong2 p = __ldg((const longlong2*)edges + EE / 2 + i);
        d0 = (int)p.x; d1 = (int)p.y;
    } else {
        int2 p = __ldg((const int2*)((const int*)edges + EE) + i);
        d0 = p.x; d1 = p.y;
    }
    atomicAdd(&g_cnt[d0], 1);
    atomicAdd(&g_cnt[d1], 1);
}

__global__ void __launch_bounds__(1024) scan_kernel() {
    __shared__ int sm[1024];
    __shared__ int base_s;
    int gi = blockIdx.x * 1024 + threadIdx.x;
    int v = (gi < NN) ? g_cnt[gi] : 0;
    sm[threadIdx.x] = v;
    __syncthreads();
#pragma unroll
    for (int o = 1; o < 1024; o <<= 1) {
        int t = (threadIdx.x >= o) ? sm[threadIdx.x - o] : 0;
        __syncthreads();
        sm[threadIdx.x] += t;
        __syncthreads();
    }
    int incl = sm[threadIdx.x];
    int excl = incl - v;
    if (threadIdx.x == 1023) {
        g_bsum[blockIdx.x] = incl;
        __threadfence();
        atomicAdd(&g_scan_done, 1);
    }
    if (threadIdx.x == 0) {
        while (*(volatile int*)&g_scan_done < SCAN_BLOCKS) {}
        __threadfence();
    }
    __syncthreads();
    if (threadIdx.x < 32) {
        int acc = 0;
        for (int i = (int)threadIdx.x; i < SCAN_BLOCKS; i += 32)
            if (i < (int)blockIdx.x) acc += g_bsum[i];
#pragma unroll
        for (int o = 16; o > 0; o >>= 1) acc += __shfl_xor_sync(0xffffffffu, acc, o);
        if (threadIdx.x == 0) base_s = acc;
    }
    __syncthreads();
    if (gi < NN) {
        int o = excl + base_s;
        g_off[gi] = o;
        g_cursor[gi] = o;
    }
    if (gi == 0) g_off[NN] = EE;
}

__global__ void __launch_bounds__(256) fill_kernel(const void* __restrict__ edges) {
    int i = blockIdx.x * 256 + threadIdx.x;   // over EE/2 pairs
    if (i >= EE / 2) return;
    int s0, s1, d0, d1;
    if (g_idx64) {
        longlong2 ps = __ldg((const longlong2*)edges + i);
        longlong2 pd = __ldg((const longlong2*)edges + EE / 2 + i);
        s0 = (int)ps.x; s1 = (int)ps.y;
        d0 = (int)pd.x; d1 = (int)pd.y;
    } else {
        int2 ps = __ldg((const int2*)edges + i);
        int2 pd = __ldg((const int2*)((const int*)edges + EE) + i);
        s0 = ps.x; s1 = ps.y;
        d0 = pd.x; d1 = pd.y;
    }
    g_col[atomicAdd(&g_cursor[d0], 1)] = s0;
    g_col[atomicAdd(&g_cursor[d1], 1)] = s1;
}

// ---------------- launch ----------------
extern "C" void kernel_launch(void* const* d_in, const int* in_sizes, int n_in,
                              void* d_out, int out_size) {
    const float* x = (const float*)d_in[0];
    const float* W1 = (const float*)d_in[1];
    const float* b1 = (const float*)d_in[2];
    const float* W2 = (const float*)d_in[3];
    const float* b2 = (const float*)d_in[4];
    const float* W3 = (const float*)d_in[5];
    const float* b3 = (const float*)d_in[6];
    const float* W4 = (const float*)d_in[7];
    const float* b4 = (const float*)d_in[8];
    const float* W5 = (const float*)d_in[9];
    const float* b5 = (const float*)d_in[10];
    const float* W6 = (const float*)d_in[11];
    const float* b6 = (const float*)d_in[12];
    const void* edges = d_in[13];
    float* out = (float*)d_out;

    const int SMEM_A = 4 * 1024 * 16 + 8 * 320 * 8 + 256 * 4 + 16;
    const int SMEM_B = 1024 * 16 + 8 * 320 * 8 + 64 * 4 + 16;
    const int SMEM_C = 1024 * 8 + 8 * 320 * 8 + 32 * 4 + 16;

    cudaFuncSetAttribute(nodeA_kernel, cudaFuncAttributeMaxDynamicSharedMemorySize, SMEM_A);
    cudaFuncSetAttribute(nodeB_kernel, cudaFuncAttributeMaxDynamicSharedMemorySize, SMEM_B);
    cudaFuncSetAttribute(nodeC_kernel, cudaFuncAttributeMaxDynamicSharedMemorySize, SMEM_C);

    const int PAIR_BLOCKS = (EE / 2 + 255) / 256;   // 3125

    cudaStream_t s2;
    cudaEvent_t ev0, evA;
    bool forked = (cudaStreamCreateWithFlags(&s2, cudaStreamNonBlocking) == cudaSuccess);
    if (forked) forked = (cudaEventCreateWithFlags(&ev0, cudaEventDisableTiming) == cudaSuccess);
    if (forked) forked = (cudaEventCreateWithFlags(&evA, cudaEventDisableTiming) == cudaSuccess);

    if (forked) {
        cudaEventRecord(ev0, 0);
        cudaStreamWaitEvent(s2, ev0, 0);
        nodeA_kernel<<<NODE_BLOCKS, 256, SMEM_A, s2>>>(x, W1, b1, W2, b2, W3, b3, W4, b4);
        cudaEventRecord(evA, s2);

        detect_kernel<<<1, 256>>>((const int*)edges);
        hist_kernel<<<PAIR_BLOCKS, 256>>>(edges);
        scan_kernel<<<SCAN_BLOCKS, 1024>>>();
        fill_kernel<<<PAIR_BLOCKS, 256>>>(edges);

        cudaStreamWaitEvent(0, evA, 0);
    } else {
        detect_kernel<<<1, 256>>>((const int*)edges);
        hist_kernel<<<PAIR_BLOCKS, 256>>>(edges);
        scan_kernel<<<SCAN_BLOCKS, 1024>>>();
        fill_kernel<<<PAIR_BLOCKS, 256>>>(edges);
        nodeA_kernel<<<NODE_BLOCKS, 256, SMEM_A>>>(x, W1, b1, W2, b2, W3, b3, W4, b4);
    }

    nodeB_kernel<<<NODE_BLOCKS, 256, SMEM_B>>>(W5, b5);

    // nodeC with programmatic dependent launch (prologue overlaps nodeB tail);
    // falls back to a plain launch if the attribute isn't accepted.
    {
        cudaLaunchConfig_t cfg = {};
        cfg.gridDim = dim3(NODE_BLOCKS);
        cfg.blockDim = dim3(256);
        cfg.dynamicSmemBytes = SMEM_C;
        cfg.stream = 0;
        cudaLaunchAttribute at[1];
        at[0].id = cudaLaunchAttributeProgrammaticStreamSerialization;
        at[0].val.programmaticStreamSerializationAllowed = 1;
        cfg.attrs = at;
        cfg.numAttrs = 1;
        if (cudaLaunchKernelEx(&cfg, nodeC_kernel, W6, b6, out) != cudaSuccess)
            nodeC_kernel<<<NODE_BLOCKS, 256, SMEM_C>>>(W6, b6, out);
    }
}